// round 1
// baseline (speedup 1.0000x reference)
#include <cuda_runtime.h>
#include <cuda_bf16.h>
#include <math.h>

// Problem dims
#define BB 2
#define LL 2048
#define DD 1024
#define VV 32000
#define NLAYERS 2
#define EE 2048
#define NN_ 16
#define RR 64
#define KK 4

#define NTOK (BB*LL)          // 4096 tokens

// ---------------- scratch (device globals; no allocation allowed) ----------
__device__ float g_x  [NTOK*DD];        // residual stream (16MB)
__device__ float g_xn [NTOK*DD];        // rmsnorm out     (16MB)
__device__ float g_xz [NTOK*2*EE];      // W_in out        (64MB)
__device__ float g_xc [NTOK*EE];        // conv+silu out   (32MB)
__device__ float g_dbl[NTOK*96];        // xproj out       (1.5MB)
__device__ float g_dt [NTOK*EE];        // softplus(dt)    (32MB)
__device__ float g_y  [NTOK*EE];        // scan out        (32MB)

// ---------------- embed gather ----------------
__global__ void embed_kernel(const int* __restrict__ tokens,
                             const float* __restrict__ embed)
{
    int t = blockIdx.x;                 // token id 0..4095
    int tok = tokens[t];
    const float4* src = (const float4*)(embed + (size_t)tok * DD);
    float4* dst = (float4*)(g_x + (size_t)t * DD);
    for (int i = threadIdx.x; i < DD/4; i += blockDim.x)
        dst[i] = src[i];
}

// ---------------- rmsnorm ----------------
__global__ void rmsnorm_kernel(const float* __restrict__ x,
                               const float* __restrict__ w,
                               float* __restrict__ o)
{
    int t = blockIdx.x;
    const float4* xr = (const float4*)(x + (size_t)t * DD);
    const float4* wr = (const float4*)w;
    float4* orow = (float4*)(o + (size_t)t * DD);

    float s = 0.f;
    for (int i = threadIdx.x; i < DD/4; i += blockDim.x) {
        float4 v = xr[i];
        s += v.x*v.x + v.y*v.y + v.z*v.z + v.w*v.w;
    }
    // block reduce (256 threads = 8 warps)
    __shared__ float red[8];
    for (int m = 16; m > 0; m >>= 1) s += __shfl_xor_sync(0xffffffffu, s, m);
    if ((threadIdx.x & 31) == 0) red[threadIdx.x >> 5] = s;
    __syncthreads();
    float tot = 0.f;
    if (threadIdx.x < 8) tot = red[threadIdx.x];
    for (int m = 4; m > 0; m >>= 1) tot += __shfl_xor_sync(0xffffffffu, tot, m);
    __shared__ float inv_s;
    if (threadIdx.x == 0) inv_s = rsqrtf(tot / (float)DD + 1e-5f);
    __syncthreads();
    float inv = inv_s;

    for (int i = threadIdx.x; i < DD/4; i += blockDim.x) {
        float4 v = xr[i];
        float4 wv = wr[i];
        v.x = v.x * wv.x * inv;
        v.y = v.y * wv.y * inv;
        v.z = v.z * wv.z * inv;
        v.w = v.w * wv.w * inv;
        orow[i] = v;
    }
}

// ---------------- causal conv (K=4) + silu ----------------
__global__ void conv_silu_kernel(const float* __restrict__ conv_w,
                                 const float* __restrict__ conv_b)
{
    int idx = blockIdx.x * blockDim.x + threadIdx.x;  // over NTOK*EE
    if (idx >= NTOK * EE) return;
    int e = idx % EE;
    int tk = idx / EE;          // global token index  (b*L + t)
    int t = tk % LL;

    const float* src = g_xz + (size_t)(tk - t) * (2*EE) + e;  // start of this batch row, col e
    float acc = conv_b[e];
    #pragma unroll
    for (int k = 0; k < KK; k++) {
        int tt = t + k - (KK - 1);
        if (tt >= 0)
            acc = fmaf(conv_w[e*KK + k], src[(size_t)tt * (2*EE)], acc);
    }
    // silu
    float sg = 1.f / (1.f + __expf(-acc));
    g_xc[idx] = acc * sg;
}

// ---------------- SGEMM (128x128x8, 8x8/thread) ----------------
// EPI: 0 = store, 1 = C += acc (residual), 2 = softplus(acc + bias[col])
// TB : false -> B is (K,N) row-major ; true -> B is (N,K) row-major (C = A*B^T)
__device__ __forceinline__ float softplus_f(float v) {
    return (v > 20.f) ? v : log1pf(expf(v));
}

template<int EPI, bool TB>
__global__ __launch_bounds__(256)
void sgemm(const float* __restrict__ A, const float* __restrict__ B,
           float* __restrict__ C, const float* __restrict__ bias,
           int M, int N, int K, int lda, int ldb, int ldc)
{
    __shared__ float As[8][128];
    __shared__ float Bs[8][128];

    int tid = threadIdx.x;
    int tx = tid & 15;
    int ty = tid >> 4;
    int bm = blockIdx.y * 128;
    int bn = blockIdx.x * 128;

    float acc[8][8];
    #pragma unroll
    for (int i = 0; i < 8; i++)
        #pragma unroll
        for (int j = 0; j < 8; j++) acc[i][j] = 0.f;

    const int a_row = tid >> 1;
    const int a_col = (tid & 1) * 4;

    for (int k0 = 0; k0 < K; k0 += 8) {
        // A tile: 128 rows x 8 k  (M always multiple of 128 here)
        float4 av = *(const float4*)(A + (size_t)(bm + a_row) * lda + k0 + a_col);
        As[a_col+0][a_row] = av.x;
        As[a_col+1][a_row] = av.y;
        As[a_col+2][a_row] = av.z;
        As[a_col+3][a_row] = av.w;

        if (!TB) {
            int kr   = tid >> 5;
            int col4 = (tid & 31) * 4;
            float4 bv = make_float4(0.f, 0.f, 0.f, 0.f);
            if (bn + col4 < N)
                bv = *(const float4*)(B + (size_t)(k0 + kr) * ldb + bn + col4);
            *(float4*)(&Bs[kr][col4]) = bv;
        } else {
            int nr = tid >> 1;
            int kc = (tid & 1) * 4;
            float4 bv = make_float4(0.f, 0.f, 0.f, 0.f);
            if (bn + nr < N)
                bv = *(const float4*)(B + (size_t)(bn + nr) * ldb + k0 + kc);
            Bs[kc+0][nr] = bv.x;
            Bs[kc+1][nr] = bv.y;
            Bs[kc+2][nr] = bv.z;
            Bs[kc+3][nr] = bv.w;
        }
        __syncthreads();

        #pragma unroll
        for (int kk = 0; kk < 8; kk++) {
            float ar[8], br[8];
            *(float4*)(ar)     = *(const float4*)(&As[kk][ty*8]);
            *(float4*)(ar + 4) = *(const float4*)(&As[kk][ty*8 + 4]);
            *(float4*)(br)     = *(const float4*)(&Bs[kk][tx*8]);
            *(float4*)(br + 4) = *(const float4*)(&Bs[kk][tx*8 + 4]);
            #pragma unroll
            for (int i = 0; i < 8; i++)
                #pragma unroll
                for (int j = 0; j < 8; j++)
                    acc[i][j] = fmaf(ar[i], br[j], acc[i][j]);
        }
        __syncthreads();
    }

    // epilogue
    #pragma unroll
    for (int i = 0; i < 8; i++) {
        size_t row = (size_t)(bm + ty*8 + i);
        #pragma unroll
        for (int j4 = 0; j4 < 8; j4 += 4) {
            int col = bn + tx*8 + j4;
            if (col < N) {
                float* cp = C + row * ldc + col;
                float4 v = make_float4(acc[i][j4], acc[i][j4+1], acc[i][j4+2], acc[i][j4+3]);
                if (EPI == 1) {
                    float4 o = *(const float4*)cp;
                    v.x += o.x; v.y += o.y; v.z += o.z; v.w += o.w;
                } else if (EPI == 2) {
                    v.x = softplus_f(v.x + bias[col]);
                    v.y = softplus_f(v.y + bias[col+1]);
                    v.z = softplus_f(v.z + bias[col+2]);
                    v.w = softplus_f(v.w + bias[col+3]);
                }
                *(float4*)cp = v;
            }
        }
    }
}

// ---------------- selective scan ----------------
// 16 lanes per channel (one per state n). 128 threads = 8 channels per block.
// Fuses: y = (scan_y + xc*D_skip) * silu(z)
__global__ __launch_bounds__(128)
void scan_kernel(const float* __restrict__ A_log,
                 const float* __restrict__ D_skip)
{
    int group = threadIdx.x >> 4;       // 0..7
    int n     = threadIdx.x & 15;       // state index
    int ch    = blockIdx.x * 8 + group; // 0..4095
    int b = ch >> 11;                   // / EE
    int e = ch & (EE - 1);

    float a   = -__expf(A_log[e * NN_ + n]);
    float dsk = D_skip[e];
    float h = 0.f;

    const float* dt_p = g_dt  + (size_t)b*LL*EE + e;
    const float* x_p  = g_xc  + (size_t)b*LL*EE + e;
    const float* z_p  = g_xz  + (size_t)b*LL*(2*EE) + EE + e;
    const float* bl_p = g_dbl + (size_t)b*LL*96 + 64 + n;   // Bc at +64, Cc at +80
    float*       y_p  = g_y   + (size_t)b*LL*EE + e;

    for (int t = 0; t < LL; t++) {
        float dte = __ldg(dt_p);
        float xe  = __ldg(x_p);
        float Bn  = __ldg(bl_p);
        float Cn  = __ldg(bl_p + 16);
        float dA  = __expf(dte * a);
        h = fmaf(h, dA, dte * xe * Bn);
        float p = h * Cn;
        p += __shfl_xor_sync(0xffffffffu, p, 8);
        p += __shfl_xor_sync(0xffffffffu, p, 4);
        p += __shfl_xor_sync(0xffffffffu, p, 2);
        p += __shfl_xor_sync(0xffffffffu, p, 1);
        if (n == 0) {
            float z = __ldg(z_p);
            float sig = 1.f / (1.f + __expf(-z));
            *y_p = (p + xe * dsk) * (z * sig);
        }
        dt_p += EE; x_p += EE; z_p += 2*EE; bl_p += 96; y_p += EE;
    }
}

// ---------------- host launch ----------------
extern "C" void kernel_launch(void* const* d_in, const int* in_sizes, int n_in,
                              void* d_out, int out_size)
{
    const int*   tokens   = (const int*)  d_in[0];
    const float* embed    = (const float*)d_in[1];
    const float* norm_w   = (const float*)d_in[2];
    const float* W_in     = (const float*)d_in[3];
    const float* conv_w   = (const float*)d_in[4];
    const float* conv_b   = (const float*)d_in[5];
    const float* W_xproj  = (const float*)d_in[6];
    const float* W_dt     = (const float*)d_in[7];
    const float* dt_bias  = (const float*)d_in[8];
    const float* A_log    = (const float*)d_in[9];
    const float* D_skip   = (const float*)d_in[10];
    const float* W_out    = (const float*)d_in[11];
    const float* final_nw = (const float*)d_in[12];
    const float* lm_head  = (const float*)d_in[13];
    float* out = (float*)d_out;

    float *px, *pxn, *pxz, *pxc, *pdbl, *pdt, *py;
    cudaGetSymbolAddress((void**)&px,   g_x);
    cudaGetSymbolAddress((void**)&pxn,  g_xn);
    cudaGetSymbolAddress((void**)&pxz,  g_xz);
    cudaGetSymbolAddress((void**)&pxc,  g_xc);
    cudaGetSymbolAddress((void**)&pdbl, g_dbl);
    cudaGetSymbolAddress((void**)&pdt,  g_dt);
    cudaGetSymbolAddress((void**)&py,   g_y);

    // embed gather
    embed_kernel<<<NTOK, 256>>>(tokens, embed);

    for (int l = 0; l < NLAYERS; l++) {
        const float* nw  = norm_w  + (size_t)l * DD;
        const float* win = W_in    + (size_t)l * DD * 2 * EE;
        const float* cw  = conv_w  + (size_t)l * EE * KK;
        const float* cb  = conv_b  + (size_t)l * EE;
        const float* wxp = W_xproj + (size_t)l * EE * 96;
        const float* wdt = W_dt    + (size_t)l * RR * EE;
        const float* dtb = dt_bias + (size_t)l * EE;
        const float* alg = A_log   + (size_t)l * EE * NN_;
        const float* dsk = D_skip  + (size_t)l * EE;
        const float* wo  = W_out   + (size_t)l * EE * DD;

        // 1. rmsnorm
        rmsnorm_kernel<<<NTOK, 256>>>(px, nw, pxn);

        // 2. xz = xn @ W_in   (4096 x 4096 x 1024)
        sgemm<0,false><<<dim3(2*EE/128, NTOK/128), 256>>>(
            pxn, win, pxz, nullptr, NTOK, 2*EE, DD, DD, 2*EE, 2*EE);

        // 3. causal conv + silu  -> g_xc
        conv_silu_kernel<<<(NTOK*EE + 255)/256, 256>>>(cw, cb);

        // 4. dbl = xc @ W_xproj  (4096 x 96 x 2048)
        sgemm<0,false><<<dim3(1, NTOK/128), 256>>>(
            pxc, wxp, pdbl, nullptr, NTOK, 96, EE, EE, 96, 96);

        // 5. dt = softplus(dbl[:, :64] @ W_dt + dt_bias)  (4096 x 2048 x 64)
        sgemm<2,false><<<dim3(EE/128, NTOK/128), 256>>>(
            pdbl, wdt, pdt, dtb, NTOK, EE, RR, 96, EE, EE);

        // 6. selective scan + gate  -> g_y
        scan_kernel<<<(BB*EE)/8, 128>>>(alg, dsk);

        // 7. x += y @ W_out  (4096 x 1024 x 2048)
        sgemm<1,false><<<dim3(DD/128, NTOK/128), 256>>>(
            py, wo, px, nullptr, NTOK, DD, EE, EE, DD, DD);
    }

    // final rmsnorm
    rmsnorm_kernel<<<NTOK, 256>>>(px, final_nw, pxn);

    // logits = xn @ lm_head^T  (4096 x 32000 x 1024)
    sgemm<0,true><<<dim3(VV/128, NTOK/128), 256>>>(
        pxn, lm_head, out, nullptr, NTOK, VV, DD, DD, DD, VV);
}

// round 3
// speedup vs baseline: 1.8517x; 1.8517x over previous
#include <cuda_runtime.h>
#include <cuda_bf16.h>
#include <math.h>
#include <stdint.h>

// Problem dims
#define BB 2
#define LL 2048
#define DD 1024
#define VV 32000
#define NLAYERS 2
#define EE 2048
#define NN_ 16
#define RR 64
#define KK 4
#define NTOK (BB*LL)          // 4096 tokens

// ---------------- scratch (device globals; no allocation allowed) ----------
__device__ float g_x  [NTOK*DD];
__device__ float g_xn [NTOK*DD];
__device__ float g_xz [NTOK*2*EE];
__device__ float g_xc [NTOK*EE];
__device__ float g_dbl[NTOK*96];
__device__ float g_dt [NTOK*EE];
__device__ float g_y  [NTOK*EE];
// bf16 split weight buffers (sized for lm_head: 32000x1024)
__device__ __nv_bfloat16 g_bh[VV*DD];
__device__ __nv_bfloat16 g_bl[VV*DD];

// ======================= helpers ==============================
__device__ __forceinline__ uint32_t smem_u32(const void* p) {
    uint32_t a;
    asm("{ .reg .u64 t; cvta.to.shared.u64 t, %1; cvt.u32.u64 %0, t; }" : "=r"(a) : "l"(p));
    return a;
}
#define SWZ(off) ((off) ^ (((off) >> 3) & 0x70))

__device__ __forceinline__ void ldsm4(uint32_t addr, uint32_t* r) {
    asm volatile("ldmatrix.sync.aligned.m8n8.x4.shared.b16 {%0,%1,%2,%3}, [%4];"
                 : "=r"(r[0]), "=r"(r[1]), "=r"(r[2]), "=r"(r[3]) : "r"(addr));
}
__device__ __forceinline__ void mma_bf16(float* d, const uint32_t* a, uint32_t b0, uint32_t b1) {
    asm volatile(
        "mma.sync.aligned.m16n8k16.row.col.f32.bf16.bf16.f32 "
        "{%0,%1,%2,%3}, {%4,%5,%6,%7}, {%8,%9}, {%0,%1,%2,%3};"
        : "+f"(d[0]), "+f"(d[1]), "+f"(d[2]), "+f"(d[3])
        : "r"(a[0]), "r"(a[1]), "r"(a[2]), "r"(a[3]), "r"(b0), "r"(b1));
}

__device__ __forceinline__ float softplus_f(float v) {
    return (v > 20.f) ? v : log1pf(expf(v));
}

// smem: double buffer; each buf: Ah(16K) Al(16K) Bh(16K) Bl(16K) = 64KB
#define BUF_BYTES 65536
#define OFF_AH 0
#define OFF_AL 16384
#define OFF_BH 32768
#define OFF_BL 49152
#define SMEM_BYTES (2*BUF_BYTES)

// ======================= mma.sync GEMM =======================================
// C[M,N] = A[M,K](fp32,row-major,lda) @ B^T, Bh/Bl bf16 [N,K] K-major (stride ldb)
// grid: (M/128, ceil(N/128));  EPI: 0=store, 1=C+=acc, 2=softplus(acc+bias[col])
template<int EPI>
__global__ __launch_bounds__(256)
void mmagemm(const float* __restrict__ A,
             const __nv_bfloat16* __restrict__ Bh, const __nv_bfloat16* __restrict__ Bl,
             float* __restrict__ C, const float* __restrict__ bias,
             int N, int K, int lda, int ldb, int ldc)
{
    extern __shared__ __align__(1024) char smem[];
    uint32_t sb = smem_u32(smem);
    const int tid = threadIdx.x;
    const int lane = tid & 31;
    const int wid = tid >> 5;
    const int warp_m = wid >> 1;       // 0..3 -> 32-row slices
    const int warp_n = wid & 1;        // 0..1 -> 64-col slices
    const int bm = blockIdx.x * 128;
    const int bn = blockIdx.y * 128;

    float acc[2][8][4];
    #pragma unroll
    for (int i = 0; i < 2; i++)
        #pragma unroll
        for (int j = 0; j < 8; j++)
            #pragma unroll
            for (int q = 0; q < 4; q++) acc[i][j][q] = 0.f;

    // staging register sets
    float4 a[8]; uint4 vbh[4], vbl[4];

    // decomposed staging indices
    const int a_row  = tid >> 1;            // 2048 float4: idx= i*256+tid, row=idx>>4
    // (we compute per-i below instead)

    const int nch = K >> 6;

    // ---- LDG chunk helper (macro-ish via lambda) ----
    auto LDGchunk = [&](int c) {
        const int k0 = c << 6;
        const float* Ab = A + (size_t)bm * lda + k0;
        #pragma unroll
        for (int i = 0; i < 8; i++) {
            int idx = i * 256 + tid;
            int row = idx >> 4, c4 = idx & 15;
            a[i] = *(const float4*)(Ab + (size_t)row * lda + c4 * 4);
        }
        const __nv_bfloat16* Bhb = Bh + k0;
        const __nv_bfloat16* Blb = Bl + k0;
        #pragma unroll
        for (int i = 0; i < 4; i++) {
            int idx = i * 256 + tid;
            int row = idx >> 3, c16 = idx & 7;
            if (bn + row < N) {
                vbh[i] = *(const uint4*)(Bhb + (size_t)(bn + row) * ldb + c16 * 8);
                vbl[i] = *(const uint4*)(Blb + (size_t)(bn + row) * ldb + c16 * 8);
            } else {
                vbh[i] = make_uint4(0,0,0,0);
                vbl[i] = make_uint4(0,0,0,0);
            }
        }
    };
    auto STSchunk = [&](int bufsel) {
        char* base = smem + bufsel * BUF_BYTES;
        #pragma unroll
        for (int i = 0; i < 8; i++) {
            int idx = i * 256 + tid;
            int row = idx >> 4, c4 = idx & 15;
            uint32_t so = SWZ((uint32_t)(row * 128 + c4 * 8));
            float4 v = a[i];
            __nv_bfloat162 h0 = __floats2bfloat162_rn(v.x, v.y);
            __nv_bfloat162 h1 = __floats2bfloat162_rn(v.z, v.w);
            float lx = v.x - __bfloat162float(h0.x);
            float ly = v.y - __bfloat162float(h0.y);
            float lz = v.z - __bfloat162float(h1.x);
            float lw = v.w - __bfloat162float(h1.y);
            __nv_bfloat162 l0 = __floats2bfloat162_rn(lx, ly);
            __nv_bfloat162 l1 = __floats2bfloat162_rn(lz, lw);
            uint2 hh, llv;
            hh.x = *(uint32_t*)&h0;  hh.y = *(uint32_t*)&h1;
            llv.x = *(uint32_t*)&l0; llv.y = *(uint32_t*)&l1;
            *(uint2*)(base + OFF_AH + so) = hh;
            *(uint2*)(base + OFF_AL + so) = llv;
        }
        #pragma unroll
        for (int i = 0; i < 4; i++) {
            int idx = i * 256 + tid;
            int row = idx >> 3, c16 = idx & 7;
            uint32_t so = SWZ((uint32_t)(row * 128 + c16 * 16));
            *(uint4*)(base + OFF_BH + so) = vbh[i];
            *(uint4*)(base + OFF_BL + so) = vbl[i];
        }
    };

    // prologue
    LDGchunk(0);
    STSchunk(0);
    __syncthreads();

    // lane-derived fragment addresses (constant parts)
    const int arow_l  = warp_m * 32 + (lane & 15);          // + mi*16
    const int akoff_l = (lane >> 4) << 4;                   // byte offset of k half
    const int brow_l  = warp_n * 64 + (lane & 7) + ((lane >> 4) << 3);   // + nj2*16
    const int bkoff_l = ((lane >> 3) & 1) << 4;

    for (int c = 0; c < nch; c++) {
        const bool more = (c + 1 < nch);
        if (more) LDGchunk(c + 1);

        uint32_t base = sb + (uint32_t)((c & 1) * BUF_BYTES);
        #pragma unroll
        for (int ks = 0; ks < 4; ks++) {
            uint32_t ah[2][4], al[2][4], bh[4][4], bl[4][4];
            const int kb = ks * 32;
            #pragma unroll
            for (int mi = 0; mi < 2; mi++) {
                uint32_t off = SWZ((uint32_t)((arow_l + mi * 16) * 128 + kb + akoff_l));
                ldsm4(base + OFF_AH + off, ah[mi]);
                ldsm4(base + OFF_AL + off, al[mi]);
            }
            #pragma unroll
            for (int nj2 = 0; nj2 < 4; nj2++) {
                uint32_t off = SWZ((uint32_t)((brow_l + nj2 * 16) * 128 + kb + bkoff_l));
                ldsm4(base + OFF_BH + off, bh[nj2]);
                ldsm4(base + OFF_BL + off, bl[nj2]);
            }
            #pragma unroll
            for (int mi = 0; mi < 2; mi++) {
                #pragma unroll
                for (int nj = 0; nj < 8; nj++) {
                    int nj2 = nj >> 1, hi = (nj & 1) * 2;
                    mma_bf16(acc[mi][nj], ah[mi], bh[nj2][hi], bh[nj2][hi + 1]);
                    mma_bf16(acc[mi][nj], ah[mi], bl[nj2][hi], bl[nj2][hi + 1]);
                    mma_bf16(acc[mi][nj], al[mi], bh[nj2][hi], bh[nj2][hi + 1]);
                }
            }
        }
        if (more) STSchunk((c + 1) & 1);
        __syncthreads();
    }

    // ---- epilogue: direct float2 stores ----
    #pragma unroll
    for (int mi = 0; mi < 2; mi++) {
        #pragma unroll
        for (int nj = 0; nj < 8; nj++) {
            int row = bm + warp_m * 32 + mi * 16 + (lane >> 2);
            int col = bn + warp_n * 64 + nj * 8 + (lane & 3) * 2;
            if (col < N) {
                float* d = acc[mi][nj];
                float2 v0 = make_float2(d[0], d[1]);
                float2 v1 = make_float2(d[2], d[3]);
                float* p0 = C + (size_t)row * ldc + col;
                float* p1 = C + (size_t)(row + 8) * ldc + col;
                if (EPI == 1) {
                    float2 o0 = *(float2*)p0; v0.x += o0.x; v0.y += o0.y;
                    float2 o1 = *(float2*)p1; v1.x += o1.x; v1.y += o1.y;
                } else if (EPI == 2) {
                    float b0 = bias[col], b1 = bias[col + 1];
                    v0.x = softplus_f(v0.x + b0); v0.y = softplus_f(v0.y + b1);
                    v1.x = softplus_f(v1.x + b0); v1.y = softplus_f(v1.y + b1);
                }
                *(float2*)p0 = v0;
                *(float2*)p1 = v1;
            }
        }
    }
}

// ============== weight prep: fp32 (K,N) -> bf16 hi/lo [N,K] ==============
__global__ void transpose_split(const float* __restrict__ W, int K, int N,
                                __nv_bfloat16* __restrict__ Bh, __nv_bfloat16* __restrict__ Bl)
{
    __shared__ float t[32][33];
    int k0 = blockIdx.x * 32, n0 = blockIdx.y * 32;
    int tx = threadIdx.x, ty = threadIdx.y;   // 32 x 8
    #pragma unroll
    for (int i = 0; i < 4; i++) {
        int k = k0 + ty + 8 * i;
        float v = (n0 + tx < N) ? W[(size_t)k * N + n0 + tx] : 0.f;
        t[ty + 8 * i][tx] = v;
    }
    __syncthreads();
    #pragma unroll
    for (int i = 0; i < 4; i++) {
        int n = n0 + ty + 8 * i;
        int k = k0 + tx;
        float v = t[tx][ty + 8 * i];
        __nv_bfloat16 h = __float2bfloat16(v);
        __nv_bfloat16 l = __float2bfloat16(v - __bfloat162float(h));
        Bh[(size_t)n * K + k] = h;
        Bl[(size_t)n * K + k] = l;
    }
}

// elementwise split (already [N,K] layout): lm_head
__global__ void split_kernel(const float4* __restrict__ W,
                             __nv_bfloat16* __restrict__ Bh, __nv_bfloat16* __restrict__ Bl, int n4)
{
    int i = blockIdx.x * blockDim.x + threadIdx.x;
    if (i >= n4) return;
    float4 v = W[i];
    __nv_bfloat162 h0 = __floats2bfloat162_rn(v.x, v.y);
    __nv_bfloat162 h1 = __floats2bfloat162_rn(v.z, v.w);
    float lx = v.x - __bfloat162float(h0.x);
    float ly = v.y - __bfloat162float(h0.y);
    float lz = v.z - __bfloat162float(h1.x);
    float lw = v.w - __bfloat162float(h1.y);
    __nv_bfloat162 l0 = __floats2bfloat162_rn(lx, ly);
    __nv_bfloat162 l1 = __floats2bfloat162_rn(lz, lw);
    uint2 hh, llv;
    hh.x = *(uint32_t*)&h0;  hh.y = *(uint32_t*)&h1;
    llv.x = *(uint32_t*)&l0; llv.y = *(uint32_t*)&l1;
    ((uint2*)Bh)[i] = hh;
    ((uint2*)Bl)[i] = llv;
}

// ---------------- embed gather ----------------
__global__ void embed_kernel(const int* __restrict__ tokens,
                             const float* __restrict__ embed)
{
    int t = blockIdx.x;
    int tok = tokens[t];
    const float4* src = (const float4*)(embed + (size_t)tok * DD);
    float4* dst = (float4*)(g_x + (size_t)t * DD);
    for (int i = threadIdx.x; i < DD/4; i += blockDim.x)
        dst[i] = src[i];
}

// ---------------- rmsnorm ----------------
__global__ void rmsnorm_kernel(const float* __restrict__ x,
                               const float* __restrict__ w,
                               float* __restrict__ o)
{
    int t = blockIdx.x;
    const float4* xr = (const float4*)(x + (size_t)t * DD);
    const float4* wr = (const float4*)w;
    float4* orow = (float4*)(o + (size_t)t * DD);

    float s = 0.f;
    for (int i = threadIdx.x; i < DD/4; i += blockDim.x) {
        float4 v = xr[i];
        s += v.x*v.x + v.y*v.y + v.z*v.z + v.w*v.w;
    }
    __shared__ float red[8];
    for (int m = 16; m > 0; m >>= 1) s += __shfl_xor_sync(0xffffffffu, s, m);
    if ((threadIdx.x & 31) == 0) red[threadIdx.x >> 5] = s;
    __syncthreads();
    float tot = 0.f;
    if (threadIdx.x < 8) tot = red[threadIdx.x];
    for (int m = 4; m > 0; m >>= 1) tot += __shfl_xor_sync(0xffffffffu, tot, m);
    __shared__ float inv_s;
    if (threadIdx.x == 0) inv_s = rsqrtf(tot / (float)DD + 1e-5f);
    __syncthreads();
    float inv = inv_s;

    for (int i = threadIdx.x; i < DD/4; i += blockDim.x) {
        float4 v = xr[i];
        float4 wv = wr[i];
        v.x = v.x * wv.x * inv;
        v.y = v.y * wv.y * inv;
        v.z = v.z * wv.z * inv;
        v.w = v.w * wv.w * inv;
        orow[i] = v;
    }
}

// ---------------- causal conv (K=4) + silu ----------------
__global__ void conv_silu_kernel(const float* __restrict__ conv_w,
                                 const float* __restrict__ conv_b)
{
    int idx = blockIdx.x * blockDim.x + threadIdx.x;
    if (idx >= NTOK * EE) return;
    int e = idx % EE;
    int tk = idx / EE;
    int t = tk % LL;

    const float* src = g_xz + (size_t)(tk - t) * (2*EE) + e;
    float acc = conv_b[e];
    #pragma unroll
    for (int k = 0; k < KK; k++) {
        int tt = t + k - (KK - 1);
        if (tt >= 0)
            acc = fmaf(conv_w[e*KK + k], src[(size_t)tt * (2*EE)], acc);
    }
    float sg = 1.f / (1.f + __expf(-acc));
    g_xc[idx] = acc * sg;
}

// ---------------- selective scan ----------------
__global__ __launch_bounds__(128)
void scan_kernel(const float* __restrict__ A_log,
                 const float* __restrict__ D_skip)
{
    int group = threadIdx.x >> 4;
    int n     = threadIdx.x & 15;
    int ch    = blockIdx.x * 8 + group;
    int b = ch >> 11;
    int e = ch & (EE - 1);

    float a   = -__expf(A_log[e * NN_ + n]);
    float dsk = D_skip[e];
    float h = 0.f;

    const float* dt_p = g_dt  + (size_t)b*LL*EE + e;
    const float* x_p  = g_xc  + (size_t)b*LL*EE + e;
    const float* z_p  = g_xz  + (size_t)b*LL*(2*EE) + EE + e;
    const float* bl_p = g_dbl + (size_t)b*LL*96 + 64 + n;
    float*       y_p  = g_y   + (size_t)b*LL*EE + e;

    for (int t = 0; t < LL; t++) {
        float dte = __ldg(dt_p);
        float xe  = __ldg(x_p);
        float Bn  = __ldg(bl_p);
        float Cn  = __ldg(bl_p + 16);
        float dA  = __expf(dte * a);
        h = fmaf(h, dA, dte * xe * Bn);
        float p = h * Cn;
        p += __shfl_xor_sync(0xffffffffu, p, 8);
        p += __shfl_xor_sync(0xffffffffu, p, 4);
        p += __shfl_xor_sync(0xffffffffu, p, 2);
        p += __shfl_xor_sync(0xffffffffu, p, 1);
        if (n == 0) {
            float z = __ldg(z_p);
            float sig = 1.f / (1.f + __expf(-z));
            *y_p = (p + xe * dsk) * (z * sig);
        }
        dt_p += EE; x_p += EE; z_p += 2*EE; bl_p += 96; y_p += EE;
    }
}

// ---------------- host launch ----------------
extern "C" void kernel_launch(void* const* d_in, const int* in_sizes, int n_in,
                              void* d_out, int out_size)
{
    const int*   tokens   = (const int*)  d_in[0];
    const float* embed    = (const float*)d_in[1];
    const float* norm_w   = (const float*)d_in[2];
    const float* W_in     = (const float*)d_in[3];
    const float* conv_w   = (const float*)d_in[4];
    const float* conv_b   = (const float*)d_in[5];
    const float* W_xproj  = (const float*)d_in[6];
    const float* W_dt     = (const float*)d_in[7];
    const float* dt_bias  = (const float*)d_in[8];
    const float* A_log    = (const float*)d_in[9];
    const float* D_skip   = (const float*)d_in[10];
    const float* W_out    = (const float*)d_in[11];
    const float* final_nw = (const float*)d_in[12];
    const float* lm_head  = (const float*)d_in[13];
    float* out = (float*)d_out;

    float *px, *pxn, *pxz, *pxc, *pdbl, *pdt, *py;
    __nv_bfloat16 *pbh, *pbl;
    cudaGetSymbolAddress((void**)&px,   g_x);
    cudaGetSymbolAddress((void**)&pxn,  g_xn);
    cudaGetSymbolAddress((void**)&pxz,  g_xz);
    cudaGetSymbolAddress((void**)&pxc,  g_xc);
    cudaGetSymbolAddress((void**)&pdbl, g_dbl);
    cudaGetSymbolAddress((void**)&pdt,  g_dt);
    cudaGetSymbolAddress((void**)&py,   g_y);
    cudaGetSymbolAddress((void**)&pbh,  g_bh);
    cudaGetSymbolAddress((void**)&pbl,  g_bl);

    static bool attr_done = false;
    if (!attr_done) {
        cudaFuncSetAttribute(mmagemm<0>, cudaFuncAttributeMaxDynamicSharedMemorySize, SMEM_BYTES);
        cudaFuncSetAttribute(mmagemm<1>, cudaFuncAttributeMaxDynamicSharedMemorySize, SMEM_BYTES);
        cudaFuncSetAttribute(mmagemm<2>, cudaFuncAttributeMaxDynamicSharedMemorySize, SMEM_BYTES);
        attr_done = true;
    }

    embed_kernel<<<NTOK, 256>>>(tokens, embed);

    for (int l = 0; l < NLAYERS; l++) {
        const float* nw  = norm_w  + (size_t)l * DD;
        const float* win = W_in    + (size_t)l * DD * 2 * EE;
        const float* cw  = conv_w  + (size_t)l * EE * KK;
        const float* cb  = conv_b  + (size_t)l * EE;
        const float* wxp = W_xproj + (size_t)l * EE * 96;
        const float* wdt = W_dt    + (size_t)l * RR * EE;
        const float* dtb = dt_bias + (size_t)l * EE;
        const float* alg = A_log   + (size_t)l * EE * NN_;
        const float* dsk = D_skip  + (size_t)l * EE;
        const float* wo  = W_out   + (size_t)l * EE * DD;

        // 1. rmsnorm
        rmsnorm_kernel<<<NTOK, 256>>>(px, nw, pxn);

        // 2. xz = xn @ W_in   (4096 x 4096 x 1024)
        transpose_split<<<dim3(DD/32, (2*EE)/32), dim3(32,8)>>>(win, DD, 2*EE, pbh, pbl);
        mmagemm<0><<<dim3(NTOK/128, (2*EE)/128), 256, SMEM_BYTES>>>(
            pxn, pbh, pbl, pxz, nullptr, 2*EE, DD, DD, DD, 2*EE);

        // 3. causal conv + silu
        conv_silu_kernel<<<(NTOK*EE + 255)/256, 256>>>(cw, cb);

        // 4. dbl = xc @ W_xproj  (4096 x 96 x 2048)
        transpose_split<<<dim3(EE/32, 128/32), dim3(32,8)>>>(wxp, EE, 96, pbh, pbl);
        mmagemm<0><<<dim3(NTOK/128, 1), 256, SMEM_BYTES>>>(
            pxc, pbh, pbl, pdbl, nullptr, 96, EE, EE, EE, 96);

        // 5. dt = softplus(dbl[:, :64] @ W_dt + dt_bias)  (4096 x 2048 x 64)
        transpose_split<<<dim3(RR/32, EE/32), dim3(32,8)>>>(wdt, RR, EE, pbh, pbl);
        mmagemm<2><<<dim3(NTOK/128, EE/128), 256, SMEM_BYTES>>>(
            pdbl, pbh, pbl, pdt, dtb, EE, RR, 96, RR, EE);

        // 6. selective scan + gate
        scan_kernel<<<(BB*EE)/8, 128>>>(alg, dsk);

        // 7. x += y @ W_out  (4096 x 1024 x 2048)
        transpose_split<<<dim3(EE/32, DD/32), dim3(32,8)>>>(wo, EE, DD, pbh, pbl);
        mmagemm<1><<<dim3(NTOK/128, DD/128), 256, SMEM_BYTES>>>(
            py, pbh, pbl, px, nullptr, DD, EE, EE, EE, DD);
    }

    // final rmsnorm
    rmsnorm_kernel<<<NTOK, 256>>>(px, final_nw, pxn);

    // logits = xn @ lm_head^T  (4096 x 32000 x 1024); lm_head already [N,K]
    split_kernel<<<(VV*DD/4 + 255)/256, 256>>>((const float4*)lm_head, pbh, pbl, VV*DD/4);
    mmagemm<0><<<dim3(NTOK/128, VV/128), 256, SMEM_BYTES>>>(
        pxn, pbh, pbl, out, nullptr, VV, DD, DD, DD, VV);
}

// round 4
// speedup vs baseline: 1.8981x; 1.0251x over previous
#include <cuda_runtime.h>
#include <cuda_bf16.h>
#include <math.h>
#include <stdint.h>

// Problem dims
#define BB 2
#define LL 2048
#define DD 1024
#define VV 32000
#define NLAYERS 2
#define EE 2048
#define NN_ 16
#define RR 64
#define KK 4
#define NTOK (BB*LL)          // 4096 tokens

// ---------------- scratch (device globals; no allocation allowed) ----------
__device__ float g_x  [NTOK*DD];               // residual fp32
__device__ __nv_bfloat16 g_xnh[NTOK*DD];       // rmsnorm out hi
__device__ __nv_bfloat16 g_xnl[NTOK*DD];       // rmsnorm out lo
__device__ float g_xz [NTOK*2*EE];             // W_in out fp32
__device__ __nv_bfloat16 g_xch[NTOK*EE];       // conv+silu out hi
__device__ __nv_bfloat16 g_xcl[NTOK*EE];       // conv+silu out lo
__device__ float g_dbl [NTOK*96];              // xproj out fp32 (scan reads B,C)
__device__ __nv_bfloat16 g_dblh[NTOK*96];
__device__ __nv_bfloat16 g_dbll[NTOK*96];
__device__ float g_dt [NTOK*EE];               // softplus(dt) fp32
__device__ __nv_bfloat16 g_yh[NTOK*EE];        // scan out hi
__device__ __nv_bfloat16 g_yl[NTOK*EE];        // scan out lo
// bf16 split weight buffers (sized for lm_head: 32000x1024)
__device__ __nv_bfloat16 g_bh[VV*DD];
__device__ __nv_bfloat16 g_bl[VV*DD];

// ======================= helpers ==============================
__device__ __forceinline__ uint32_t smem_u32(const void* p) {
    uint32_t a;
    asm("{ .reg .u64 t; cvta.to.shared.u64 t, %1; cvt.u32.u64 %0, t; }" : "=r"(a) : "l"(p));
    return a;
}
#define SWZ(off) ((off) ^ (((off) >> 3) & 0x70))

__device__ __forceinline__ void ldsm4(uint32_t addr, uint32_t* r) {
    asm volatile("ldmatrix.sync.aligned.m8n8.x4.shared.b16 {%0,%1,%2,%3}, [%4];"
                 : "=r"(r[0]), "=r"(r[1]), "=r"(r[2]), "=r"(r[3]) : "r"(addr));
}
__device__ __forceinline__ void mma_bf16(float* d, const uint32_t* a, uint32_t b0, uint32_t b1) {
    asm volatile(
        "mma.sync.aligned.m16n8k16.row.col.f32.bf16.bf16.f32 "
        "{%0,%1,%2,%3}, {%4,%5,%6,%7}, {%8,%9}, {%0,%1,%2,%3};"
        : "+f"(d[0]), "+f"(d[1]), "+f"(d[2]), "+f"(d[3])
        : "r"(a[0]), "r"(a[1]), "r"(a[2]), "r"(a[3]), "r"(b0), "r"(b1));
}
__device__ __forceinline__ void cp16(uint32_t s, const void* g, bool p) {
    asm volatile("cp.async.cg.shared.global [%0], [%1], 16, %2;"
                 :: "r"(s), "l"(g), "r"(p ? 16 : 0) : "memory");
}
#define CP_COMMIT() asm volatile("cp.async.commit_group;" ::: "memory")
#define CP_WAIT1()  asm volatile("cp.async.wait_group 1;"  ::: "memory")

__device__ __forceinline__ float softplus_f(float v) {
    return (v > 20.f) ? v : log1pf(expf(v));
}
__device__ __forceinline__ void split_bf16(float v, __nv_bfloat16& h, __nv_bfloat16& l) {
    h = __float2bfloat16(v);
    l = __float2bfloat16(v - __bfloat162float(h));
}

// smem: 3-stage; each stage: Ah(16K) Al(16K) Bh(16K) Bl(16K) = 64KB
#define STAGES 3
#define BUF_BYTES 65536
#define OFF_AH 0
#define OFF_AL 16384
#define OFF_BH 32768
#define OFF_BL 49152
#define SMEM_BYTES (STAGES*BUF_BYTES)

// ======================= mma.sync GEMM (pure bf16, cp.async 3-stage) ========
// C[M,N] = (Ah+Al)[M,K] @ (Bh+Bl)^T, 3-term split. A row-major (lda), B [N,K] (ldb).
// grid: (M/128, ceil(N/128))
// EPI: 0=store fp32, 1=C+=acc, 2=softplus(acc+bias[col]), 3=store fp32 + bf16 split to Ch/Cl
template<int EPI>
__global__ __launch_bounds__(256)
void mmagemm(const __nv_bfloat16* __restrict__ Ah, const __nv_bfloat16* __restrict__ Al,
             const __nv_bfloat16* __restrict__ Bh, const __nv_bfloat16* __restrict__ Bl,
             float* __restrict__ C, const float* __restrict__ bias,
             __nv_bfloat16* __restrict__ Ch, __nv_bfloat16* __restrict__ Cl,
             int N, int K, int lda, int ldb, int ldc)
{
    extern __shared__ __align__(1024) char smem[];
    uint32_t sb = smem_u32(smem);
    const int tid = threadIdx.x;
    const int lane = tid & 31;
    const int wid = tid >> 5;
    const int warp_m = wid >> 1;
    const int warp_n = wid & 1;
    const int bm = blockIdx.x * 128;
    const int bn = blockIdx.y * 128;
    const int nch = K >> 6;

    float acc[2][8][4];
    #pragma unroll
    for (int i = 0; i < 2; i++)
        #pragma unroll
        for (int j = 0; j < 8; j++)
            #pragma unroll
            for (int q = 0; q < 4; q++) acc[i][j][q] = 0.f;

    auto issue = [&](int c, int s) {
        uint32_t st = sb + (uint32_t)s * BUF_BYTES;
        const int k0 = c << 6;
        const __nv_bfloat16* pAh = Ah + (size_t)bm * lda + k0;
        const __nv_bfloat16* pAl = Al + (size_t)bm * lda + k0;
        #pragma unroll
        for (int i = 0; i < 4; i++) {
            int idx = i * 256 + tid;
            int row = idx >> 3, c8 = idx & 7;
            uint32_t so = SWZ((uint32_t)(row * 128 + c8 * 16));
            cp16(st + OFF_AH + so, pAh + (size_t)row * lda + c8 * 8, true);
            cp16(st + OFF_AL + so, pAl + (size_t)row * lda + c8 * 8, true);
        }
        const __nv_bfloat16* pBh = Bh + k0;
        const __nv_bfloat16* pBl = Bl + k0;
        #pragma unroll
        for (int i = 0; i < 4; i++) {
            int idx = i * 256 + tid;
            int row = idx >> 3, c8 = idx & 7;
            bool ok = (bn + row) < N;
            size_t gr = ok ? (size_t)(bn + row) : 0;
            uint32_t so = SWZ((uint32_t)(row * 128 + c8 * 16));
            cp16(st + OFF_BH + so, pBh + gr * ldb + c8 * 8, ok);
            cp16(st + OFF_BL + so, pBl + gr * ldb + c8 * 8, ok);
        }
    };

    // prologue: fill up to STAGES-1 stages; pad empty commits for uniform bookkeeping
    int pre = (nch < STAGES - 1) ? nch : (STAGES - 1);
    for (int s = 0; s < pre; s++) { issue(s, s); CP_COMMIT(); }
    for (int s = pre; s < STAGES - 1; s++) { CP_COMMIT(); }

    // lane-derived fragment address components
    const int arow_l  = warp_m * 32 + (lane & 15);
    const int akoff_l = (lane >> 4) << 4;
    const int brow_l  = warp_n * 64 + (lane & 7) + ((lane >> 4) << 3);
    const int bkoff_l = ((lane >> 3) & 1) << 4;

    for (int c = 0; c < nch; c++) {
        CP_WAIT1();
        __syncthreads();
        uint32_t base = sb + (uint32_t)((c % STAGES) * BUF_BYTES);
        #pragma unroll
        for (int ks = 0; ks < 4; ks++) {
            uint32_t ah[2][4], al[2][4], bh[4][4], bl[4][4];
            const int kb = ks * 32;
            #pragma unroll
            for (int mi = 0; mi < 2; mi++) {
                uint32_t off = SWZ((uint32_t)((arow_l + mi * 16) * 128 + kb + akoff_l));
                ldsm4(base + OFF_AH + off, ah[mi]);
                ldsm4(base + OFF_AL + off, al[mi]);
            }
            #pragma unroll
            for (int nj2 = 0; nj2 < 4; nj2++) {
                uint32_t off = SWZ((uint32_t)((brow_l + nj2 * 16) * 128 + kb + bkoff_l));
                ldsm4(base + OFF_BH + off, bh[nj2]);
                ldsm4(base + OFF_BL + off, bl[nj2]);
            }
            #pragma unroll
            for (int mi = 0; mi < 2; mi++) {
                #pragma unroll
                for (int nj = 0; nj < 8; nj++) {
                    int nj2 = nj >> 1, hi = (nj & 1) * 2;
                    mma_bf16(acc[mi][nj], ah[mi], bh[nj2][hi], bh[nj2][hi + 1]);
                    mma_bf16(acc[mi][nj], ah[mi], bl[nj2][hi], bl[nj2][hi + 1]);
                    mma_bf16(acc[mi][nj], al[mi], bh[nj2][hi], bh[nj2][hi + 1]);
                }
            }
        }
        __syncthreads();
        int cn = c + STAGES - 1;
        if (cn < nch) issue(cn, cn % STAGES);
        CP_COMMIT();
    }

    // ---- epilogue ----
    #pragma unroll
    for (int mi = 0; mi < 2; mi++) {
        #pragma unroll
        for (int nj = 0; nj < 8; nj++) {
            int row = bm + warp_m * 32 + mi * 16 + (lane >> 2);
            int col = bn + warp_n * 64 + nj * 8 + (lane & 3) * 2;
            if (col < N) {
                float* d = acc[mi][nj];
                float2 v0 = make_float2(d[0], d[1]);
                float2 v1 = make_float2(d[2], d[3]);
                float* p0 = C + (size_t)row * ldc + col;
                float* p1 = C + (size_t)(row + 8) * ldc + col;
                if (EPI == 1) {
                    float2 o0 = *(float2*)p0; v0.x += o0.x; v0.y += o0.y;
                    float2 o1 = *(float2*)p1; v1.x += o1.x; v1.y += o1.y;
                } else if (EPI == 2) {
                    float b0 = bias[col], b1 = bias[col + 1];
                    v0.x = softplus_f(v0.x + b0); v0.y = softplus_f(v0.y + b1);
                    v1.x = softplus_f(v1.x + b0); v1.y = softplus_f(v1.y + b1);
                }
                *(float2*)p0 = v0;
                *(float2*)p1 = v1;
                if (EPI == 3) {
                    __nv_bfloat16 h, l;
                    size_t o0 = (size_t)row * ldc + col;
                    size_t o1 = (size_t)(row + 8) * ldc + col;
                    split_bf16(v0.x, h, l); Ch[o0]   = h; Cl[o0]   = l;
                    split_bf16(v0.y, h, l); Ch[o0+1] = h; Cl[o0+1] = l;
                    split_bf16(v1.x, h, l); Ch[o1]   = h; Cl[o1]   = l;
                    split_bf16(v1.y, h, l); Ch[o1+1] = h; Cl[o1+1] = l;
                }
            }
        }
    }
}

// ============== weight prep: fp32 (K,N) -> bf16 hi/lo [N,K] ==============
__global__ void transpose_split(const float* __restrict__ W, int K, int N,
                                __nv_bfloat16* __restrict__ Bh, __nv_bfloat16* __restrict__ Bl)
{
    __shared__ float t[32][33];
    int k0 = blockIdx.x * 32, n0 = blockIdx.y * 32;
    int tx = threadIdx.x, ty = threadIdx.y;   // 32 x 8
    #pragma unroll
    for (int i = 0; i < 4; i++) {
        int k = k0 + ty + 8 * i;
        float v = (n0 + tx < N) ? W[(size_t)k * N + n0 + tx] : 0.f;
        t[ty + 8 * i][tx] = v;
    }
    __syncthreads();
    #pragma unroll
    for (int i = 0; i < 4; i++) {
        int n = n0 + ty + 8 * i;
        int k = k0 + tx;
        float v = t[tx][ty + 8 * i];
        __nv_bfloat16 h, l; split_bf16(v, h, l);
        Bh[(size_t)n * K + k] = h;
        Bl[(size_t)n * K + k] = l;
    }
}

// elementwise split (already [N,K] layout): lm_head
__global__ void split_kernel(const float4* __restrict__ W,
                             __nv_bfloat16* __restrict__ Bh, __nv_bfloat16* __restrict__ Bl, int n4)
{
    int i = blockIdx.x * blockDim.x + threadIdx.x;
    if (i >= n4) return;
    float4 v = W[i];
    __nv_bfloat162 h0 = __floats2bfloat162_rn(v.x, v.y);
    __nv_bfloat162 h1 = __floats2bfloat162_rn(v.z, v.w);
    float lx = v.x - __bfloat162float(h0.x);
    float ly = v.y - __bfloat162float(h0.y);
    float lz = v.z - __bfloat162float(h1.x);
    float lw = v.w - __bfloat162float(h1.y);
    __nv_bfloat162 l0 = __floats2bfloat162_rn(lx, ly);
    __nv_bfloat162 l1 = __floats2bfloat162_rn(lz, lw);
    uint2 hh, llv;
    hh.x = *(uint32_t*)&h0;  hh.y = *(uint32_t*)&h1;
    llv.x = *(uint32_t*)&l0; llv.y = *(uint32_t*)&l1;
    ((uint2*)Bh)[i] = hh;
    ((uint2*)Bl)[i] = llv;
}

// ---------------- embed gather ----------------
__global__ void embed_kernel(const int* __restrict__ tokens,
                             const float* __restrict__ embed)
{
    int t = blockIdx.x;
    int tok = tokens[t];
    const float4* src = (const float4*)(embed + (size_t)tok * DD);
    float4* dst = (float4*)(g_x + (size_t)t * DD);
    for (int i = threadIdx.x; i < DD/4; i += blockDim.x)
        dst[i] = src[i];
}

// ---------------- rmsnorm (writes bf16 hi/lo) ----------------
__global__ void rmsnorm_kernel(const float* __restrict__ x,
                               const float* __restrict__ w,
                               __nv_bfloat16* __restrict__ oh,
                               __nv_bfloat16* __restrict__ ol)
{
    int t = blockIdx.x;
    const float4* xr = (const float4*)(x + (size_t)t * DD);
    const float4* wr = (const float4*)w;

    float s = 0.f;
    for (int i = threadIdx.x; i < DD/4; i += blockDim.x) {
        float4 v = xr[i];
        s += v.x*v.x + v.y*v.y + v.z*v.z + v.w*v.w;
    }
    __shared__ float red[8];
    for (int m = 16; m > 0; m >>= 1) s += __shfl_xor_sync(0xffffffffu, s, m);
    if ((threadIdx.x & 31) == 0) red[threadIdx.x >> 5] = s;
    __syncthreads();
    float tot = 0.f;
    if (threadIdx.x < 8) tot = red[threadIdx.x];
    for (int m = 4; m > 0; m >>= 1) tot += __shfl_xor_sync(0xffffffffu, tot, m);
    __shared__ float inv_s;
    if (threadIdx.x == 0) inv_s = rsqrtf(tot / (float)DD + 1e-5f);
    __syncthreads();
    float inv = inv_s;

    for (int i = threadIdx.x; i < DD/4; i += blockDim.x) {
        float4 v = xr[i];
        float4 wv = wr[i];
        float r0 = v.x * wv.x * inv, r1 = v.y * wv.y * inv;
        float r2 = v.z * wv.z * inv, r3 = v.w * wv.w * inv;
        __nv_bfloat162 h0 = __floats2bfloat162_rn(r0, r1);
        __nv_bfloat162 h1 = __floats2bfloat162_rn(r2, r3);
        __nv_bfloat162 l0 = __floats2bfloat162_rn(r0 - __bfloat162float(h0.x), r1 - __bfloat162float(h0.y));
        __nv_bfloat162 l1 = __floats2bfloat162_rn(r2 - __bfloat162float(h1.x), r3 - __bfloat162float(h1.y));
        uint2 hh, llv;
        hh.x = *(uint32_t*)&h0;  hh.y = *(uint32_t*)&h1;
        llv.x = *(uint32_t*)&l0; llv.y = *(uint32_t*)&l1;
        *(uint2*)(oh + (size_t)t * DD + i * 4) = hh;
        *(uint2*)(ol + (size_t)t * DD + i * 4) = llv;
    }
}

// ---------------- causal conv (K=4) + silu (writes bf16 hi/lo) -------------
__global__ void conv_silu_kernel(const float* __restrict__ conv_w,
                                 const float* __restrict__ conv_b)
{
    int idx = blockIdx.x * blockDim.x + threadIdx.x;
    if (idx >= NTOK * EE) return;
    int e = idx % EE;
    int tk = idx / EE;
    int t = tk % LL;

    const float* src = g_xz + (size_t)(tk - t) * (2*EE) + e;
    float acc = conv_b[e];
    #pragma unroll
    for (int k = 0; k < KK; k++) {
        int tt = t + k - (KK - 1);
        if (tt >= 0)
            acc = fmaf(conv_w[e*KK + k], src[(size_t)tt * (2*EE)], acc);
    }
    float sg = 1.f / (1.f + __expf(-acc));
    float v = acc * sg;
    __nv_bfloat16 h, l; split_bf16(v, h, l);
    g_xch[idx] = h;
    g_xcl[idx] = l;
}

// ---------------- selective scan ----------------
__global__ __launch_bounds__(128)
void scan_kernel(const float* __restrict__ A_log,
                 const float* __restrict__ D_skip)
{
    int group = threadIdx.x >> 4;
    int n     = threadIdx.x & 15;
    int ch    = blockIdx.x * 8 + group;
    int b = ch >> 11;
    int e = ch & (EE - 1);

    float a   = -__expf(A_log[e * NN_ + n]);
    float dsk = D_skip[e];
    float h = 0.f;

    const float* dt_p = g_dt  + (size_t)b*LL*EE + e;
    const __nv_bfloat16* xh_p = g_xch + (size_t)b*LL*EE + e;
    const __nv_bfloat16* xl_p = g_xcl + (size_t)b*LL*EE + e;
    const float* z_p  = g_xz  + (size_t)b*LL*(2*EE) + EE + e;
    const float* bl_p = g_dbl + (size_t)b*LL*96 + 64 + n;
    __nv_bfloat16* yh_p = g_yh + (size_t)b*LL*EE + e;
    __nv_bfloat16* yl_p = g_yl + (size_t)b*LL*EE + e;

    for (int t = 0; t < LL; t++) {
        float dte = __ldg(dt_p);
        float xe  = __bfloat162float(__ldg(xh_p)) + __bfloat162float(__ldg(xl_p));
        float Bn  = __ldg(bl_p);
        float Cn  = __ldg(bl_p + 16);
        float dA  = __expf(dte * a);
        h = fmaf(h, dA, dte * xe * Bn);
        float p = h * Cn;
        p += __shfl_xor_sync(0xffffffffu, p, 8);
        p += __shfl_xor_sync(0xffffffffu, p, 4);
        p += __shfl_xor_sync(0xffffffffu, p, 2);
        p += __shfl_xor_sync(0xffffffffu, p, 1);
        if (n == 0) {
            float z = __ldg(z_p);
            float sig = 1.f / (1.f + __expf(-z));
            float y = (p + xe * dsk) * (z * sig);
            __nv_bfloat16 hh, ll; split_bf16(y, hh, ll);
            *yh_p = hh; *yl_p = ll;
        }
        dt_p += EE; xh_p += EE; xl_p += EE; z_p += 2*EE; bl_p += 96;
        yh_p += EE; yl_p += EE;
    }
}

// ---------------- host launch ----------------
extern "C" void kernel_launch(void* const* d_in, const int* in_sizes, int n_in,
                              void* d_out, int out_size)
{
    const int*   tokens   = (const int*)  d_in[0];
    const float* embed    = (const float*)d_in[1];
    const float* norm_w   = (const float*)d_in[2];
    const float* W_in     = (const float*)d_in[3];
    const float* conv_w   = (const float*)d_in[4];
    const float* conv_b   = (const float*)d_in[5];
    const float* W_xproj  = (const float*)d_in[6];
    const float* W_dt     = (const float*)d_in[7];
    const float* dt_bias  = (const float*)d_in[8];
    const float* A_log    = (const float*)d_in[9];
    const float* D_skip   = (const float*)d_in[10];
    const float* W_out    = (const float*)d_in[11];
    const float* final_nw = (const float*)d_in[12];
    const float* lm_head  = (const float*)d_in[13];
    float* out = (float*)d_out;

    float *px, *pxz, *pdbl, *pdt;
    __nv_bfloat16 *pxnh, *pxnl, *pxch, *pxcl, *pdblh, *pdbll, *pyh, *pyl, *pbh, *pbl;
    cudaGetSymbolAddress((void**)&px,    g_x);
    cudaGetSymbolAddress((void**)&pxnh,  g_xnh);
    cudaGetSymbolAddress((void**)&pxnl,  g_xnl);
    cudaGetSymbolAddress((void**)&pxz,   g_xz);
    cudaGetSymbolAddress((void**)&pxch,  g_xch);
    cudaGetSymbolAddress((void**)&pxcl,  g_xcl);
    cudaGetSymbolAddress((void**)&pdbl,  g_dbl);
    cudaGetSymbolAddress((void**)&pdblh, g_dblh);
    cudaGetSymbolAddress((void**)&pdbll, g_dbll);
    cudaGetSymbolAddress((void**)&pdt,   g_dt);
    cudaGetSymbolAddress((void**)&pyh,   g_yh);
    cudaGetSymbolAddress((void**)&pyl,   g_yl);
    cudaGetSymbolAddress((void**)&pbh,   g_bh);
    cudaGetSymbolAddress((void**)&pbl,   g_bl);

    static bool attr_done = false;
    if (!attr_done) {
        cudaFuncSetAttribute(mmagemm<0>, cudaFuncAttributeMaxDynamicSharedMemorySize, SMEM_BYTES);
        cudaFuncSetAttribute(mmagemm<1>, cudaFuncAttributeMaxDynamicSharedMemorySize, SMEM_BYTES);
        cudaFuncSetAttribute(mmagemm<2>, cudaFuncAttributeMaxDynamicSharedMemorySize, SMEM_BYTES);
        cudaFuncSetAttribute(mmagemm<3>, cudaFuncAttributeMaxDynamicSharedMemorySize, SMEM_BYTES);
        attr_done = true;
    }

    embed_kernel<<<NTOK, 256>>>(tokens, embed);

    for (int l = 0; l < NLAYERS; l++) {
        const float* nw  = norm_w  + (size_t)l * DD;
        const float* win = W_in    + (size_t)l * DD * 2 * EE;
        const float* cw  = conv_w  + (size_t)l * EE * KK;
        const float* cb  = conv_b  + (size_t)l * EE;
        const float* wxp = W_xproj + (size_t)l * EE * 96;
        const float* wdt = W_dt    + (size_t)l * RR * EE;
        const float* dtb = dt_bias + (size_t)l * EE;
        const float* alg = A_log   + (size_t)l * EE * NN_;
        const float* dsk = D_skip  + (size_t)l * EE;
        const float* wo  = W_out   + (size_t)l * EE * DD;

        // 1. rmsnorm -> split xn
        rmsnorm_kernel<<<NTOK, 256>>>(px, nw, pxnh, pxnl);

        // 2. xz = xn @ W_in   (4096 x 4096 x 1024)
        transpose_split<<<dim3(DD/32, (2*EE)/32), dim3(32,8)>>>(win, DD, 2*EE, pbh, pbl);
        mmagemm<0><<<dim3(NTOK/128, (2*EE)/128), 256, SMEM_BYTES>>>(
            pxnh, pxnl, pbh, pbl, pxz, nullptr, nullptr, nullptr,
            2*EE, DD, DD, DD, 2*EE);

        // 3. causal conv + silu -> split xc
        conv_silu_kernel<<<(NTOK*EE + 255)/256, 256>>>(cw, cb);

        // 4. dbl = xc @ W_xproj  (4096 x 96 x 2048), fp32 + split out
        transpose_split<<<dim3(EE/32, 128/32), dim3(32,8)>>>(wxp, EE, 96, pbh, pbl);
        mmagemm<3><<<dim3(NTOK/128, 1), 256, SMEM_BYTES>>>(
            pxch, pxcl, pbh, pbl, pdbl, nullptr, pdblh, pdbll,
            96, EE, EE, EE, 96);

        // 5. dt = softplus(dbl[:, :64] @ W_dt + dt_bias)  (4096 x 2048 x 64)
        transpose_split<<<dim3(RR/32, EE/32), dim3(32,8)>>>(wdt, RR, EE, pbh, pbl);
        mmagemm<2><<<dim3(NTOK/128, EE/128), 256, SMEM_BYTES>>>(
            pdblh, pdbll, pbh, pbl, pdt, dtb, nullptr, nullptr,
            EE, RR, 96, RR, EE);

        // 6. selective scan + gate -> split y
        scan_kernel<<<(BB*EE)/8, 128>>>(alg, dsk);

        // 7. x += y @ W_out  (4096 x 1024 x 2048)
        transpose_split<<<dim3(EE/32, DD/32), dim3(32,8)>>>(wo, EE, DD, pbh, pbl);
        mmagemm<1><<<dim3(NTOK/128, DD/128), 256, SMEM_BYTES>>>(
            pyh, pyl, pbh, pbl, px, nullptr, nullptr, nullptr,
            DD, EE, EE, EE, DD);
    }

    // final rmsnorm -> split xn
    rmsnorm_kernel<<<NTOK, 256>>>(px, final_nw, pxnh, pxnl);

    // logits = xn @ lm_head^T  (4096 x 32000 x 1024); lm_head already [N,K]
    split_kernel<<<(VV*DD/4 + 255)/256, 256>>>((const float4*)lm_head, pbh, pbl, VV*DD/4);
    mmagemm<0><<<dim3(NTOK/128, VV/128), 256, SMEM_BYTES>>>(
        pxnh, pxnl, pbh, pbl, out, nullptr, nullptr, nullptr,
        VV, DD, DD, DD, VV);
}

// round 5
// speedup vs baseline: 3.1699x; 1.6700x over previous
#include <cuda_runtime.h>
#include <cuda_bf16.h>
#include <math.h>
#include <stdint.h>

// Problem dims
#define BB 2
#define LL 2048
#define DD 1024
#define VV 32000
#define NLAYERS 2
#define EE 2048
#define NN_ 16
#define RR 64
#define KK 4
#define NTOK (BB*LL)          // 4096 tokens

// ---------------- scratch (device globals; no allocation allowed) ----------
__device__ float g_x  [NTOK*DD];               // residual fp32
__device__ __nv_bfloat16 g_xnh[NTOK*DD];       // rmsnorm out hi
__device__ __nv_bfloat16 g_xnl[NTOK*DD];       // rmsnorm out lo
__device__ float g_xz [NTOK*2*EE];             // W_in out fp32
__device__ __nv_bfloat16 g_xch[NTOK*EE];       // conv+silu out hi
__device__ __nv_bfloat16 g_xcl[NTOK*EE];       // conv+silu out lo
__device__ float g_dbl [NTOK*96];              // xproj out fp32 (scan reads B,C)
__device__ __nv_bfloat16 g_dblh[NTOK*96];
__device__ __nv_bfloat16 g_dbll[NTOK*96];
__device__ float g_dt [NTOK*EE];               // softplus(dt) fp32
__device__ __nv_bfloat16 g_yh[NTOK*EE];        // scan out hi
__device__ __nv_bfloat16 g_yl[NTOK*EE];        // scan out lo
// bf16 split weight buffers (sized for lm_head: 32000x1024)
__device__ __nv_bfloat16 g_bh[VV*DD];
__device__ __nv_bfloat16 g_bl[VV*DD];

// ======================= helpers ==============================
__device__ __forceinline__ uint32_t smem_u32(const void* p) {
    uint32_t a;
    asm("{ .reg .u64 t; cvta.to.shared.u64 t, %1; cvt.u32.u64 %0, t; }" : "=r"(a) : "l"(p));
    return a;
}
#define SWZ(off) ((off) ^ (((off) >> 3) & 0x70))

__device__ __forceinline__ void ldsm4(uint32_t addr, uint32_t* r) {
    asm volatile("ldmatrix.sync.aligned.m8n8.x4.shared.b16 {%0,%1,%2,%3}, [%4];"
                 : "=r"(r[0]), "=r"(r[1]), "=r"(r[2]), "=r"(r[3]) : "r"(addr));
}
__device__ __forceinline__ void mma_bf16(float* d, const uint32_t* a, uint32_t b0, uint32_t b1) {
    asm volatile(
        "mma.sync.aligned.m16n8k16.row.col.f32.bf16.bf16.f32 "
        "{%0,%1,%2,%3}, {%4,%5,%6,%7}, {%8,%9}, {%0,%1,%2,%3};"
        : "+f"(d[0]), "+f"(d[1]), "+f"(d[2]), "+f"(d[3])
        : "r"(a[0]), "r"(a[1]), "r"(a[2]), "r"(a[3]), "r"(b0), "r"(b1));
}
__device__ __forceinline__ void cp16(uint32_t s, const void* g, bool p) {
    asm volatile("cp.async.cg.shared.global [%0], [%1], 16, %2;"
                 :: "r"(s), "l"(g), "r"(p ? 16 : 0) : "memory");
}
#define CP_COMMIT() asm volatile("cp.async.commit_group;" ::: "memory")
#define CP_WAIT1()  asm volatile("cp.async.wait_group 1;"  ::: "memory")

__device__ __forceinline__ float softplus_f(float v) {
    return (v > 20.f) ? v : log1pf(expf(v));
}
__device__ __forceinline__ void split_bf16(float v, __nv_bfloat16& h, __nv_bfloat16& l) {
    h = __float2bfloat16(v);
    l = __float2bfloat16(v - __bfloat162float(h));
}

// smem: 2 stages; each stage: AH(32K) AL(32K) BH(16K) BL(16K) = 96KB
#define STAGE_BYTES 98304
#define OFF_AH 0
#define OFF_AL 32768
#define OFF_BH 65536
#define OFF_BL 81920
#define SMEM_BYTES (2*STAGE_BYTES)

// ======================= mma.sync GEMM (pure bf16, cp.async 2-stage) ========
// C[M,N] = (Ah+Al)[M,K] @ (Bh+Bl)^T, 3-term split. A row-major (lda), B [N,K] (ldb).
// CTA tile 256x128, 8 warps (4m x 2n), warp tile 64x64. grid: (M/256, ceil(N/128))
// EPI: 0=store fp32, 1=C+=acc, 2=softplus(acc+bias[col]), 3=store fp32 + bf16 split Ch/Cl
template<int EPI>
__global__ __launch_bounds__(256, 1)
void mmagemm(const __nv_bfloat16* __restrict__ Ah, const __nv_bfloat16* __restrict__ Al,
             const __nv_bfloat16* __restrict__ Bh, const __nv_bfloat16* __restrict__ Bl,
             float* __restrict__ C, const float* __restrict__ bias,
             __nv_bfloat16* __restrict__ Ch, __nv_bfloat16* __restrict__ Cl,
             int N, int K, int lda, int ldb, int ldc)
{
    extern __shared__ __align__(1024) char smem[];
    uint32_t sb = smem_u32(smem);
    const int tid = threadIdx.x;
    const int lane = tid & 31;
    const int wid = tid >> 5;
    const int warp_m = wid >> 1;       // 0..3, 64 rows each
    const int warp_n = wid & 1;        // 0..1, 64 cols each
    const int bm = blockIdx.x * 256;
    const int bn = blockIdx.y * 128;
    const int nch = K >> 6;

    float acc[4][8][4];
    #pragma unroll
    for (int i = 0; i < 4; i++)
        #pragma unroll
        for (int j = 0; j < 8; j++)
            #pragma unroll
            for (int q = 0; q < 4; q++) acc[i][j][q] = 0.f;

    auto issue = [&](int c, int s) {
        uint32_t st = sb + (uint32_t)s * STAGE_BYTES;
        const int k0 = c << 6;
        const __nv_bfloat16* pAh = Ah + (size_t)bm * lda + k0;
        const __nv_bfloat16* pAl = Al + (size_t)bm * lda + k0;
        #pragma unroll
        for (int i = 0; i < 8; i++) {           // 256 rows x 8 chunks of 16B
            int idx = i * 256 + tid;
            int row = idx >> 3, c8 = idx & 7;
            uint32_t so = SWZ((uint32_t)(row * 128 + c8 * 16));
            cp16(st + OFF_AH + so, pAh + (size_t)row * lda + c8 * 8, true);
            cp16(st + OFF_AL + so, pAl + (size_t)row * lda + c8 * 8, true);
        }
        const __nv_bfloat16* pBh = Bh + k0;
        const __nv_bfloat16* pBl = Bl + k0;
        #pragma unroll
        for (int i = 0; i < 4; i++) {           // 128 rows x 8 chunks of 16B
            int idx = i * 256 + tid;
            int row = idx >> 3, c8 = idx & 7;
            bool ok = (bn + row) < N;
            size_t gr = ok ? (size_t)(bn + row) : 0;
            uint32_t so = SWZ((uint32_t)(row * 128 + c8 * 16));
            cp16(st + OFF_BH + so, pBh + gr * ldb + c8 * 8, ok);
            cp16(st + OFF_BL + so, pBl + gr * ldb + c8 * 8, ok);
        }
    };

    issue(0, 0);
    CP_COMMIT();

    const int arow_l  = warp_m * 64 + (lane & 15);
    const int akoff_l = (lane >> 4) << 4;
    const int brow_l  = warp_n * 64 + (lane & 7) + ((lane >> 4) << 3);
    const int bkoff_l = ((lane >> 3) & 1) << 4;

    for (int c = 0; c < nch; c++) {
        if (c + 1 < nch) issue(c + 1, (c + 1) & 1);
        CP_COMMIT();
        CP_WAIT1();
        __syncthreads();
        uint32_t base = sb + (uint32_t)((c & 1) * STAGE_BYTES);
        #pragma unroll
        for (int ks = 0; ks < 4; ks++) {
            const int kb = ks * 32;
            uint32_t ah[4][4], al[4][4];
            #pragma unroll
            for (int mi = 0; mi < 4; mi++) {
                uint32_t off = SWZ((uint32_t)((arow_l + mi * 16) * 128 + kb + akoff_l));
                ldsm4(base + OFF_AH + off, ah[mi]);
                ldsm4(base + OFF_AL + off, al[mi]);
            }
            #pragma unroll
            for (int nj2 = 0; nj2 < 4; nj2++) {
                uint32_t bh[4], bl[4];
                uint32_t off = SWZ((uint32_t)((brow_l + nj2 * 16) * 128 + kb + bkoff_l));
                ldsm4(base + OFF_BH + off, bh);
                ldsm4(base + OFF_BL + off, bl);
                #pragma unroll
                for (int mi = 0; mi < 4; mi++) {
                    mma_bf16(acc[mi][nj2*2+0], ah[mi], bh[0], bh[1]);
                    mma_bf16(acc[mi][nj2*2+0], ah[mi], bl[0], bl[1]);
                    mma_bf16(acc[mi][nj2*2+0], al[mi], bh[0], bh[1]);
                    mma_bf16(acc[mi][nj2*2+1], ah[mi], bh[2], bh[3]);
                    mma_bf16(acc[mi][nj2*2+1], ah[mi], bl[2], bl[3]);
                    mma_bf16(acc[mi][nj2*2+1], al[mi], bh[2], bh[3]);
                }
            }
        }
        __syncthreads();
    }

    // ---- epilogue ----
    #pragma unroll
    for (int mi = 0; mi < 4; mi++) {
        #pragma unroll
        for (int nj = 0; nj < 8; nj++) {
            int row = bm + warp_m * 64 + mi * 16 + (lane >> 2);
            int col = bn + warp_n * 64 + nj * 8 + (lane & 3) * 2;
            if (col < N) {
                float* d = acc[mi][nj];
                float2 v0 = make_float2(d[0], d[1]);
                float2 v1 = make_float2(d[2], d[3]);
                float* p0 = C + (size_t)row * ldc + col;
                float* p1 = C + (size_t)(row + 8) * ldc + col;
                if (EPI == 1) {
                    float2 o0 = *(float2*)p0; v0.x += o0.x; v0.y += o0.y;
                    float2 o1 = *(float2*)p1; v1.x += o1.x; v1.y += o1.y;
                } else if (EPI == 2) {
                    float b0 = bias[col], b1 = bias[col + 1];
                    v0.x = softplus_f(v0.x + b0); v0.y = softplus_f(v0.y + b1);
                    v1.x = softplus_f(v1.x + b0); v1.y = softplus_f(v1.y + b1);
                }
                *(float2*)p0 = v0;
                *(float2*)p1 = v1;
                if (EPI == 3) {
                    __nv_bfloat16 h, l;
                    size_t o0 = (size_t)row * ldc + col;
                    size_t o1 = (size_t)(row + 8) * ldc + col;
                    split_bf16(v0.x, h, l); Ch[o0]   = h; Cl[o0]   = l;
                    split_bf16(v0.y, h, l); Ch[o0+1] = h; Cl[o0+1] = l;
                    split_bf16(v1.x, h, l); Ch[o1]   = h; Cl[o1]   = l;
                    split_bf16(v1.y, h, l); Ch[o1+1] = h; Cl[o1+1] = l;
                }
            }
        }
    }
}

// ============== weight prep: fp32 (K,N) -> bf16 hi/lo [N,K] ==============
__global__ void transpose_split(const float* __restrict__ W, int K, int N,
                                __nv_bfloat16* __restrict__ Bh, __nv_bfloat16* __restrict__ Bl)
{
    __shared__ float t[32][33];
    int k0 = blockIdx.x * 32, n0 = blockIdx.y * 32;
    int tx = threadIdx.x, ty = threadIdx.y;   // 32 x 8
    #pragma unroll
    for (int i = 0; i < 4; i++) {
        int k = k0 + ty + 8 * i;
        float v = (n0 + tx < N) ? W[(size_t)k * N + n0 + tx] : 0.f;
        t[ty + 8 * i][tx] = v;
    }
    __syncthreads();
    #pragma unroll
    for (int i = 0; i < 4; i++) {
        int n = n0 + ty + 8 * i;
        int k = k0 + tx;
        float v = t[tx][ty + 8 * i];
        __nv_bfloat16 h, l; split_bf16(v, h, l);
        Bh[(size_t)n * K + k] = h;
        Bl[(size_t)n * K + k] = l;
    }
}

// elementwise split (already [N,K] layout): lm_head
__global__ void split_kernel(const float4* __restrict__ W,
                             __nv_bfloat16* __restrict__ Bh, __nv_bfloat16* __restrict__ Bl, int n4)
{
    int i = blockIdx.x * blockDim.x + threadIdx.x;
    if (i >= n4) return;
    float4 v = W[i];
    __nv_bfloat162 h0 = __floats2bfloat162_rn(v.x, v.y);
    __nv_bfloat162 h1 = __floats2bfloat162_rn(v.z, v.w);
    float lx = v.x - __bfloat162float(h0.x);
    float ly = v.y - __bfloat162float(h0.y);
    float lz = v.z - __bfloat162float(h1.x);
    float lw = v.w - __bfloat162float(h1.y);
    __nv_bfloat162 l0 = __floats2bfloat162_rn(lx, ly);
    __nv_bfloat162 l1 = __floats2bfloat162_rn(lz, lw);
    uint2 hh, llv;
    hh.x = *(uint32_t*)&h0;  hh.y = *(uint32_t*)&h1;
    llv.x = *(uint32_t*)&l0; llv.y = *(uint32_t*)&l1;
    ((uint2*)Bh)[i] = hh;
    ((uint2*)Bl)[i] = llv;
}

// ---------------- embed gather ----------------
__global__ void embed_kernel(const int* __restrict__ tokens,
                             const float* __restrict__ embed)
{
    int t = blockIdx.x;
    int tok = tokens[t];
    const float4* src = (const float4*)(embed + (size_t)tok * DD);
    float4* dst = (float4*)(g_x + (size_t)t * DD);
    for (int i = threadIdx.x; i < DD/4; i += blockDim.x)
        dst[i] = src[i];
}

// ---------------- rmsnorm (writes bf16 hi/lo) ----------------
__global__ void rmsnorm_kernel(const float* __restrict__ x,
                               const float* __restrict__ w,
                               __nv_bfloat16* __restrict__ oh,
                               __nv_bfloat16* __restrict__ ol)
{
    int t = blockIdx.x;
    const float4* xr = (const float4*)(x + (size_t)t * DD);
    const float4* wr = (const float4*)w;

    float s = 0.f;
    for (int i = threadIdx.x; i < DD/4; i += blockDim.x) {
        float4 v = xr[i];
        s += v.x*v.x + v.y*v.y + v.z*v.z + v.w*v.w;
    }
    __shared__ float red[8];
    for (int m = 16; m > 0; m >>= 1) s += __shfl_xor_sync(0xffffffffu, s, m);
    if ((threadIdx.x & 31) == 0) red[threadIdx.x >> 5] = s;
    __syncthreads();
    float tot = 0.f;
    if (threadIdx.x < 8) tot = red[threadIdx.x];
    for (int m = 4; m > 0; m >>= 1) tot += __shfl_xor_sync(0xffffffffu, tot, m);
    __shared__ float inv_s;
    if (threadIdx.x == 0) inv_s = rsqrtf(tot / (float)DD + 1e-5f);
    __syncthreads();
    float inv = inv_s;

    for (int i = threadIdx.x; i < DD/4; i += blockDim.x) {
        float4 v = xr[i];
        float4 wv = wr[i];
        float r0 = v.x * wv.x * inv, r1 = v.y * wv.y * inv;
        float r2 = v.z * wv.z * inv, r3 = v.w * wv.w * inv;
        __nv_bfloat162 h0 = __floats2bfloat162_rn(r0, r1);
        __nv_bfloat162 h1 = __floats2bfloat162_rn(r2, r3);
        __nv_bfloat162 l0 = __floats2bfloat162_rn(r0 - __bfloat162float(h0.x), r1 - __bfloat162float(h0.y));
        __nv_bfloat162 l1 = __floats2bfloat162_rn(r2 - __bfloat162float(h1.x), r3 - __bfloat162float(h1.y));
        uint2 hh, llv;
        hh.x = *(uint32_t*)&h0;  hh.y = *(uint32_t*)&h1;
        llv.x = *(uint32_t*)&l0; llv.y = *(uint32_t*)&l1;
        *(uint2*)(oh + (size_t)t * DD + i * 4) = hh;
        *(uint2*)(ol + (size_t)t * DD + i * 4) = llv;
    }
}

// ---------------- causal conv (K=4) + silu (writes bf16 hi/lo) -------------
__global__ void conv_silu_kernel(const float* __restrict__ conv_w,
                                 const float* __restrict__ conv_b)
{
    int idx = blockIdx.x * blockDim.x + threadIdx.x;
    if (idx >= NTOK * EE) return;
    int e = idx % EE;
    int tk = idx / EE;
    int t = tk % LL;

    const float* src = g_xz + (size_t)(tk - t) * (2*EE) + e;
    float acc = conv_b[e];
    #pragma unroll
    for (int k = 0; k < KK; k++) {
        int tt = t + k - (KK - 1);
        if (tt >= 0)
            acc = fmaf(conv_w[e*KK + k], src[(size_t)tt * (2*EE)], acc);
    }
    float sg = 1.f / (1.f + __expf(-acc));
    float v = acc * sg;
    __nv_bfloat16 h, l; split_bf16(v, h, l);
    g_xch[idx] = h;
    g_xcl[idx] = l;
}

// ---------------- selective scan (register-prefetch ping-pong) -------------
#define SD 8
__global__ __launch_bounds__(128)
void scan_kernel(const float* __restrict__ A_log,
                 const float* __restrict__ D_skip)
{
    int group = threadIdx.x >> 4;
    int n     = threadIdx.x & 15;
    int ch    = blockIdx.x * 8 + group;
    int b = ch >> 11;
    int e = ch & (EE - 1);

    float a   = -__expf(A_log[e * NN_ + n]);
    float dsk = D_skip[e];
    float h = 0.f;

    const float* dt0 = g_dt  + (size_t)b*LL*EE + e;
    const __nv_bfloat16* xh0 = g_xch + (size_t)b*LL*EE + e;
    const __nv_bfloat16* xl0 = g_xcl + (size_t)b*LL*EE + e;
    const float* z0  = g_xz  + (size_t)b*LL*(2*EE) + EE + e;
    const float* bc0 = g_dbl + (size_t)b*LL*96 + 64 + n;
    __nv_bfloat16* yh0 = g_yh + (size_t)b*LL*EE + e;
    __nv_bfloat16* yl0 = g_yl + (size_t)b*LL*EE + e;

    float p_dt[2][SD], p_B[2][SD], p_C[2][SD], p_z[2][SD];
    __nv_bfloat16 p_xh[2][SD], p_xl[2][SD];

#define PREF(BK, TP) do {                                                   \
    _Pragma("unroll")                                                       \
    for (int j = 0; j < SD; j++) {                                          \
        int t = (TP) + j; if (t > LL-1) t = LL-1;                           \
        p_dt[BK][j] = __ldg(dt0 + (size_t)t * EE);                          \
        p_xh[BK][j] = __ldg(xh0 + (size_t)t * EE);                          \
        p_xl[BK][j] = __ldg(xl0 + (size_t)t * EE);                          \
        p_B [BK][j] = __ldg(bc0 + (size_t)t * 96);                          \
        p_C [BK][j] = __ldg(bc0 + (size_t)t * 96 + 16);                     \
        p_z [BK][j] = (n == 0) ? __ldg(z0 + (size_t)t * (2*EE)) : 0.f;      \
    } } while (0)

#define COMP(BK, T0) do {                                                   \
    _Pragma("unroll")                                                       \
    for (int j = 0; j < SD; j++) {                                          \
        float dte = p_dt[BK][j];                                            \
        float xe  = __bfloat162float(p_xh[BK][j])                           \
                  + __bfloat162float(p_xl[BK][j]);                          \
        float dA  = __expf(dte * a);                                        \
        h = fmaf(h, dA, dte * xe * p_B[BK][j]);                             \
        float p = h * p_C[BK][j];                                           \
        p += __shfl_xor_sync(0xffffffffu, p, 8);                            \
        p += __shfl_xor_sync(0xffffffffu, p, 4);                            \
        p += __shfl_xor_sync(0xffffffffu, p, 2);                            \
        p += __shfl_xor_sync(0xffffffffu, p, 1);                            \
        if (n == 0) {                                                       \
            float z = p_z[BK][j];                                           \
            float sig = 1.f / (1.f + __expf(-z));                           \
            float y = (p + xe * dsk) * (z * sig);                           \
            __nv_bfloat16 hh, ll; split_bf16(y, hh, ll);                    \
            yh0[(size_t)((T0)+j) * EE] = hh;                                \
            yl0[(size_t)((T0)+j) * EE] = ll;                                \
        }                                                                   \
    } } while (0)

    PREF(0, 0);
    for (int t0 = 0; t0 < LL; t0 += 2*SD) {
        PREF(1, t0 + SD);
        COMP(0, t0);
        PREF(0, t0 + 2*SD);
        COMP(1, t0 + SD);
    }
#undef PREF
#undef COMP
}

// ---------------- host launch ----------------
extern "C" void kernel_launch(void* const* d_in, const int* in_sizes, int n_in,
                              void* d_out, int out_size)
{
    const int*   tokens   = (const int*)  d_in[0];
    const float* embed    = (const float*)d_in[1];
    const float* norm_w   = (const float*)d_in[2];
    const float* W_in     = (const float*)d_in[3];
    const float* conv_w   = (const float*)d_in[4];
    const float* conv_b   = (const float*)d_in[5];
    const float* W_xproj  = (const float*)d_in[6];
    const float* W_dt     = (const float*)d_in[7];
    const float* dt_bias  = (const float*)d_in[8];
    const float* A_log    = (const float*)d_in[9];
    const float* D_skip   = (const float*)d_in[10];
    const float* W_out    = (const float*)d_in[11];
    const float* final_nw = (const float*)d_in[12];
    const float* lm_head  = (const float*)d_in[13];
    float* out = (float*)d_out;

    float *px, *pxz, *pdbl, *pdt;
    __nv_bfloat16 *pxnh, *pxnl, *pxch, *pxcl, *pdblh, *pdbll, *pyh, *pyl, *pbh, *pbl;
    cudaGetSymbolAddress((void**)&px,    g_x);
    cudaGetSymbolAddress((void**)&pxnh,  g_xnh);
    cudaGetSymbolAddress((void**)&pxnl,  g_xnl);
    cudaGetSymbolAddress((void**)&pxz,   g_xz);
    cudaGetSymbolAddress((void**)&pxch,  g_xch);
    cudaGetSymbolAddress((void**)&pxcl,  g_xcl);
    cudaGetSymbolAddress((void**)&pdbl,  g_dbl);
    cudaGetSymbolAddress((void**)&pdblh, g_dblh);
    cudaGetSymbolAddress((void**)&pdbll, g_dbll);
    cudaGetSymbolAddress((void**)&pdt,   g_dt);
    cudaGetSymbolAddress((void**)&pyh,   g_yh);
    cudaGetSymbolAddress((void**)&pyl,   g_yl);
    cudaGetSymbolAddress((void**)&pbh,   g_bh);
    cudaGetSymbolAddress((void**)&pbl,   g_bl);

    static bool attr_done = false;
    if (!attr_done) {
        cudaFuncSetAttribute(mmagemm<0>, cudaFuncAttributeMaxDynamicSharedMemorySize, SMEM_BYTES);
        cudaFuncSetAttribute(mmagemm<1>, cudaFuncAttributeMaxDynamicSharedMemorySize, SMEM_BYTES);
        cudaFuncSetAttribute(mmagemm<2>, cudaFuncAttributeMaxDynamicSharedMemorySize, SMEM_BYTES);
        cudaFuncSetAttribute(mmagemm<3>, cudaFuncAttributeMaxDynamicSharedMemorySize, SMEM_BYTES);
        attr_done = true;
    }

    embed_kernel<<<NTOK, 256>>>(tokens, embed);

    for (int l = 0; l < NLAYERS; l++) {
        const float* nw  = norm_w  + (size_t)l * DD;
        const float* win = W_in    + (size_t)l * DD * 2 * EE;
        const float* cw  = conv_w  + (size_t)l * EE * KK;
        const float* cb  = conv_b  + (size_t)l * EE;
        const float* wxp = W_xproj + (size_t)l * EE * 96;
        const float* wdt = W_dt    + (size_t)l * RR * EE;
        const float* dtb = dt_bias + (size_t)l * EE;
        const float* alg = A_log   + (size_t)l * EE * NN_;
        const float* dsk = D_skip  + (size_t)l * EE;
        const float* wo  = W_out   + (size_t)l * EE * DD;

        // 1. rmsnorm -> split xn
        rmsnorm_kernel<<<NTOK, 256>>>(px, nw, pxnh, pxnl);

        // 2. xz = xn @ W_in   (4096 x 4096 x 1024)
        transpose_split<<<dim3(DD/32, (2*EE)/32), dim3(32,8)>>>(win, DD, 2*EE, pbh, pbl);
        mmagemm<0><<<dim3(NTOK/256, (2*EE)/128), 256, SMEM_BYTES>>>(
            pxnh, pxnl, pbh, pbl, pxz, nullptr, nullptr, nullptr,
            2*EE, DD, DD, DD, 2*EE);

        // 3. causal conv + silu -> split xc
        conv_silu_kernel<<<(NTOK*EE + 255)/256, 256>>>(cw, cb);

        // 4. dbl = xc @ W_xproj  (4096 x 96 x 2048), fp32 + split out
        transpose_split<<<dim3(EE/32, 128/32), dim3(32,8)>>>(wxp, EE, 96, pbh, pbl);
        mmagemm<3><<<dim3(NTOK/256, 1), 256, SMEM_BYTES>>>(
            pxch, pxcl, pbh, pbl, pdbl, nullptr, pdblh, pdbll,
            96, EE, EE, EE, 96);

        // 5. dt = softplus(dbl[:, :64] @ W_dt + dt_bias)  (4096 x 2048 x 64)
        transpose_split<<<dim3(RR/32, EE/32), dim3(32,8)>>>(wdt, RR, EE, pbh, pbl);
        mmagemm<2><<<dim3(NTOK/256, EE/128), 256, SMEM_BYTES>>>(
            pdblh, pdbll, pbh, pbl, pdt, dtb, nullptr, nullptr,
            EE, RR, 96, RR, EE);

        // 6. selective scan + gate -> split y
        scan_kernel<<<(BB*EE)/8, 128>>>(alg, dsk);

        // 7. x += y @ W_out  (4096 x 1024 x 2048)
        transpose_split<<<dim3(EE/32, DD/32), dim3(32,8)>>>(wo, EE, DD, pbh, pbl);
        mmagemm<1><<<dim3(NTOK/256, DD/128), 256, SMEM_BYTES>>>(
            pyh, pyl, pbh, pbl, px, nullptr, nullptr, nullptr,
            DD, EE, EE, EE, DD);
    }

    // final rmsnorm -> split xn
    rmsnorm_kernel<<<NTOK, 256>>>(px, final_nw, pxnh, pxnl);

    // logits = xn @ lm_head^T  (4096 x 32000 x 1024); lm_head already [N,K]
    split_kernel<<<(VV*DD/4 + 255)/256, 256>>>((const float4*)lm_head, pbh, pbl, VV*DD/4);
    mmagemm<0><<<dim3(NTOK/256, VV/128), 256, SMEM_BYTES>>>(
        pxnh, pxnl, pbh, pbl, out, nullptr, nullptr, nullptr,
        VV, DD, DD, DD, VV);
}

// round 6
// speedup vs baseline: 3.8965x; 1.2292x over previous
#include <cuda_runtime.h>
#include <cuda_bf16.h>
#include <cuda_fp16.h>
#include <math.h>
#include <stdint.h>

// Problem dims
#define BB 2
#define LL 2048
#define DD 1024
#define VV 32000
#define NLAYERS 2
#define EE 2048
#define NN_ 16
#define RR 64
#define KK 4
#define NTOK (BB*LL)          // 4096 tokens

// ---------------- scratch (device globals; no allocation allowed) ----------
__device__ float g_x  [NTOK*DD];               // residual fp32
__device__ __nv_bfloat16 g_xnh[NTOK*DD];       // rmsnorm out hi (bf16) / fp16 for final
__device__ __nv_bfloat16 g_xnl[NTOK*DD];       // rmsnorm out lo
__device__ float g_xz [NTOK*2*EE];             // W_in out fp32
__device__ __nv_bfloat16 g_xch[NTOK*EE];       // conv+silu out hi
__device__ __nv_bfloat16 g_xcl[NTOK*EE];       // conv+silu out lo
__device__ float g_dbl [NTOK*96];              // xproj out fp32 (scan reads B,C)
__device__ __nv_bfloat16 g_dblh[NTOK*96];
__device__ __nv_bfloat16 g_dbll[NTOK*96];
__device__ float g_xpart[4*NTOK*96];           // xproj split-K partials
__device__ float g_dt [NTOK*EE];               // softplus(dt) fp32
__device__ __nv_bfloat16 g_yh[NTOK*EE];        // scan out hi
__device__ __nv_bfloat16 g_yl[NTOK*EE];        // scan out lo
// split weight buffers (sized for lm_head: 32000x1024); bf16 or fp16 via cast
__device__ __nv_bfloat16 g_bh[VV*DD];
__device__ __nv_bfloat16 g_bl[VV*DD];

// ======================= helpers ==============================
__device__ __forceinline__ uint32_t smem_u32(const void* p) {
    uint32_t a;
    asm("{ .reg .u64 t; cvta.to.shared.u64 t, %1; cvt.u32.u64 %0, t; }" : "=r"(a) : "l"(p));
    return a;
}
#define SWZ(off) ((off) ^ (((off) >> 3) & 0x70))

__device__ __forceinline__ void ldsm4(uint32_t addr, uint32_t* r) {
    asm volatile("ldmatrix.sync.aligned.m8n8.x4.shared.b16 {%0,%1,%2,%3}, [%4];"
                 : "=r"(r[0]), "=r"(r[1]), "=r"(r[2]), "=r"(r[3]) : "r"(addr));
}
__device__ __forceinline__ void mma_bf16(float* d, const uint32_t* a, uint32_t b0, uint32_t b1) {
    asm volatile(
        "mma.sync.aligned.m16n8k16.row.col.f32.bf16.bf16.f32 "
        "{%0,%1,%2,%3}, {%4,%5,%6,%7}, {%8,%9}, {%0,%1,%2,%3};"
        : "+f"(d[0]), "+f"(d[1]), "+f"(d[2]), "+f"(d[3])
        : "r"(a[0]), "r"(a[1]), "r"(a[2]), "r"(a[3]), "r"(b0), "r"(b1));
}
__device__ __forceinline__ void mma_f16(float* d, const uint32_t* a, uint32_t b0, uint32_t b1) {
    asm volatile(
        "mma.sync.aligned.m16n8k16.row.col.f32.f16.f16.f32 "
        "{%0,%1,%2,%3}, {%4,%5,%6,%7}, {%8,%9}, {%0,%1,%2,%3};"
        : "+f"(d[0]), "+f"(d[1]), "+f"(d[2]), "+f"(d[3])
        : "r"(a[0]), "r"(a[1]), "r"(a[2]), "r"(a[3]), "r"(b0), "r"(b1));
}
__device__ __forceinline__ void cp16(uint32_t s, const void* g, bool p) {
    asm volatile("cp.async.cg.shared.global [%0], [%1], 16, %2;"
                 :: "r"(s), "l"(g), "r"(p ? 16 : 0) : "memory");
}
#define CP_COMMIT() asm volatile("cp.async.commit_group;" ::: "memory")
#define CP_WAIT1()  asm volatile("cp.async.wait_group 1;"  ::: "memory")

__device__ __forceinline__ float softplus_f(float v) {
    return (v > 20.f) ? v : log1pf(expf(v));
}
__device__ __forceinline__ void split_bf16(float v, __nv_bfloat16& h, __nv_bfloat16& l) {
    h = __float2bfloat16(v);
    l = __float2bfloat16(v - __bfloat162float(h));
}

// smem: 3 stages; each stage: AH(16K) AL(16K) BH(16K) BL(16K) = 64KB
#define STAGE_BYTES 65536
#define OFF_AH 0
#define OFF_AL 16384
#define OFF_BH 32768
#define OFF_BL 49152
#define SMEM_BYTES (3*STAGE_BYTES)

// ======================= mma.sync GEMM (3-stage cp.async) ====================
// bf16 mode (H2=false): C = (Ah+Al)(Bh+Bl)^T 3-term split.
// fp16 mode (H2=true):  C = Ah(Bh+Bl)^T 2-term (A lo unused; operands are fp16).
// A row-major (lda), B [N,K] K-major (ldb). CTA tile 128x128, 8 warps (4m x 2n).
// grid: (M/128, ceil(N/128), ksplit); per-split K depth passed as K;
// A/B advance by blockIdx.z*K columns, C by blockIdx.z*czstride.
// EPI: 0=store fp32, 1=C+=acc, 2=softplus(acc+bias[col])
template<int EPI, bool H2>
__global__ __launch_bounds__(256, 1)
void mmagemm(const __nv_bfloat16* __restrict__ Ah, const __nv_bfloat16* __restrict__ Al,
             const __nv_bfloat16* __restrict__ Bh, const __nv_bfloat16* __restrict__ Bl,
             float* __restrict__ C, const float* __restrict__ bias,
             int N, int K, int lda, int ldb, int ldc, size_t czstride)
{
    extern __shared__ __align__(1024) char smem[];
    uint32_t sb = smem_u32(smem);
    const int tid = threadIdx.x;
    const int lane = tid & 31;
    const int wid = tid >> 5;
    const int warp_m = wid >> 1;       // 0..3, 32 rows
    const int warp_n = wid & 1;        // 0..1, 64 cols
    const int bm = blockIdx.x * 128;
    const int bn = blockIdx.y * 128;
    const int zoff = blockIdx.z * K;   // K-split column offset
    float* Cz = C + (size_t)blockIdx.z * czstride;
    const int nch = K >> 6;

    float acc[2][8][4];
    #pragma unroll
    for (int i = 0; i < 2; i++)
        #pragma unroll
        for (int j = 0; j < 8; j++)
            #pragma unroll
            for (int q = 0; q < 4; q++) acc[i][j][q] = 0.f;

    auto issue = [&](int c, int s) {
        if (c >= nch) return;
        uint32_t st = sb + (uint32_t)s * STAGE_BYTES;
        const int k0 = zoff + (c << 6);
        const __nv_bfloat16* pAh = Ah + (size_t)bm * lda + k0;
        #pragma unroll
        for (int i = 0; i < 4; i++) {           // 128 rows x 8 chunks of 16B
            int idx = i * 256 + tid;
            int row = idx >> 3, c8 = idx & 7;
            uint32_t so = SWZ((uint32_t)(row * 128 + c8 * 16));
            cp16(st + OFF_AH + so, pAh + (size_t)row * lda + c8 * 8, true);
        }
        if (!H2) {
            const __nv_bfloat16* pAl = Al + (size_t)bm * lda + k0;
            #pragma unroll
            for (int i = 0; i < 4; i++) {
                int idx = i * 256 + tid;
                int row = idx >> 3, c8 = idx & 7;
                uint32_t so = SWZ((uint32_t)(row * 128 + c8 * 16));
                cp16(st + OFF_AL + so, pAl + (size_t)row * lda + c8 * 8, true);
            }
        }
        const __nv_bfloat16* pBh = Bh + k0;
        const __nv_bfloat16* pBl = Bl + k0;
        #pragma unroll
        for (int i = 0; i < 4; i++) {
            int idx = i * 256 + tid;
            int row = idx >> 3, c8 = idx & 7;
            bool ok = (bn + row) < N;
            size_t gr = ok ? (size_t)(bn + row) : 0;
            uint32_t so = SWZ((uint32_t)(row * 128 + c8 * 16));
            cp16(st + OFF_BH + so, pBh + gr * ldb + c8 * 8, ok);
            cp16(st + OFF_BL + so, pBl + gr * ldb + c8 * 8, ok);
        }
    };

    issue(0, 0); CP_COMMIT();
    issue(1, 1); CP_COMMIT();

    const int arow_l  = warp_m * 32 + (lane & 15);
    const int akoff_l = (lane >> 4) << 4;
    const int brow_l  = warp_n * 64 + (lane & 7) + ((lane >> 4) << 3);
    const int bkoff_l = ((lane >> 3) & 1) << 4;

    for (int c = 0; c < nch; c++) {
        CP_WAIT1();
        __syncthreads();
        uint32_t base = sb + (uint32_t)((c % 3) * STAGE_BYTES);
        #pragma unroll
        for (int ks = 0; ks < 4; ks++) {
            const int kb = ks * 32;
            uint32_t ah[2][4], al[2][4];
            #pragma unroll
            for (int mi = 0; mi < 2; mi++) {
                uint32_t off = SWZ((uint32_t)((arow_l + mi * 16) * 128 + kb + akoff_l));
                ldsm4(base + OFF_AH + off, ah[mi]);
                if (!H2) ldsm4(base + OFF_AL + off, al[mi]);
            }
            #pragma unroll
            for (int nj2 = 0; nj2 < 4; nj2++) {
                uint32_t bh[4], bl[4];
                uint32_t off = SWZ((uint32_t)((brow_l + nj2 * 16) * 128 + kb + bkoff_l));
                ldsm4(base + OFF_BH + off, bh);
                ldsm4(base + OFF_BL + off, bl);
                #pragma unroll
                for (int mi = 0; mi < 2; mi++) {
                    if (H2) {
                        mma_f16(acc[mi][nj2*2+0], ah[mi], bh[0], bh[1]);
                        mma_f16(acc[mi][nj2*2+0], ah[mi], bl[0], bl[1]);
                        mma_f16(acc[mi][nj2*2+1], ah[mi], bh[2], bh[3]);
                        mma_f16(acc[mi][nj2*2+1], ah[mi], bl[2], bl[3]);
                    } else {
                        mma_bf16(acc[mi][nj2*2+0], ah[mi], bh[0], bh[1]);
                        mma_bf16(acc[mi][nj2*2+0], ah[mi], bl[0], bl[1]);
                        mma_bf16(acc[mi][nj2*2+0], al[mi], bh[0], bh[1]);
                        mma_bf16(acc[mi][nj2*2+1], ah[mi], bh[2], bh[3]);
                        mma_bf16(acc[mi][nj2*2+1], ah[mi], bl[2], bl[3]);
                        mma_bf16(acc[mi][nj2*2+1], al[mi], bh[2], bh[3]);
                    }
                }
            }
        }
        issue(c + 2, (c + 2) % 3);
        CP_COMMIT();
    }

    // ---- epilogue ----
    #pragma unroll
    for (int mi = 0; mi < 2; mi++) {
        #pragma unroll
        for (int nj = 0; nj < 8; nj++) {
            int row = bm + warp_m * 32 + mi * 16 + (lane >> 2);
            int col = bn + warp_n * 64 + nj * 8 + (lane & 3) * 2;
            if (col < N) {
                float* d = acc[mi][nj];
                float2 v0 = make_float2(d[0], d[1]);
                float2 v1 = make_float2(d[2], d[3]);
                float* p0 = Cz + (size_t)row * ldc + col;
                float* p1 = Cz + (size_t)(row + 8) * ldc + col;
                if (EPI == 1) {
                    float2 o0 = *(float2*)p0; v0.x += o0.x; v0.y += o0.y;
                    float2 o1 = *(float2*)p1; v1.x += o1.x; v1.y += o1.y;
                } else if (EPI == 2) {
                    float b0 = bias[col], b1 = bias[col + 1];
                    v0.x = softplus_f(v0.x + b0); v0.y = softplus_f(v0.y + b1);
                    v1.x = softplus_f(v1.x + b0); v1.y = softplus_f(v1.y + b1);
                }
                *(float2*)p0 = v0;
                *(float2*)p1 = v1;
            }
        }
    }
}

// ============== weight prep: fp32 (K,N) -> bf16 hi/lo [N,K] ==============
__global__ void transpose_split(const float* __restrict__ W, int K, int N,
                                __nv_bfloat16* __restrict__ Bh, __nv_bfloat16* __restrict__ Bl)
{
    __shared__ float t[32][33];
    int k0 = blockIdx.x * 32, n0 = blockIdx.y * 32;
    int tx = threadIdx.x, ty = threadIdx.y;   // 32 x 8
    #pragma unroll
    for (int i = 0; i < 4; i++) {
        int k = k0 + ty + 8 * i;
        float v = (n0 + tx < N) ? W[(size_t)k * N + n0 + tx] : 0.f;
        t[ty + 8 * i][tx] = v;
    }
    __syncthreads();
    #pragma unroll
    for (int i = 0; i < 4; i++) {
        int n = n0 + ty + 8 * i;
        int k = k0 + tx;
        float v = t[tx][ty + 8 * i];
        __nv_bfloat16 h, l; split_bf16(v, h, l);
        Bh[(size_t)n * K + k] = h;
        Bl[(size_t)n * K + k] = l;
    }
}

// elementwise fp16 hi/lo split (already [N,K] layout): lm_head
__global__ void split_kernel_f16(const float4* __restrict__ W,
                                 __half* __restrict__ Bh, __half* __restrict__ Bl, int n4)
{
    int i = blockIdx.x * blockDim.x + threadIdx.x;
    if (i >= n4) return;
    float4 v = W[i];
    __half2 h0 = __floats2half2_rn(v.x, v.y);
    __half2 h1 = __floats2half2_rn(v.z, v.w);
    __half2 l0 = __floats2half2_rn(v.x - __low2float(h0), v.y - __high2float(h0));
    __half2 l1 = __floats2half2_rn(v.z - __low2float(h1), v.w - __high2float(h1));
    uint2 hh, llv;
    hh.x = *(uint32_t*)&h0;  hh.y = *(uint32_t*)&h1;
    llv.x = *(uint32_t*)&l0; llv.y = *(uint32_t*)&l1;
    ((uint2*)Bh)[i] = hh;
    ((uint2*)Bl)[i] = llv;
}

// ---------------- xproj split-K reduce + bf16 split ----------------
__global__ void reduce_xproj()
{
    int i = blockIdx.x * blockDim.x + threadIdx.x;
    if (i >= NTOK * 96) return;
    float s = g_xpart[i] + g_xpart[i + NTOK*96] + g_xpart[i + 2*NTOK*96] + g_xpart[i + 3*NTOK*96];
    g_dbl[i] = s;
    __nv_bfloat16 h, l; split_bf16(s, h, l);
    g_dblh[i] = h; g_dbll[i] = l;
}

// ---------------- embed gather ----------------
__global__ void embed_kernel(const int* __restrict__ tokens,
                             const float* __restrict__ embed)
{
    int t = blockIdx.x;
    int tok = tokens[t];
    const float4* src = (const float4*)(embed + (size_t)tok * DD);
    float4* dst = (float4*)(g_x + (size_t)t * DD);
    for (int i = threadIdx.x; i < DD/4; i += blockDim.x)
        dst[i] = src[i];
}

// ---------------- rmsnorm ----------------
// HALF=false: write bf16 hi+lo. HALF=true: write fp16 hi only (ol unused).
template<bool HALF>
__global__ void rmsnorm_kernel(const float* __restrict__ x,
                               const float* __restrict__ w,
                               __nv_bfloat16* __restrict__ oh,
                               __nv_bfloat16* __restrict__ ol)
{
    int t = blockIdx.x;
    const float4* xr = (const float4*)(x + (size_t)t * DD);
    const float4* wr = (const float4*)w;

    float s = 0.f;
    for (int i = threadIdx.x; i < DD/4; i += blockDim.x) {
        float4 v = xr[i];
        s += v.x*v.x + v.y*v.y + v.z*v.z + v.w*v.w;
    }
    __shared__ float red[8];
    for (int m = 16; m > 0; m >>= 1) s += __shfl_xor_sync(0xffffffffu, s, m);
    if ((threadIdx.x & 31) == 0) red[threadIdx.x >> 5] = s;
    __syncthreads();
    float tot = 0.f;
    if (threadIdx.x < 8) tot = red[threadIdx.x];
    for (int m = 4; m > 0; m >>= 1) tot += __shfl_xor_sync(0xffffffffu, tot, m);
    __shared__ float inv_s;
    if (threadIdx.x == 0) inv_s = rsqrtf(tot / (float)DD + 1e-5f);
    __syncthreads();
    float inv = inv_s;

    for (int i = threadIdx.x; i < DD/4; i += blockDim.x) {
        float4 v = xr[i];
        float4 wv = wr[i];
        float r0 = v.x * wv.x * inv, r1 = v.y * wv.y * inv;
        float r2 = v.z * wv.z * inv, r3 = v.w * wv.w * inv;
        if (HALF) {
            __half2 h0 = __floats2half2_rn(r0, r1);
            __half2 h1 = __floats2half2_rn(r2, r3);
            uint2 hh;
            hh.x = *(uint32_t*)&h0; hh.y = *(uint32_t*)&h1;
            *(uint2*)((__half*)oh + (size_t)t * DD + i * 4) = hh;
        } else {
            __nv_bfloat162 h0 = __floats2bfloat162_rn(r0, r1);
            __nv_bfloat162 h1 = __floats2bfloat162_rn(r2, r3);
            __nv_bfloat162 l0 = __floats2bfloat162_rn(r0 - __bfloat162float(h0.x), r1 - __bfloat162float(h0.y));
            __nv_bfloat162 l1 = __floats2bfloat162_rn(r2 - __bfloat162float(h1.x), r3 - __bfloat162float(h1.y));
            uint2 hh, llv;
            hh.x = *(uint32_t*)&h0;  hh.y = *(uint32_t*)&h1;
            llv.x = *(uint32_t*)&l0; llv.y = *(uint32_t*)&l1;
            *(uint2*)(oh + (size_t)t * DD + i * 4) = hh;
            *(uint2*)(ol + (size_t)t * DD + i * 4) = llv;
        }
    }
}

// ---------------- causal conv (K=4) + silu (writes bf16 hi/lo) -------------
__global__ void conv_silu_kernel(const float* __restrict__ conv_w,
                                 const float* __restrict__ conv_b)
{
    int idx = blockIdx.x * blockDim.x + threadIdx.x;
    if (idx >= NTOK * EE) return;
    int e = idx % EE;
    int tk = idx / EE;
    int t = tk % LL;

    const float* src = g_xz + (size_t)(tk - t) * (2*EE) + e;
    float acc = conv_b[e];
    #pragma unroll
    for (int k = 0; k < KK; k++) {
        int tt = t + k - (KK - 1);
        if (tt >= 0)
            acc = fmaf(conv_w[e*KK + k], src[(size_t)tt * (2*EE)], acc);
    }
    float sg = 1.f / (1.f + __expf(-acc));
    float v = acc * sg;
    __nv_bfloat16 h, l; split_bf16(v, h, l);
    g_xch[idx] = h;
    g_xcl[idx] = l;
}

// ---------------- selective scan (register-prefetch ping-pong) -------------
#define SD 8
__global__ __launch_bounds__(128)
void scan_kernel(const float* __restrict__ A_log,
                 const float* __restrict__ D_skip)
{
    int group = threadIdx.x >> 4;
    int n     = threadIdx.x & 15;
    int ch    = blockIdx.x * 8 + group;
    int b = ch >> 11;
    int e = ch & (EE - 1);

    float a   = -__expf(A_log[e * NN_ + n]);
    float dsk = D_skip[e];
    float h = 0.f;

    const float* dt0 = g_dt  + (size_t)b*LL*EE + e;
    const __nv_bfloat16* xh0 = g_xch + (size_t)b*LL*EE + e;
    const __nv_bfloat16* xl0 = g_xcl + (size_t)b*LL*EE + e;
    const float* z0  = g_xz  + (size_t)b*LL*(2*EE) + EE + e;
    const float* bc0 = g_dbl + (size_t)b*LL*96 + 64 + n;
    __nv_bfloat16* yh0 = g_yh + (size_t)b*LL*EE + e;
    __nv_bfloat16* yl0 = g_yl + (size_t)b*LL*EE + e;

    float p_dt[2][SD], p_B[2][SD], p_C[2][SD], p_z[2][SD];
    __nv_bfloat16 p_xh[2][SD], p_xl[2][SD];

#define PREF(BK, TP) do {                                                   \
    _Pragma("unroll")                                                       \
    for (int j = 0; j < SD; j++) {                                          \
        int t = (TP) + j; if (t > LL-1) t = LL-1;                           \
        p_dt[BK][j] = __ldg(dt0 + (size_t)t * EE);                          \
        p_xh[BK][j] = __ldg(xh0 + (size_t)t * EE);                          \
        p_xl[BK][j] = __ldg(xl0 + (size_t)t * EE);                          \
        p_B [BK][j] = __ldg(bc0 + (size_t)t * 96);                          \
        p_C [BK][j] = __ldg(bc0 + (size_t)t * 96 + 16);                     \
        p_z [BK][j] = (n == 0) ? __ldg(z0 + (size_t)t * (2*EE)) : 0.f;      \
    } } while (0)

#define COMP(BK, T0) do {                                                   \
    _Pragma("unroll")                                                       \
    for (int j = 0; j < SD; j++) {                                          \
        float dte = p_dt[BK][j];                                            \
        float xe  = __bfloat162float(p_xh[BK][j])                           \
                  + __bfloat162float(p_xl[BK][j]);                          \
        float dA  = __expf(dte * a);                                        \
        h = fmaf(h, dA, dte * xe * p_B[BK][j]);                             \
        float p = h * p_C[BK][j];                                           \
        p += __shfl_xor_sync(0xffffffffu, p, 8);                            \
        p += __shfl_xor_sync(0xffffffffu, p, 4);                            \
        p += __shfl_xor_sync(0xffffffffu, p, 2);                            \
        p += __shfl_xor_sync(0xffffffffu, p, 1);                            \
        if (n == 0) {                                                       \
            float z = p_z[BK][j];                                           \
            float sig = 1.f / (1.f + __expf(-z));                           \
            float y = (p + xe * dsk) * (z * sig);                           \
            __nv_bfloat16 hh, ll; split_bf16(y, hh, ll);                    \
            yh0[(size_t)((T0)+j) * EE] = hh;                                \
            yl0[(size_t)((T0)+j) * EE] = ll;                                \
        }                                                                   \
    } } while (0)

    PREF(0, 0);
    for (int t0 = 0; t0 < LL; t0 += 2*SD) {
        PREF(1, t0 + SD);
        COMP(0, t0);
        PREF(0, t0 + 2*SD);
        COMP(1, t0 + SD);
    }
#undef PREF
#undef COMP
}

// ---------------- host launch ----------------
extern "C" void kernel_launch(void* const* d_in, const int* in_sizes, int n_in,
                              void* d_out, int out_size)
{
    const int*   tokens   = (const int*)  d_in[0];
    const float* embed    = (const float*)d_in[1];
    const float* norm_w   = (const float*)d_in[2];
    const float* W_in     = (const float*)d_in[3];
    const float* conv_w   = (const float*)d_in[4];
    const float* conv_b   = (const float*)d_in[5];
    const float* W_xproj  = (const float*)d_in[6];
    const float* W_dt     = (const float*)d_in[7];
    const float* dt_bias  = (const float*)d_in[8];
    const float* A_log    = (const float*)d_in[9];
    const float* D_skip   = (const float*)d_in[10];
    const float* W_out    = (const float*)d_in[11];
    const float* final_nw = (const float*)d_in[12];
    const float* lm_head  = (const float*)d_in[13];
    float* out = (float*)d_out;

    float *px, *pxz, *pdt, *pxpart;
    __nv_bfloat16 *pxnh, *pxnl, *pxch, *pxcl, *pdblh, *pdbll, *pyh, *pyl, *pbh, *pbl;
    cudaGetSymbolAddress((void**)&px,    g_x);
    cudaGetSymbolAddress((void**)&pxnh,  g_xnh);
    cudaGetSymbolAddress((void**)&pxnl,  g_xnl);
    cudaGetSymbolAddress((void**)&pxz,   g_xz);
    cudaGetSymbolAddress((void**)&pxch,  g_xch);
    cudaGetSymbolAddress((void**)&pxcl,  g_xcl);
    cudaGetSymbolAddress((void**)&pdblh, g_dblh);
    cudaGetSymbolAddress((void**)&pdbll, g_dbll);
    cudaGetSymbolAddress((void**)&pdt,   g_dt);
    cudaGetSymbolAddress((void**)&pyh,   g_yh);
    cudaGetSymbolAddress((void**)&pyl,   g_yl);
    cudaGetSymbolAddress((void**)&pbh,   g_bh);
    cudaGetSymbolAddress((void**)&pbl,   g_bl);
    cudaGetSymbolAddress((void**)&pxpart, g_xpart);

    static bool attr_done = false;
    if (!attr_done) {
        cudaFuncSetAttribute(mmagemm<0,false>, cudaFuncAttributeMaxDynamicSharedMemorySize, SMEM_BYTES);
        cudaFuncSetAttribute(mmagemm<1,false>, cudaFuncAttributeMaxDynamicSharedMemorySize, SMEM_BYTES);
        cudaFuncSetAttribute(mmagemm<2,false>, cudaFuncAttributeMaxDynamicSharedMemorySize, SMEM_BYTES);
        cudaFuncSetAttribute(mmagemm<0,true>,  cudaFuncAttributeMaxDynamicSharedMemorySize, SMEM_BYTES);
        attr_done = true;
    }

    embed_kernel<<<NTOK, 256>>>(tokens, embed);

    for (int l = 0; l < NLAYERS; l++) {
        const float* nw  = norm_w  + (size_t)l * DD;
        const float* win = W_in    + (size_t)l * DD * 2 * EE;
        const float* cw  = conv_w  + (size_t)l * EE * KK;
        const float* cb  = conv_b  + (size_t)l * EE;
        const float* wxp = W_xproj + (size_t)l * EE * 96;
        const float* wdt = W_dt    + (size_t)l * RR * EE;
        const float* dtb = dt_bias + (size_t)l * EE;
        const float* alg = A_log   + (size_t)l * EE * NN_;
        const float* dsk = D_skip  + (size_t)l * EE;
        const float* wo  = W_out   + (size_t)l * EE * DD;

        // 1. rmsnorm -> split xn (bf16 hi/lo)
        rmsnorm_kernel<false><<<NTOK, 256>>>(px, nw, pxnh, pxnl);

        // 2. xz = xn @ W_in   (4096 x 4096 x 1024)
        transpose_split<<<dim3(DD/32, (2*EE)/32), dim3(32,8)>>>(win, DD, 2*EE, pbh, pbl);
        mmagemm<0,false><<<dim3(NTOK/128, (2*EE)/128), 256, SMEM_BYTES>>>(
            pxnh, pxnl, pbh, pbl, pxz, nullptr,
            2*EE, DD, DD, DD, 2*EE, 0);

        // 3. causal conv + silu -> split xc
        conv_silu_kernel<<<(NTOK*EE + 255)/256, 256>>>(cw, cb);

        // 4. dbl = xc @ W_xproj  (4096 x 96 x 2048), split-K x4 + reduce
        transpose_split<<<dim3(EE/32, 128/32), dim3(32,8)>>>(wxp, EE, 96, pbh, pbl);
        mmagemm<0,false><<<dim3(NTOK/128, 1, 4), 256, SMEM_BYTES>>>(
            pxch, pxcl, pbh, pbl, pxpart, nullptr,
            96, EE/4, EE, EE, 96, (size_t)NTOK*96);
        reduce_xproj<<<(NTOK*96 + 255)/256, 256>>>();

        // 5. dt = softplus(dbl[:, :64] @ W_dt + dt_bias)  (4096 x 2048 x 64)
        transpose_split<<<dim3(RR/32, EE/32), dim3(32,8)>>>(wdt, RR, EE, pbh, pbl);
        mmagemm<2,false><<<dim3(NTOK/128, EE/128), 256, SMEM_BYTES>>>(
            pdblh, pdbll, pbh, pbl, pdt, dtb,
            EE, RR, 96, RR, EE, 0);

        // 6. selective scan + gate -> split y
        scan_kernel<<<(BB*EE)/8, 128>>>(alg, dsk);

        // 7. x += y @ W_out  (4096 x 1024 x 2048)
        transpose_split<<<dim3(EE/32, DD/32), dim3(32,8)>>>(wo, EE, DD, pbh, pbl);
        mmagemm<1,false><<<dim3(NTOK/128, DD/128), 256, SMEM_BYTES>>>(
            pyh, pyl, pbh, pbl, px, nullptr,
            DD, EE, EE, EE, DD, 0);
    }

    // final rmsnorm -> fp16 hi only
    rmsnorm_kernel<true><<<NTOK, 256>>>(px, final_nw, pxnh, nullptr);

    // logits = xn @ lm_head^T  (4096 x 32000 x 1024); fp16 2-term
    split_kernel_f16<<<(VV*DD/4 + 255)/256, 256>>>(
        (const float4*)lm_head, (__half*)pbh, (__half*)pbl, VV*DD/4);
    mmagemm<0,true><<<dim3(NTOK/128, VV/128), 256, SMEM_BYTES>>>(
        pxnh, nullptr, pbh, pbl, out, nullptr,
        VV, DD, DD, DD, VV, 0);
}

// round 7
// speedup vs baseline: 4.6836x; 1.2020x over previous
#include <cuda_runtime.h>
#include <cuda_fp16.h>
#include <math.h>
#include <stdint.h>

// Problem dims
#define BB 2
#define LL 2048
#define DD 1024
#define VV 32000
#define NLAYERS 2
#define EE 2048
#define NN_ 16
#define RR 64
#define KK 4
#define NTOK (BB*LL)          // 4096 tokens

// ---------------- scratch (device globals; no allocation allowed) ----------
__device__ float  g_x  [NTOK*DD];       // residual fp32
__device__ __half g_xn [NTOK*DD];       // rmsnorm out fp16
__device__ float  g_xz [NTOK*2*EE];     // W_in out fp32
__device__ __half g_xc [NTOK*EE];       // conv+silu out fp16
__device__ float  g_dbl [NTOK*96];      // xproj out fp32 (scan reads B,C)
__device__ __half g_dblh[NTOK*96];      // xproj out fp16 (dt GEMM A)
__device__ float  g_xpart[4*NTOK*96];   // xproj split-K partials
__device__ float  g_dt [NTOK*EE];       // softplus(dt) fp32
__device__ __half g_y  [NTOK*EE];       // scan out fp16
// fp16 hi/lo split weight buffers (sized for lm_head: 32000x1024)
__device__ __half g_bh[VV*DD];
__device__ __half g_bl[VV*DD];

// ======================= helpers ==============================
__device__ __forceinline__ uint32_t smem_u32(const void* p) {
    uint32_t a;
    asm("{ .reg .u64 t; cvta.to.shared.u64 t, %1; cvt.u32.u64 %0, t; }" : "=r"(a) : "l"(p));
    return a;
}
#define SWZ(off) ((off) ^ (((off) >> 3) & 0x70))

__device__ __forceinline__ void ldsm4(uint32_t addr, uint32_t* r) {
    asm volatile("ldmatrix.sync.aligned.m8n8.x4.shared.b16 {%0,%1,%2,%3}, [%4];"
                 : "=r"(r[0]), "=r"(r[1]), "=r"(r[2]), "=r"(r[3]) : "r"(addr));
}
__device__ __forceinline__ void mma_f16(float* d, const uint32_t* a, uint32_t b0, uint32_t b1) {
    asm volatile(
        "mma.sync.aligned.m16n8k16.row.col.f32.f16.f16.f32 "
        "{%0,%1,%2,%3}, {%4,%5,%6,%7}, {%8,%9}, {%0,%1,%2,%3};"
        : "+f"(d[0]), "+f"(d[1]), "+f"(d[2]), "+f"(d[3])
        : "r"(a[0]), "r"(a[1]), "r"(a[2]), "r"(a[3]), "r"(b0), "r"(b1));
}
__device__ __forceinline__ void cp16(uint32_t s, const void* g, bool p) {
    asm volatile("cp.async.cg.shared.global [%0], [%1], 16, %2;"
                 :: "r"(s), "l"(g), "r"(p ? 16 : 0) : "memory");
}
#define CP_COMMIT() asm volatile("cp.async.commit_group;" ::: "memory")
#define CP_WAIT1()  asm volatile("cp.async.wait_group 1;"  ::: "memory")

__device__ __forceinline__ float softplus_f(float v) {
    return (v > 20.f) ? v : log1pf(expf(v));
}

// smem: 2 stages; each stage: AH(16K) BH(16K) BL(16K) = 48KB
#define STAGE_BYTES 49152
#define OFF_AH 0
#define OFF_BH 16384
#define OFF_BL 32768
#define SMEM_BYTES (2*STAGE_BYTES)

// ======================= fp16 mma.sync GEMM (2-stage, 2 CTA/SM) =============
// C = Ah @ (Bh+Bl)^T. A fp16 row-major (lda), Bh/Bl fp16 [N,K] K-major (ldb).
// CTA tile 128x128, 8 warps (4m x 2n, warp tile 32x64).
// grid: (M/128, ceil(N/128), ksplit); A/B advance blockIdx.z*K cols,
// C advances blockIdx.z*czstride.
// EPI: 0=store fp32, 1=C+=acc, 2=softplus(acc+bias[col])
template<int EPI>
__global__ __launch_bounds__(256, 2)
void mmagemm(const __half* __restrict__ Ah,
             const __half* __restrict__ Bh, const __half* __restrict__ Bl,
             float* __restrict__ C, const float* __restrict__ bias,
             int N, int K, int lda, int ldb, int ldc, size_t czstride)
{
    extern __shared__ __align__(1024) char smem[];
    uint32_t sb = smem_u32(smem);
    const int tid = threadIdx.x;
    const int lane = tid & 31;
    const int wid = tid >> 5;
    const int warp_m = wid >> 1;       // 0..3, 32 rows
    const int warp_n = wid & 1;        // 0..1, 64 cols
    const int bm = blockIdx.x * 128;
    const int bn = blockIdx.y * 128;
    const int zoff = blockIdx.z * K;
    float* Cz = C + (size_t)blockIdx.z * czstride;
    const int nch = K >> 6;

    float acc[2][8][4];
    #pragma unroll
    for (int i = 0; i < 2; i++)
        #pragma unroll
        for (int j = 0; j < 8; j++)
            #pragma unroll
            for (int q = 0; q < 4; q++) acc[i][j][q] = 0.f;

    auto issue = [&](int c, int s) {
        if (c >= nch) return;
        uint32_t st = sb + (uint32_t)s * STAGE_BYTES;
        const int k0 = zoff + (c << 6);
        const __half* pAh = Ah + (size_t)bm * lda + k0;
        #pragma unroll
        for (int i = 0; i < 4; i++) {           // 128 rows x 8 chunks of 16B
            int idx = i * 256 + tid;
            int row = idx >> 3, c8 = idx & 7;
            uint32_t so = SWZ((uint32_t)(row * 128 + c8 * 16));
            cp16(st + OFF_AH + so, pAh + (size_t)row * lda + c8 * 8, true);
        }
        const __half* pBh = Bh + k0;
        const __half* pBl = Bl + k0;
        #pragma unroll
        for (int i = 0; i < 4; i++) {
            int idx = i * 256 + tid;
            int row = idx >> 3, c8 = idx & 7;
            bool ok = (bn + row) < N;
            size_t gr = ok ? (size_t)(bn + row) : 0;
            uint32_t so = SWZ((uint32_t)(row * 128 + c8 * 16));
            cp16(st + OFF_BH + so, pBh + gr * ldb + c8 * 8, ok);
            cp16(st + OFF_BL + so, pBl + gr * ldb + c8 * 8, ok);
        }
    };

    issue(0, 0); CP_COMMIT();
    issue(1, 1); CP_COMMIT();

    const int arow_l  = warp_m * 32 + (lane & 15);
    const int akoff_l = (lane >> 4) << 4;
    const int brow_l  = warp_n * 64 + (lane & 7) + ((lane >> 4) << 3);
    const int bkoff_l = ((lane >> 3) & 1) << 4;

    for (int c = 0; c < nch; c++) {
        CP_WAIT1();
        __syncthreads();
        uint32_t base = sb + (uint32_t)((c & 1) * STAGE_BYTES);
        #pragma unroll
        for (int ks = 0; ks < 4; ks++) {
            const int kb = ks * 32;
            uint32_t ah[2][4];
            #pragma unroll
            for (int mi = 0; mi < 2; mi++) {
                uint32_t off = SWZ((uint32_t)((arow_l + mi * 16) * 128 + kb + akoff_l));
                ldsm4(base + OFF_AH + off, ah[mi]);
            }
            #pragma unroll
            for (int nj2 = 0; nj2 < 4; nj2++) {
                uint32_t bh[4], bl[4];
                uint32_t off = SWZ((uint32_t)((brow_l + nj2 * 16) * 128 + kb + bkoff_l));
                ldsm4(base + OFF_BH + off, bh);
                ldsm4(base + OFF_BL + off, bl);
                #pragma unroll
                for (int mi = 0; mi < 2; mi++) {
                    mma_f16(acc[mi][nj2*2+0], ah[mi], bh[0], bh[1]);
                    mma_f16(acc[mi][nj2*2+0], ah[mi], bl[0], bl[1]);
                    mma_f16(acc[mi][nj2*2+1], ah[mi], bh[2], bh[3]);
                    mma_f16(acc[mi][nj2*2+1], ah[mi], bl[2], bl[3]);
                }
            }
        }
        __syncthreads();                 // all warps done reading stage c&1
        issue(c + 2, (c + 2) & 1);       // safe to overwrite it now
        CP_COMMIT();
    }

    // ---- epilogue ----
    #pragma unroll
    for (int mi = 0; mi < 2; mi++) {
        #pragma unroll
        for (int nj = 0; nj < 8; nj++) {
            int row = bm + warp_m * 32 + mi * 16 + (lane >> 2);
            int col = bn + warp_n * 64 + nj * 8 + (lane & 3) * 2;
            if (col < N) {
                float* d = acc[mi][nj];
                float2 v0 = make_float2(d[0], d[1]);
                float2 v1 = make_float2(d[2], d[3]);
                float* p0 = Cz + (size_t)row * ldc + col;
                float* p1 = Cz + (size_t)(row + 8) * ldc + col;
                if (EPI == 1) {
                    float2 o0 = *(float2*)p0; v0.x += o0.x; v0.y += o0.y;
                    float2 o1 = *(float2*)p1; v1.x += o1.x; v1.y += o1.y;
                } else if (EPI == 2) {
                    float b0 = bias[col], b1 = bias[col + 1];
                    v0.x = softplus_f(v0.x + b0); v0.y = softplus_f(v0.y + b1);
                    v1.x = softplus_f(v1.x + b0); v1.y = softplus_f(v1.y + b1);
                }
                *(float2*)p0 = v0;
                *(float2*)p1 = v1;
            }
        }
    }
}

// ============== weight prep: fp32 (K,N) -> fp16 hi/lo [N,K] ==============
__global__ void transpose_split_f16(const float* __restrict__ W, int K, int N,
                                    __half* __restrict__ Bh, __half* __restrict__ Bl)
{
    __shared__ float t[32][33];
    int k0 = blockIdx.x * 32, n0 = blockIdx.y * 32;
    int tx = threadIdx.x, ty = threadIdx.y;   // 32 x 8
    #pragma unroll
    for (int i = 0; i < 4; i++) {
        int k = k0 + ty + 8 * i;
        float v = (n0 + tx < N) ? W[(size_t)k * N + n0 + tx] : 0.f;
        t[ty + 8 * i][tx] = v;
    }
    __syncthreads();
    #pragma unroll
    for (int i = 0; i < 4; i++) {
        int n = n0 + ty + 8 * i;
        int k = k0 + tx;
        float v = t[tx][ty + 8 * i];
        __half h = __float2half_rn(v);
        __half l = __float2half_rn(v - __half2float(h));
        Bh[(size_t)n * K + k] = h;
        Bl[(size_t)n * K + k] = l;
    }
}

// elementwise fp16 hi/lo split (already [N,K] layout): lm_head
__global__ void split_kernel_f16(const float4* __restrict__ W,
                                 __half* __restrict__ Bh, __half* __restrict__ Bl, int n4)
{
    int i = blockIdx.x * blockDim.x + threadIdx.x;
    if (i >= n4) return;
    float4 v = W[i];
    __half2 h0 = __floats2half2_rn(v.x, v.y);
    __half2 h1 = __floats2half2_rn(v.z, v.w);
    __half2 l0 = __floats2half2_rn(v.x - __low2float(h0), v.y - __high2float(h0));
    __half2 l1 = __floats2half2_rn(v.z - __low2float(h1), v.w - __high2float(h1));
    uint2 hh, llv;
    hh.x = *(uint32_t*)&h0;  hh.y = *(uint32_t*)&h1;
    llv.x = *(uint32_t*)&l0; llv.y = *(uint32_t*)&l1;
    ((uint2*)Bh)[i] = hh;
    ((uint2*)Bl)[i] = llv;
}

// ---------------- xproj split-K reduce: fp32 + fp16 ----------------
__global__ void reduce_xproj()
{
    int i = blockIdx.x * blockDim.x + threadIdx.x;
    if (i >= NTOK * 96) return;
    float s = g_xpart[i] + g_xpart[i + NTOK*96] + g_xpart[i + 2*NTOK*96] + g_xpart[i + 3*NTOK*96];
    g_dbl[i] = s;
    g_dblh[i] = __float2half_rn(s);
}

// ---------------- embed gather ----------------
__global__ void embed_kernel(const int* __restrict__ tokens,
                             const float* __restrict__ embed)
{
    int t = blockIdx.x;
    int tok = tokens[t];
    const float4* src = (const float4*)(embed + (size_t)tok * DD);
    float4* dst = (float4*)(g_x + (size_t)t * DD);
    for (int i = threadIdx.x; i < DD/4; i += blockDim.x)
        dst[i] = src[i];
}

// ---------------- rmsnorm (writes fp16) ----------------
__global__ void rmsnorm_kernel(const float* __restrict__ x,
                               const float* __restrict__ w,
                               __half* __restrict__ o)
{
    int t = blockIdx.x;
    const float4* xr = (const float4*)(x + (size_t)t * DD);
    const float4* wr = (const float4*)w;

    float s = 0.f;
    for (int i = threadIdx.x; i < DD/4; i += blockDim.x) {
        float4 v = xr[i];
        s += v.x*v.x + v.y*v.y + v.z*v.z + v.w*v.w;
    }
    __shared__ float red[8];
    for (int m = 16; m > 0; m >>= 1) s += __shfl_xor_sync(0xffffffffu, s, m);
    if ((threadIdx.x & 31) == 0) red[threadIdx.x >> 5] = s;
    __syncthreads();
    float tot = 0.f;
    if (threadIdx.x < 8) tot = red[threadIdx.x];
    for (int m = 4; m > 0; m >>= 1) tot += __shfl_xor_sync(0xffffffffu, tot, m);
    __shared__ float inv_s;
    if (threadIdx.x == 0) inv_s = rsqrtf(tot / (float)DD + 1e-5f);
    __syncthreads();
    float inv = inv_s;

    for (int i = threadIdx.x; i < DD/4; i += blockDim.x) {
        float4 v = xr[i];
        float4 wv = wr[i];
        __half2 h0 = __floats2half2_rn(v.x * wv.x * inv, v.y * wv.y * inv);
        __half2 h1 = __floats2half2_rn(v.z * wv.z * inv, v.w * wv.w * inv);
        uint2 hh;
        hh.x = *(uint32_t*)&h0; hh.y = *(uint32_t*)&h1;
        *(uint2*)(o + (size_t)t * DD + i * 4) = hh;
    }
}

// ---------------- causal conv (K=4) + silu (writes fp16) -------------
__global__ void conv_silu_kernel(const float* __restrict__ conv_w,
                                 const float* __restrict__ conv_b)
{
    int idx = blockIdx.x * blockDim.x + threadIdx.x;
    if (idx >= NTOK * EE) return;
    int e = idx % EE;
    int tk = idx / EE;
    int t = tk % LL;

    const float* src = g_xz + (size_t)(tk - t) * (2*EE) + e;
    float acc = conv_b[e];
    #pragma unroll
    for (int k = 0; k < KK; k++) {
        int tt = t + k - (KK - 1);
        if (tt >= 0)
            acc = fmaf(conv_w[e*KK + k], src[(size_t)tt * (2*EE)], acc);
    }
    float sg = 1.f / (1.f + __expf(-acc));
    g_xc[idx] = __float2half_rn(acc * sg);
}

// ---------------- selective scan (register-prefetch ping-pong) -------------
#define SD 8
__global__ __launch_bounds__(128)
void scan_kernel(const float* __restrict__ A_log,
                 const float* __restrict__ D_skip)
{
    int group = threadIdx.x >> 4;
    int n     = threadIdx.x & 15;
    int ch    = blockIdx.x * 8 + group;
    int b = ch >> 11;
    int e = ch & (EE - 1);

    float a   = -__expf(A_log[e * NN_ + n]);
    float dsk = D_skip[e];
    float h = 0.f;

    const float* dt0 = g_dt  + (size_t)b*LL*EE + e;
    const __half* x0 = g_xc  + (size_t)b*LL*EE + e;
    const float* z0  = g_xz  + (size_t)b*LL*(2*EE) + EE + e;
    const float* bc0 = g_dbl + (size_t)b*LL*96 + 64 + n;
    __half* y0 = g_y + (size_t)b*LL*EE + e;

    float p_dt[2][SD], p_B[2][SD], p_C[2][SD], p_z[2][SD];
    __half p_x[2][SD];

#define PREF(BK, TP) do {                                                   \
    _Pragma("unroll")                                                       \
    for (int j = 0; j < SD; j++) {                                          \
        int t = (TP) + j; if (t > LL-1) t = LL-1;                           \
        p_dt[BK][j] = __ldg(dt0 + (size_t)t * EE);                          \
        p_x [BK][j] = __ldg(x0  + (size_t)t * EE);                          \
        p_B [BK][j] = __ldg(bc0 + (size_t)t * 96);                          \
        p_C [BK][j] = __ldg(bc0 + (size_t)t * 96 + 16);                     \
        p_z [BK][j] = (n == 0) ? __ldg(z0 + (size_t)t * (2*EE)) : 0.f;      \
    } } while (0)

#define COMP(BK, T0) do {                                                   \
    _Pragma("unroll")                                                       \
    for (int j = 0; j < SD; j++) {                                          \
        float dte = p_dt[BK][j];                                            \
        float xe  = __half2float(p_x[BK][j]);                               \
        float dA  = __expf(dte * a);                                        \
        h = fmaf(h, dA, dte * xe * p_B[BK][j]);                             \
        float p = h * p_C[BK][j];                                           \
        p += __shfl_xor_sync(0xffffffffu, p, 8);                            \
        p += __shfl_xor_sync(0xffffffffu, p, 4);                            \
        p += __shfl_xor_sync(0xffffffffu, p, 2);                            \
        p += __shfl_xor_sync(0xffffffffu, p, 1);                            \
        if (n == 0) {                                                       \
            float z = p_z[BK][j];                                           \
            float sig = 1.f / (1.f + __expf(-z));                           \
            float y = (p + xe * dsk) * (z * sig);                           \
            y0[(size_t)((T0)+j) * EE] = __float2half_rn(y);                 \
        }                                                                   \
    } } while (0)

    PREF(0, 0);
    for (int t0 = 0; t0 < LL; t0 += 2*SD) {
        PREF(1, t0 + SD);
        COMP(0, t0);
        PREF(0, t0 + 2*SD);
        COMP(1, t0 + SD);
    }
#undef PREF
#undef COMP
}

// ---------------- host launch ----------------
extern "C" void kernel_launch(void* const* d_in, const int* in_sizes, int n_in,
                              void* d_out, int out_size)
{
    const int*   tokens   = (const int*)  d_in[0];
    const float* embed    = (const float*)d_in[1];
    const float* norm_w   = (const float*)d_in[2];
    const float* W_in     = (const float*)d_in[3];
    const float* conv_w   = (const float*)d_in[4];
    const float* conv_b   = (const float*)d_in[5];
    const float* W_xproj  = (const float*)d_in[6];
    const float* W_dt     = (const float*)d_in[7];
    const float* dt_bias  = (const float*)d_in[8];
    const float* A_log    = (const float*)d_in[9];
    const float* D_skip   = (const float*)d_in[10];
    const float* W_out    = (const float*)d_in[11];
    const float* final_nw = (const float*)d_in[12];
    const float* lm_head  = (const float*)d_in[13];
    float* out = (float*)d_out;

    float *px, *pxz, *pdt, *pxpart, *pdbl;
    __half *pxn, *pxc, *pdblh, *py, *pbh, *pbl;
    cudaGetSymbolAddress((void**)&px,    g_x);
    cudaGetSymbolAddress((void**)&pxn,   g_xn);
    cudaGetSymbolAddress((void**)&pxz,   g_xz);
    cudaGetSymbolAddress((void**)&pxc,   g_xc);
    cudaGetSymbolAddress((void**)&pdbl,  g_dbl);
    cudaGetSymbolAddress((void**)&pdblh, g_dblh);
    cudaGetSymbolAddress((void**)&pdt,   g_dt);
    cudaGetSymbolAddress((void**)&py,    g_y);
    cudaGetSymbolAddress((void**)&pbh,   g_bh);
    cudaGetSymbolAddress((void**)&pbl,   g_bl);
    cudaGetSymbolAddress((void**)&pxpart, g_xpart);

    static bool attr_done = false;
    if (!attr_done) {
        cudaFuncSetAttribute(mmagemm<0>, cudaFuncAttributeMaxDynamicSharedMemorySize, SMEM_BYTES);
        cudaFuncSetAttribute(mmagemm<1>, cudaFuncAttributeMaxDynamicSharedMemorySize, SMEM_BYTES);
        cudaFuncSetAttribute(mmagemm<2>, cudaFuncAttributeMaxDynamicSharedMemorySize, SMEM_BYTES);
        attr_done = true;
    }

    embed_kernel<<<NTOK, 256>>>(tokens, embed);

    for (int l = 0; l < NLAYERS; l++) {
        const float* nw  = norm_w  + (size_t)l * DD;
        const float* win = W_in    + (size_t)l * DD * 2 * EE;
        const float* cw  = conv_w  + (size_t)l * EE * KK;
        const float* cb  = conv_b  + (size_t)l * EE;
        const float* wxp = W_xproj + (size_t)l * EE * 96;
        const float* wdt = W_dt    + (size_t)l * RR * EE;
        const float* dtb = dt_bias + (size_t)l * EE;
        const float* alg = A_log   + (size_t)l * EE * NN_;
        const float* dsk = D_skip  + (size_t)l * EE;
        const float* wo  = W_out   + (size_t)l * EE * DD;

        // 1. rmsnorm -> fp16 xn
        rmsnorm_kernel<<<NTOK, 256>>>(px, nw, pxn);

        // 2. xz = xn @ W_in   (4096 x 4096 x 1024)
        transpose_split_f16<<<dim3(DD/32, (2*EE)/32), dim3(32,8)>>>(win, DD, 2*EE, pbh, pbl);
        mmagemm<0><<<dim3(NTOK/128, (2*EE)/128), 256, SMEM_BYTES>>>(
            pxn, pbh, pbl, pxz, nullptr,
            2*EE, DD, DD, DD, 2*EE, 0);

        // 3. causal conv + silu -> fp16 xc
        conv_silu_kernel<<<(NTOK*EE + 255)/256, 256>>>(cw, cb);

        // 4. dbl = xc @ W_xproj  (4096 x 96 x 2048), split-K x4 + reduce
        transpose_split_f16<<<dim3(EE/32, 128/32), dim3(32,8)>>>(wxp, EE, 96, pbh, pbl);
        mmagemm<0><<<dim3(NTOK/128, 1, 4), 256, SMEM_BYTES>>>(
            pxc, pbh, pbl, pxpart, nullptr,
            96, EE/4, EE, EE, 96, (size_t)NTOK*96);
        reduce_xproj<<<(NTOK*96 + 255)/256, 256>>>();

        // 5. dt = softplus(dbl[:, :64] @ W_dt + dt_bias)  (4096 x 2048 x 64)
        transpose_split_f16<<<dim3(RR/32, EE/32), dim3(32,8)>>>(wdt, RR, EE, pbh, pbl);
        mmagemm<2><<<dim3(NTOK/128, EE/128), 256, SMEM_BYTES>>>(
            pdblh, pbh, pbl, pdt, dtb,
            EE, RR, 96, RR, EE, 0);

        // 6. selective scan + gate -> fp16 y
        scan_kernel<<<(BB*EE)/8, 128>>>(alg, dsk);

        // 7. x += y @ W_out  (4096 x 1024 x 2048)
        transpose_split_f16<<<dim3(EE/32, DD/32), dim3(32,8)>>>(wo, EE, DD, pbh, pbl);
        mmagemm<1><<<dim3(NTOK/128, DD/128), 256, SMEM_BYTES>>>(
            py, pbh, pbl, px, nullptr,
            DD, EE, EE, EE, DD, 0);
    }

    // final rmsnorm -> fp16 xn
    rmsnorm_kernel<<<NTOK, 256>>>(px, final_nw, pxn);

    // logits = xn @ lm_head^T  (4096 x 32000 x 1024); lm_head already [N,K]
    split_kernel_f16<<<(VV*DD/4 + 255)/256, 256>>>(
        (const float4*)lm_head, pbh, pbl, VV*DD/4);
    mmagemm<0><<<dim3(NTOK/128, VV/128), 256, SMEM_BYTES>>>(
        pxn, pbh, pbl, out, nullptr,
        VV, DD, DD, DD, VV, 0);
}

// round 8
// speedup vs baseline: 4.8488x; 1.0353x over previous
#include <cuda_runtime.h>
#include <cuda_fp16.h>
#include <math.h>
#include <stdint.h>

// Problem dims
#define BB 2
#define LL 2048
#define DD 1024
#define VV 32000
#define NLAYERS 2
#define EE 2048
#define NN_ 16
#define RR 64
#define KK 4
#define NTOK (BB*LL)          // 4096 tokens

// ---------------- scratch (device globals; no allocation allowed) ----------
__device__ float  g_x  [NTOK*DD];       // residual fp32
__device__ __half g_xn [NTOK*DD];       // rmsnorm out fp16
__device__ float  g_xz [NTOK*2*EE];     // W_in out fp32
__device__ __half g_xc [NTOK*EE];       // conv+silu out fp16
__device__ float  g_dbl [NTOK*96];      // xproj out fp32 (scan reads B,C)
__device__ __half g_dblh[NTOK*96];      // xproj out fp16 (dt GEMM A)
__device__ float  g_xpart[4*NTOK*96];   // xproj split-K partials
__device__ float  g_dt [NTOK*EE];       // softplus(dt) fp32
__device__ __half g_y  [NTOK*EE];       // scan out fp16
// fp16 hi/lo split weight buffers (sized for lm_head: 32000x1024)
__device__ __half g_bh[VV*DD];
__device__ __half g_bl[VV*DD];

// ======================= helpers ==============================
__device__ __forceinline__ uint32_t smem_u32(const void* p) {
    uint32_t a;
    asm("{ .reg .u64 t; cvta.to.shared.u64 t, %1; cvt.u32.u64 %0, t; }" : "=r"(a) : "l"(p));
    return a;
}
// SW64 swizzle for 64-byte rows (Swizzle<2,4,3>)
#define SWZ64(off) ((off) ^ (((off) >> 3) & 0x30))

__device__ __forceinline__ void ldsm4(uint32_t addr, uint32_t* r) {
    asm volatile("ldmatrix.sync.aligned.m8n8.x4.shared.b16 {%0,%1,%2,%3}, [%4];"
                 : "=r"(r[0]), "=r"(r[1]), "=r"(r[2]), "=r"(r[3]) : "r"(addr));
}
__device__ __forceinline__ void mma_f16(float* d, const uint32_t* a, uint32_t b0, uint32_t b1) {
    asm volatile(
        "mma.sync.aligned.m16n8k16.row.col.f32.f16.f16.f32 "
        "{%0,%1,%2,%3}, {%4,%5,%6,%7}, {%8,%9}, {%0,%1,%2,%3};"
        : "+f"(d[0]), "+f"(d[1]), "+f"(d[2]), "+f"(d[3])
        : "r"(a[0]), "r"(a[1]), "r"(a[2]), "r"(a[3]), "r"(b0), "r"(b1));
}
__device__ __forceinline__ void cp16(uint32_t s, const void* g, bool p) {
    asm volatile("cp.async.cg.shared.global [%0], [%1], 16, %2;"
                 :: "r"(s), "l"(g), "r"(p ? 16 : 0) : "memory");
}
#define CP_COMMIT() asm volatile("cp.async.commit_group;" ::: "memory")
#define CP_WAIT2()  asm volatile("cp.async.wait_group 2;"  ::: "memory")

__device__ __forceinline__ float softplus_f(float v) {
    return (v > 20.f) ? v : log1pf(expf(v));
}

// smem: 4 stages; each stage (K-chunk 32): AH(8K) BH(8K) BL(8K) = 24KB
#define STAGE_BYTES 24576
#define OFF_AH 0
#define OFF_BH 8192
#define OFF_BL 16384
#define SMEM_BYTES (4*STAGE_BYTES)

// ======================= fp16 mma.sync GEMM (4-stage ring, 1 sync/chunk) ====
// C = Ah @ (Bh+Bl)^T. A fp16 row-major (lda), Bh/Bl fp16 [N,K] K-major (ldb).
// CTA tile 128x128, 8 warps (4m x 2n, warp tile 32x64). K-chunk = 32.
// grid: (M/128, ceil(N/128), ksplit); A/B advance blockIdx.z*K cols,
// C advances blockIdx.z*czstride.
// EPI: 0=store fp32, 1=C+=acc, 2=softplus(acc+bias[col])
template<int EPI>
__global__ __launch_bounds__(256, 2)
void mmagemm(const __half* __restrict__ Ah,
             const __half* __restrict__ Bh, const __half* __restrict__ Bl,
             float* __restrict__ C, const float* __restrict__ bias,
             int N, int K, int lda, int ldb, int ldc, size_t czstride)
{
    extern __shared__ __align__(1024) char smem[];
    uint32_t sb = smem_u32(smem);
    const int tid = threadIdx.x;
    const int lane = tid & 31;
    const int wid = tid >> 5;
    const int warp_m = wid >> 1;       // 0..3, 32 rows
    const int warp_n = wid & 1;        // 0..1, 64 cols
    const int bm = blockIdx.x * 128;
    const int bn = blockIdx.y * 128;
    const int zoff = blockIdx.z * K;
    float* Cz = C + (size_t)blockIdx.z * czstride;
    const int nch = K >> 5;            // 32-wide K chunks

    float acc[2][8][4];
    #pragma unroll
    for (int i = 0; i < 2; i++)
        #pragma unroll
        for (int j = 0; j < 8; j++)
            #pragma unroll
            for (int q = 0; q < 4; q++) acc[i][j][q] = 0.f;

    auto issue = [&](int c, int s) {
        if (c >= nch) return;
        uint32_t st = sb + (uint32_t)s * STAGE_BYTES;
        const int k0 = zoff + (c << 5);
        const __half* pAh = Ah + (size_t)bm * lda + k0;
        #pragma unroll
        for (int i = 0; i < 2; i++) {           // 128 rows x 4 chunks of 16B
            int idx = i * 256 + tid;
            int row = idx >> 2, c4 = idx & 3;
            uint32_t so = SWZ64((uint32_t)(row * 64 + c4 * 16));
            cp16(st + OFF_AH + so, pAh + (size_t)row * lda + c4 * 8, true);
        }
        const __half* pBh = Bh + k0;
        const __half* pBl = Bl + k0;
        #pragma unroll
        for (int i = 0; i < 2; i++) {
            int idx = i * 256 + tid;
            int row = idx >> 2, c4 = idx & 3;
            bool ok = (bn + row) < N;
            size_t gr = ok ? (size_t)(bn + row) : 0;
            uint32_t so = SWZ64((uint32_t)(row * 64 + c4 * 16));
            cp16(st + OFF_BH + so, pBh + gr * ldb + c4 * 8, ok);
            cp16(st + OFF_BL + so, pBl + gr * ldb + c4 * 8, ok);
        }
    };

    issue(0, 0); CP_COMMIT();
    issue(1, 1); CP_COMMIT();
    issue(2, 2); CP_COMMIT();

    const int arow_l  = warp_m * 32 + (lane & 15);
    const int akoff_l = (lane >> 4) << 4;
    const int brow_l  = warp_n * 64 + (lane & 7) + ((lane >> 4) << 3);
    const int bkoff_l = ((lane >> 3) & 1) << 4;

    for (int c = 0; c < nch; c++) {
        CP_WAIT2();
        __syncthreads();      // all warps done with chunk c-1; chunk c resident
        uint32_t base = sb + (uint32_t)((c & 3) * STAGE_BYTES);
        #pragma unroll
        for (int ks = 0; ks < 2; ks++) {
            const int kb = ks * 32;           // byte offset of k16 slice
            uint32_t ah[2][4];
            #pragma unroll
            for (int mi = 0; mi < 2; mi++) {
                uint32_t off = SWZ64((uint32_t)((arow_l + mi * 16) * 64 + kb + akoff_l));
                ldsm4(base + OFF_AH + off, ah[mi]);
            }
            #pragma unroll
            for (int nj2 = 0; nj2 < 4; nj2++) {
                uint32_t bh[4], bl[4];
                uint32_t off = SWZ64((uint32_t)((brow_l + nj2 * 16) * 64 + kb + bkoff_l));
                ldsm4(base + OFF_BH + off, bh);
                ldsm4(base + OFF_BL + off, bl);
                #pragma unroll
                for (int mi = 0; mi < 2; mi++) {
                    mma_f16(acc[mi][nj2*2+0], ah[mi], bh[0], bh[1]);
                    mma_f16(acc[mi][nj2*2+0], ah[mi], bl[0], bl[1]);
                    mma_f16(acc[mi][nj2*2+1], ah[mi], bh[2], bh[3]);
                    mma_f16(acc[mi][nj2*2+1], ah[mi], bl[2], bl[3]);
                }
            }
        }
        // writes slot (c+3)&3 == (c-1)&3 — finished by all warps before the
        // sync at the top of this iteration, so no second barrier needed.
        issue(c + 3, (c + 3) & 3);
        CP_COMMIT();
    }

    // ---- epilogue ----
    #pragma unroll
    for (int mi = 0; mi < 2; mi++) {
        #pragma unroll
        for (int nj = 0; nj < 8; nj++) {
            int row = bm + warp_m * 32 + mi * 16 + (lane >> 2);
            int col = bn + warp_n * 64 + nj * 8 + (lane & 3) * 2;
            if (col < N) {
                float* d = acc[mi][nj];
                float2 v0 = make_float2(d[0], d[1]);
                float2 v1 = make_float2(d[2], d[3]);
                float* p0 = Cz + (size_t)row * ldc + col;
                float* p1 = Cz + (size_t)(row + 8) * ldc + col;
                if (EPI == 1) {
                    float2 o0 = *(float2*)p0; v0.x += o0.x; v0.y += o0.y;
                    float2 o1 = *(float2*)p1; v1.x += o1.x; v1.y += o1.y;
                } else if (EPI == 2) {
                    float b0 = bias[col], b1 = bias[col + 1];
                    v0.x = softplus_f(v0.x + b0); v0.y = softplus_f(v0.y + b1);
                    v1.x = softplus_f(v1.x + b0); v1.y = softplus_f(v1.y + b1);
                }
                *(float2*)p0 = v0;
                *(float2*)p1 = v1;
            }
        }
    }
}

// ============== weight prep: fp32 (K,N) -> fp16 hi/lo [N,K] ==============
__global__ void transpose_split_f16(const float* __restrict__ W, int K, int N,
                                    __half* __restrict__ Bh, __half* __restrict__ Bl)
{
    __shared__ float t[32][33];
    int k0 = blockIdx.x * 32, n0 = blockIdx.y * 32;
    int tx = threadIdx.x, ty = threadIdx.y;   // 32 x 8
    #pragma unroll
    for (int i = 0; i < 4; i++) {
        int k = k0 + ty + 8 * i;
        float v = (n0 + tx < N) ? W[(size_t)k * N + n0 + tx] : 0.f;
        t[ty + 8 * i][tx] = v;
    }
    __syncthreads();
    #pragma unroll
    for (int i = 0; i < 4; i++) {
        int n = n0 + ty + 8 * i;
        int k = k0 + tx;
        float v = t[tx][ty + 8 * i];
        __half h = __float2half_rn(v);
        __half l = __float2half_rn(v - __half2float(h));
        Bh[(size_t)n * K + k] = h;
        Bl[(size_t)n * K + k] = l;
    }
}

// elementwise fp16 hi/lo split (already [N,K] layout): lm_head
__global__ void split_kernel_f16(const float4* __restrict__ W,
                                 __half* __restrict__ Bh, __half* __restrict__ Bl, int n4)
{
    int i = blockIdx.x * blockDim.x + threadIdx.x;
    if (i >= n4) return;
    float4 v = W[i];
    __half2 h0 = __floats2half2_rn(v.x, v.y);
    __half2 h1 = __floats2half2_rn(v.z, v.w);
    __half2 l0 = __floats2half2_rn(v.x - __low2float(h0), v.y - __high2float(h0));
    __half2 l1 = __floats2half2_rn(v.z - __low2float(h1), v.w - __high2float(h1));
    uint2 hh, llv;
    hh.x = *(uint32_t*)&h0;  hh.y = *(uint32_t*)&h1;
    llv.x = *(uint32_t*)&l0; llv.y = *(uint32_t*)&l1;
    ((uint2*)Bh)[i] = hh;
    ((uint2*)Bl)[i] = llv;
}

// ---------------- xproj split-K reduce: fp32 + fp16 ----------------
__global__ void reduce_xproj()
{
    int i = blockIdx.x * blockDim.x + threadIdx.x;
    if (i >= NTOK * 96) return;
    float s = g_xpart[i] + g_xpart[i + NTOK*96] + g_xpart[i + 2*NTOK*96] + g_xpart[i + 3*NTOK*96];
    g_dbl[i] = s;
    g_dblh[i] = __float2half_rn(s);
}

// ---------------- embed gather ----------------
__global__ void embed_kernel(const int* __restrict__ tokens,
                             const float* __restrict__ embed)
{
    int t = blockIdx.x;
    int tok = tokens[t];
    const float4* src = (const float4*)(embed + (size_t)tok * DD);
    float4* dst = (float4*)(g_x + (size_t)t * DD);
    for (int i = threadIdx.x; i < DD/4; i += blockDim.x)
        dst[i] = src[i];
}

// ---------------- rmsnorm (writes fp16) ----------------
__global__ void rmsnorm_kernel(const float* __restrict__ x,
                               const float* __restrict__ w,
                               __half* __restrict__ o)
{
    int t = blockIdx.x;
    const float4* xr = (const float4*)(x + (size_t)t * DD);
    const float4* wr = (const float4*)w;

    float s = 0.f;
    for (int i = threadIdx.x; i < DD/4; i += blockDim.x) {
        float4 v = xr[i];
        s += v.x*v.x + v.y*v.y + v.z*v.z + v.w*v.w;
    }
    __shared__ float red[8];
    for (int m = 16; m > 0; m >>= 1) s += __shfl_xor_sync(0xffffffffu, s, m);
    if ((threadIdx.x & 31) == 0) red[threadIdx.x >> 5] = s;
    __syncthreads();
    float tot = 0.f;
    if (threadIdx.x < 8) tot = red[threadIdx.x];
    for (int m = 4; m > 0; m >>= 1) tot += __shfl_xor_sync(0xffffffffu, tot, m);
    __shared__ float inv_s;
    if (threadIdx.x == 0) inv_s = rsqrtf(tot / (float)DD + 1e-5f);
    __syncthreads();
    float inv = inv_s;

    for (int i = threadIdx.x; i < DD/4; i += blockDim.x) {
        float4 v = xr[i];
        float4 wv = wr[i];
        __half2 h0 = __floats2half2_rn(v.x * wv.x * inv, v.y * wv.y * inv);
        __half2 h1 = __floats2half2_rn(v.z * wv.z * inv, v.w * wv.w * inv);
        uint2 hh;
        hh.x = *(uint32_t*)&h0; hh.y = *(uint32_t*)&h1;
        *(uint2*)(o + (size_t)t * DD + i * 4) = hh;
    }
}

// ---------------- causal conv (K=4) + silu (writes fp16) -------------
__global__ void conv_silu_kernel(const float* __restrict__ conv_w,
                                 const float* __restrict__ conv_b)
{
    int idx = blockIdx.x * blockDim.x + threadIdx.x;
    if (idx >= NTOK * EE) return;
    int e = idx % EE;
    int tk = idx / EE;
    int t = tk % LL;

    const float* src = g_xz + (size_t)(tk - t) * (2*EE) + e;
    float acc = conv_b[e];
    #pragma unroll
    for (int k = 0; k < KK; k++) {
        int tt = t + k - (KK - 1);
        if (tt >= 0)
            acc = fmaf(conv_w[e*KK + k], src[(size_t)tt * (2*EE)], acc);
    }
    float sg = 1.f / (1.f + __expf(-acc));
    g_xc[idx] = __float2half_rn(acc * sg);
}

// ---------------- selective scan (register-prefetch ping-pong) -------------
#define SD 8
__global__ __launch_bounds__(128)
void scan_kernel(const float* __restrict__ A_log,
                 const float* __restrict__ D_skip)
{
    int group = threadIdx.x >> 4;
    int n     = threadIdx.x & 15;
    int ch    = blockIdx.x * 8 + group;
    int b = ch >> 11;
    int e = ch & (EE - 1);

    float a   = -__expf(A_log[e * NN_ + n]);
    float dsk = D_skip[e];
    float h = 0.f;

    const float* dt0 = g_dt  + (size_t)b*LL*EE + e;
    const __half* x0 = g_xc  + (size_t)b*LL*EE + e;
    const float* z0  = g_xz  + (size_t)b*LL*(2*EE) + EE + e;
    const float* bc0 = g_dbl + (size_t)b*LL*96 + 64 + n;
    __half* y0 = g_y + (size_t)b*LL*EE + e;

    float p_dt[2][SD], p_B[2][SD], p_C[2][SD], p_z[2][SD];
    __half p_x[2][SD];

#define PREF(BK, TP) do {                                                   \
    _Pragma("unroll")                                                       \
    for (int j = 0; j < SD; j++) {                                          \
        int t = (TP) + j; if (t > LL-1) t = LL-1;                           \
        p_dt[BK][j] = __ldg(dt0 + (size_t)t * EE);                          \
        p_x [BK][j] = __ldg(x0  + (size_t)t * EE);                          \
        p_B [BK][j] = __ldg(bc0 + (size_t)t * 96);                          \
        p_C [BK][j] = __ldg(bc0 + (size_t)t * 96 + 16);                     \
        p_z [BK][j] = (n == 0) ? __ldg(z0 + (size_t)t * (2*EE)) : 0.f;      \
    } } while (0)

#define COMP(BK, T0) do {                                                   \
    _Pragma("unroll")                                                       \
    for (int j = 0; j < SD; j++) {                                          \
        float dte = p_dt[BK][j];                                            \
        float xe  = __half2float(p_x[BK][j]);                               \
        float dA  = __expf(dte * a);                                        \
        h = fmaf(h, dA, dte * xe * p_B[BK][j]);                             \
        float p = h * p_C[BK][j];                                           \
        p += __shfl_xor_sync(0xffffffffu, p, 8);                            \
        p += __shfl_xor_sync(0xffffffffu, p, 4);                            \
        p += __shfl_xor_sync(0xffffffffu, p, 2);                            \
        p += __shfl_xor_sync(0xffffffffu, p, 1);                            \
        if (n == 0) {                                                       \
            float z = p_z[BK][j];                                           \
            float sig = 1.f / (1.f + __expf(-z));                           \
            float y = (p + xe * dsk) * (z * sig);                           \
            y0[(size_t)((T0)+j) * EE] = __float2half_rn(y);                 \
        }                                                                   \
    } } while (0)

    PREF(0, 0);
    for (int t0 = 0; t0 < LL; t0 += 2*SD) {
        PREF(1, t0 + SD);
        COMP(0, t0);
        PREF(0, t0 + 2*SD);
        COMP(1, t0 + SD);
    }
#undef PREF
#undef COMP
}

// ---------------- host launch ----------------
extern "C" void kernel_launch(void* const* d_in, const int* in_sizes, int n_in,
                              void* d_out, int out_size)
{
    const int*   tokens   = (const int*)  d_in[0];
    const float* embed    = (const float*)d_in[1];
    const float* norm_w   = (const float*)d_in[2];
    const float* W_in     = (const float*)d_in[3];
    const float* conv_w   = (const float*)d_in[4];
    const float* conv_b   = (const float*)d_in[5];
    const float* W_xproj  = (const float*)d_in[6];
    const float* W_dt     = (const float*)d_in[7];
    const float* dt_bias  = (const float*)d_in[8];
    const float* A_log    = (const float*)d_in[9];
    const float* D_skip   = (const float*)d_in[10];
    const float* W_out    = (const float*)d_in[11];
    const float* final_nw = (const float*)d_in[12];
    const float* lm_head  = (const float*)d_in[13];
    float* out = (float*)d_out;

    float *px, *pxz, *pdt, *pxpart, *pdbl;
    __half *pxn, *pxc, *pdblh, *py, *pbh, *pbl;
    cudaGetSymbolAddress((void**)&px,    g_x);
    cudaGetSymbolAddress((void**)&pxn,   g_xn);
    cudaGetSymbolAddress((void**)&pxz,   g_xz);
    cudaGetSymbolAddress((void**)&pxc,   g_xc);
    cudaGetSymbolAddress((void**)&pdbl,  g_dbl);
    cudaGetSymbolAddress((void**)&pdblh, g_dblh);
    cudaGetSymbolAddress((void**)&pdt,   g_dt);
    cudaGetSymbolAddress((void**)&py,    g_y);
    cudaGetSymbolAddress((void**)&pbh,   g_bh);
    cudaGetSymbolAddress((void**)&pbl,   g_bl);
    cudaGetSymbolAddress((void**)&pxpart, g_xpart);

    static bool attr_done = false;
    if (!attr_done) {
        cudaFuncSetAttribute(mmagemm<0>, cudaFuncAttributeMaxDynamicSharedMemorySize, SMEM_BYTES);
        cudaFuncSetAttribute(mmagemm<1>, cudaFuncAttributeMaxDynamicSharedMemorySize, SMEM_BYTES);
        cudaFuncSetAttribute(mmagemm<2>, cudaFuncAttributeMaxDynamicSharedMemorySize, SMEM_BYTES);
        attr_done = true;
    }

    embed_kernel<<<NTOK, 256>>>(tokens, embed);

    for (int l = 0; l < NLAYERS; l++) {
        const float* nw  = norm_w  + (size_t)l * DD;
        const float* win = W_in    + (size_t)l * DD * 2 * EE;
        const float* cw  = conv_w  + (size_t)l * EE * KK;
        const float* cb  = conv_b  + (size_t)l * EE;
        const float* wxp = W_xproj + (size_t)l * EE * 96;
        const float* wdt = W_dt    + (size_t)l * RR * EE;
        const float* dtb = dt_bias + (size_t)l * EE;
        const float* alg = A_log   + (size_t)l * EE * NN_;
        const float* dsk = D_skip  + (size_t)l * EE;
        const float* wo  = W_out   + (size_t)l * EE * DD;

        // 1. rmsnorm -> fp16 xn
        rmsnorm_kernel<<<NTOK, 256>>>(px, nw, pxn);

        // 2. xz = xn @ W_in   (4096 x 4096 x 1024)
        transpose_split_f16<<<dim3(DD/32, (2*EE)/32), dim3(32,8)>>>(win, DD, 2*EE, pbh, pbl);
        mmagemm<0><<<dim3(NTOK/128, (2*EE)/128), 256, SMEM_BYTES>>>(
            pxn, pbh, pbl, pxz, nullptr,
            2*EE, DD, DD, DD, 2*EE, 0);

        // 3. causal conv + silu -> fp16 xc
        conv_silu_kernel<<<(NTOK*EE + 255)/256, 256>>>(cw, cb);

        // 4. dbl = xc @ W_xproj  (4096 x 96 x 2048), split-K x4 + reduce
        transpose_split_f16<<<dim3(EE/32, 128/32), dim3(32,8)>>>(wxp, EE, 96, pbh, pbl);
        mmagemm<0><<<dim3(NTOK/128, 1, 4), 256, SMEM_BYTES>>>(
            pxc, pbh, pbl, pxpart, nullptr,
            96, EE/4, EE, EE, 96, (size_t)NTOK*96);
        reduce_xproj<<<(NTOK*96 + 255)/256, 256>>>();

        // 5. dt = softplus(dbl[:, :64] @ W_dt + dt_bias)  (4096 x 2048 x 64)
        transpose_split_f16<<<dim3(RR/32, EE/32), dim3(32,8)>>>(wdt, RR, EE, pbh, pbl);
        mmagemm<2><<<dim3(NTOK/128, EE/128), 256, SMEM_BYTES>>>(
            pdblh, pbh, pbl, pdt, dtb,
            EE, RR, 96, RR, EE, 0);

        // 6. selective scan + gate -> fp16 y
        scan_kernel<<<(BB*EE)/8, 128>>>(alg, dsk);

        // 7. x += y @ W_out  (4096 x 1024 x 2048)
        transpose_split_f16<<<dim3(EE/32, DD/32), dim3(32,8)>>>(wo, EE, DD, pbh, pbl);
        mmagemm<1><<<dim3(NTOK/128, DD/128), 256, SMEM_BYTES>>>(
            py, pbh, pbl, px, nullptr,
            DD, EE, EE, EE, DD, 0);
    }

    // final rmsnorm -> fp16 xn
    rmsnorm_kernel<<<NTOK, 256>>>(px, final_nw, pxn);

    // logits = xn @ lm_head^T  (4096 x 32000 x 1024); lm_head already [N,K]
    split_kernel_f16<<<(VV*DD/4 + 255)/256, 256>>>(
        (const float4*)lm_head, pbh, pbl, VV*DD/4);
    mmagemm<0><<<dim3(NTOK/128, VV/128), 256, SMEM_BYTES>>>(
        pxn, pbh, pbl, out, nullptr,
        VV, DD, DD, DD, VV, 0);
}

// round 9
// speedup vs baseline: 5.2056x; 1.0736x over previous
#include <cuda_runtime.h>
#include <cuda_fp16.h>
#include <math.h>
#include <stdint.h>

// Problem dims
#define BB 2
#define LL 2048
#define DD 1024
#define VV 32000
#define NLAYERS 2
#define EE 2048
#define NN_ 16
#define RR 64
#define KK 4
#define NTOK (BB*LL)          // 4096 tokens

// ---------------- scratch (device globals; no allocation allowed) ----------
__device__ float  g_x   [NTOK*DD];      // residual fp32
__device__ __half g_xn  [NTOK*DD];      // rmsnorm out fp16
__device__ float  g_xz  [NTOK*2*EE];    // W_in out fp32
__device__ __half g_xc  [NTOK*EE];      // conv+silu out fp16 [t][e]
__device__ __half g_xcT [EE*NTOK];      // conv+silu out fp16 [e][t]
__device__ __half g_gT  [EE*NTOK];      // silu(z) fp16 [e][t]
__device__ __half g_dblh[NTOK*96];      // xproj out hi fp16 (dt GEMM B)
__device__ __half g_dbll[NTOK*96];      // xproj out lo fp16
__device__ float  g_bcT [32*NTOK];      // B (rows 0..15), C (rows 16..31) [n][tk]
__device__ float  g_xpart[4*NTOK*96];   // xproj split-K partials
__device__ float  g_dtT [EE*NTOK];      // softplus(dt) fp32 [e][tk]
__device__ __half g_y   [NTOK*EE];      // scan out fp16 [t][e]
// fp16 hi/lo split weight buffers (sized for lm_head: 32000x1024)
__device__ __half g_bh[VV*DD];
__device__ __half g_bl[VV*DD];

// ======================= helpers ==============================
__device__ __forceinline__ uint32_t smem_u32(const void* p) {
    uint32_t a;
    asm("{ .reg .u64 t; cvta.to.shared.u64 t, %1; cvt.u32.u64 %0, t; }" : "=r"(a) : "l"(p));
    return a;
}
// SW64 swizzle for 64-byte rows (Swizzle<2,4,3>)
#define SWZ64(off) ((off) ^ (((off) >> 3) & 0x30))

__device__ __forceinline__ void ldsm4(uint32_t addr, uint32_t* r) {
    asm volatile("ldmatrix.sync.aligned.m8n8.x4.shared.b16 {%0,%1,%2,%3}, [%4];"
                 : "=r"(r[0]), "=r"(r[1]), "=r"(r[2]), "=r"(r[3]) : "r"(addr));
}
__device__ __forceinline__ void mma_f16(float* d, const uint32_t* a, uint32_t b0, uint32_t b1) {
    asm volatile(
        "mma.sync.aligned.m16n8k16.row.col.f32.f16.f16.f32 "
        "{%0,%1,%2,%3}, {%4,%5,%6,%7}, {%8,%9}, {%0,%1,%2,%3};"
        : "+f"(d[0]), "+f"(d[1]), "+f"(d[2]), "+f"(d[3])
        : "r"(a[0]), "r"(a[1]), "r"(a[2]), "r"(a[3]), "r"(b0), "r"(b1));
}
__device__ __forceinline__ void cp16(uint32_t s, const void* g, bool p) {
    asm volatile("cp.async.cg.shared.global [%0], [%1], 16, %2;"
                 :: "r"(s), "l"(g), "r"(p ? 16 : 0) : "memory");
}
#define CP_COMMIT() asm volatile("cp.async.commit_group;" ::: "memory")
#define CP_WAIT2()  asm volatile("cp.async.wait_group 2;"  ::: "memory")

__device__ __forceinline__ float softplus_f(float v) {
    return (v > 20.f) ? v : log1pf(expf(v));
}
__device__ __forceinline__ float h2f_lo(uint32_t w) {
    return __half2float(__ushort_as_half((unsigned short)(w & 0xFFFFu)));
}
__device__ __forceinline__ float h2f_hi(uint32_t w) {
    return __half2float(__ushort_as_half((unsigned short)(w >> 16)));
}

// smem: 4 stages; each stage (K-chunk 32): AH(8K) BH(8K) BL(8K) = 24KB
#define STAGE_BYTES 24576
#define OFF_AH 0
#define OFF_BH 8192
#define OFF_BL 16384
#define SMEM_BYTES (4*STAGE_BYTES)

// ======================= fp16 mma.sync GEMM (4-stage ring, 1 sync/chunk) ====
// C = Ah @ (Bh+Bl)^T. A fp16 row-major (lda), Bh/Bl fp16 [N,K] K-major (ldb).
// CTA tile 128x128, 8 warps (4m x 2n, warp tile 32x64). K-chunk = 32.
// grid: (M/128, ceil(N/128), ksplit)
// EPI: 0=store fp32, 1=C+=acc, 3=softplus(acc+bias[row])
template<int EPI>
__global__ __launch_bounds__(256, 2)
void mmagemm(const __half* __restrict__ Ah,
             const __half* __restrict__ Bh, const __half* __restrict__ Bl,
             float* __restrict__ C, const float* __restrict__ bias,
             int N, int K, int lda, int ldb, int ldc, size_t czstride)
{
    extern __shared__ __align__(1024) char smem[];
    uint32_t sb = smem_u32(smem);
    const int tid = threadIdx.x;
    const int lane = tid & 31;
    const int wid = tid >> 5;
    const int warp_m = wid >> 1;
    const int warp_n = wid & 1;
    const int bm = blockIdx.x * 128;
    const int bn = blockIdx.y * 128;
    const int zoff = blockIdx.z * K;
    float* Cz = C + (size_t)blockIdx.z * czstride;
    const int nch = K >> 5;

    float acc[2][8][4];
    #pragma unroll
    for (int i = 0; i < 2; i++)
        #pragma unroll
        for (int j = 0; j < 8; j++)
            #pragma unroll
            for (int q = 0; q < 4; q++) acc[i][j][q] = 0.f;

    auto issue = [&](int c, int s) {
        if (c >= nch) return;
        uint32_t st = sb + (uint32_t)s * STAGE_BYTES;
        const int k0 = zoff + (c << 5);
        const __half* pAh = Ah + (size_t)bm * lda + k0;
        #pragma unroll
        for (int i = 0; i < 2; i++) {
            int idx = i * 256 + tid;
            int row = idx >> 2, c4 = idx & 3;
            uint32_t so = SWZ64((uint32_t)(row * 64 + c4 * 16));
            cp16(st + OFF_AH + so, pAh + (size_t)row * lda + c4 * 8, true);
        }
        const __half* pBh = Bh + k0;
        const __half* pBl = Bl + k0;
        #pragma unroll
        for (int i = 0; i < 2; i++) {
            int idx = i * 256 + tid;
            int row = idx >> 2, c4 = idx & 3;
            bool ok = (bn + row) < N;
            size_t gr = ok ? (size_t)(bn + row) : 0;
            uint32_t so = SWZ64((uint32_t)(row * 64 + c4 * 16));
            cp16(st + OFF_BH + so, pBh + gr * ldb + c4 * 8, ok);
            cp16(st + OFF_BL + so, pBl + gr * ldb + c4 * 8, ok);
        }
    };

    issue(0, 0); CP_COMMIT();
    issue(1, 1); CP_COMMIT();
    issue(2, 2); CP_COMMIT();

    const int arow_l  = warp_m * 32 + (lane & 15);
    const int akoff_l = (lane >> 4) << 4;
    const int brow_l  = warp_n * 64 + (lane & 7) + ((lane >> 4) << 3);
    const int bkoff_l = ((lane >> 3) & 1) << 4;

    for (int c = 0; c < nch; c++) {
        CP_WAIT2();
        __syncthreads();
        uint32_t base = sb + (uint32_t)((c & 3) * STAGE_BYTES);
        #pragma unroll
        for (int ks = 0; ks < 2; ks++) {
            const int kb = ks * 32;
            uint32_t ah[2][4];
            #pragma unroll
            for (int mi = 0; mi < 2; mi++) {
                uint32_t off = SWZ64((uint32_t)((arow_l + mi * 16) * 64 + kb + akoff_l));
                ldsm4(base + OFF_AH + off, ah[mi]);
            }
            #pragma unroll
            for (int nj2 = 0; nj2 < 4; nj2++) {
                uint32_t bh[4], bl[4];
                uint32_t off = SWZ64((uint32_t)((brow_l + nj2 * 16) * 64 + kb + bkoff_l));
                ldsm4(base + OFF_BH + off, bh);
                ldsm4(base + OFF_BL + off, bl);
                #pragma unroll
                for (int mi = 0; mi < 2; mi++) {
                    mma_f16(acc[mi][nj2*2+0], ah[mi], bh[0], bh[1]);
                    mma_f16(acc[mi][nj2*2+0], ah[mi], bl[0], bl[1]);
                    mma_f16(acc[mi][nj2*2+1], ah[mi], bh[2], bh[3]);
                    mma_f16(acc[mi][nj2*2+1], ah[mi], bl[2], bl[3]);
                }
            }
        }
        issue(c + 3, (c + 3) & 3);
        CP_COMMIT();
    }

    // ---- epilogue ----
    #pragma unroll
    for (int mi = 0; mi < 2; mi++) {
        #pragma unroll
        for (int nj = 0; nj < 8; nj++) {
            int row = bm + warp_m * 32 + mi * 16 + (lane >> 2);
            int col = bn + warp_n * 64 + nj * 8 + (lane & 3) * 2;
            if (col < N) {
                float* d = acc[mi][nj];
                float2 v0 = make_float2(d[0], d[1]);
                float2 v1 = make_float2(d[2], d[3]);
                float* p0 = Cz + (size_t)row * ldc + col;
                float* p1 = Cz + (size_t)(row + 8) * ldc + col;
                if (EPI == 1) {
                    float2 o0 = *(float2*)p0; v0.x += o0.x; v0.y += o0.y;
                    float2 o1 = *(float2*)p1; v1.x += o1.x; v1.y += o1.y;
                } else if (EPI == 3) {
                    float br0 = bias[row], br1 = bias[row + 8];
                    v0.x = softplus_f(v0.x + br0); v0.y = softplus_f(v0.y + br0);
                    v1.x = softplus_f(v1.x + br1); v1.y = softplus_f(v1.y + br1);
                }
                *(float2*)p0 = v0;
                *(float2*)p1 = v1;
            }
        }
    }
}

// ============== weight prep: fp32 (K,N) -> fp16 hi/lo [N,K] ==============
__global__ void transpose_split_f16(const float* __restrict__ W, int K, int N,
                                    __half* __restrict__ Bh, __half* __restrict__ Bl)
{
    __shared__ float t[32][33];
    int k0 = blockIdx.x * 32, n0 = blockIdx.y * 32;
    int tx = threadIdx.x, ty = threadIdx.y;   // 32 x 8
    #pragma unroll
    for (int i = 0; i < 4; i++) {
        int k = k0 + ty + 8 * i;
        float v = (n0 + tx < N) ? W[(size_t)k * N + n0 + tx] : 0.f;
        t[ty + 8 * i][tx] = v;
    }
    __syncthreads();
    #pragma unroll
    for (int i = 0; i < 4; i++) {
        int n = n0 + ty + 8 * i;
        int k = k0 + tx;
        float v = t[tx][ty + 8 * i];
        __half h = __float2half_rn(v);
        __half l = __float2half_rn(v - __half2float(h));
        Bh[(size_t)n * K + k] = h;
        Bl[(size_t)n * K + k] = l;
    }
}

// elementwise fp16 hi/lo split (already [N,K] layout): lm_head
__global__ void split_kernel_f16(const float4* __restrict__ W,
                                 __half* __restrict__ Bh, __half* __restrict__ Bl, int n4)
{
    int i = blockIdx.x * blockDim.x + threadIdx.x;
    if (i >= n4) return;
    float4 v = W[i];
    __half2 h0 = __floats2half2_rn(v.x, v.y);
    __half2 h1 = __floats2half2_rn(v.z, v.w);
    __half2 l0 = __floats2half2_rn(v.x - __low2float(h0), v.y - __high2float(h0));
    __half2 l1 = __floats2half2_rn(v.z - __low2float(h1), v.w - __high2float(h1));
    uint2 hh, llv;
    hh.x = *(uint32_t*)&h0;  hh.y = *(uint32_t*)&h1;
    llv.x = *(uint32_t*)&l0; llv.y = *(uint32_t*)&l1;
    ((uint2*)Bh)[i] = hh;
    ((uint2*)Bl)[i] = llv;
}

// ---------------- xproj split-K reduce: dbl hi/lo + transposed B,C ---------
__global__ void reduce_xproj()
{
    int i = blockIdx.x * blockDim.x + threadIdx.x;
    if (i >= NTOK * 96) return;
    float s = g_xpart[i] + g_xpart[i + NTOK*96] + g_xpart[i + 2*NTOK*96] + g_xpart[i + 3*NTOK*96];
    int c = i % 96, t = i / 96;
    if (c < 64) {
        __half h = __float2half_rn(s);
        __half l = __float2half_rn(s - __half2float(h));
        g_dblh[i] = h;
        g_dbll[i] = l;
    } else {
        g_bcT[(size_t)(c - 64) * NTOK + t] = s;
    }
}

// ---------------- embed gather ----------------
__global__ void embed_kernel(const int* __restrict__ tokens,
                             const float* __restrict__ embed)
{
    int t = blockIdx.x;
    int tok = tokens[t];
    const float4* src = (const float4*)(embed + (size_t)tok * DD);
    float4* dst = (float4*)(g_x + (size_t)t * DD);
    for (int i = threadIdx.x; i < DD/4; i += blockDim.x)
        dst[i] = src[i];
}

// ---------------- rmsnorm (writes fp16) ----------------
__global__ void rmsnorm_kernel(const float* __restrict__ x,
                               const float* __restrict__ w,
                               __half* __restrict__ o)
{
    int t = blockIdx.x;
    const float4* xr = (const float4*)(x + (size_t)t * DD);
    const float4* wr = (const float4*)w;

    float s = 0.f;
    for (int i = threadIdx.x; i < DD/4; i += blockDim.x) {
        float4 v = xr[i];
        s += v.x*v.x + v.y*v.y + v.z*v.z + v.w*v.w;
    }
    __shared__ float red[8];
    for (int m = 16; m > 0; m >>= 1) s += __shfl_xor_sync(0xffffffffu, s, m);
    if ((threadIdx.x & 31) == 0) red[threadIdx.x >> 5] = s;
    __syncthreads();
    float tot = 0.f;
    if (threadIdx.x < 8) tot = red[threadIdx.x];
    for (int m = 4; m > 0; m >>= 1) tot += __shfl_xor_sync(0xffffffffu, tot, m);
    __shared__ float inv_s;
    if (threadIdx.x == 0) inv_s = rsqrtf(tot / (float)DD + 1e-5f);
    __syncthreads();
    float inv = inv_s;

    for (int i = threadIdx.x; i < DD/4; i += blockDim.x) {
        float4 v = xr[i];
        float4 wv = wr[i];
        __half2 h0 = __floats2half2_rn(v.x * wv.x * inv, v.y * wv.y * inv);
        __half2 h1 = __floats2half2_rn(v.z * wv.z * inv, v.w * wv.w * inv);
        uint2 hh;
        hh.x = *(uint32_t*)&h0; hh.y = *(uint32_t*)&h1;
        *(uint2*)(o + (size_t)t * DD + i * 4) = hh;
    }
}

// ---------------- causal conv (K=4) + silu (writes fp16 [t][e]) ------------
__global__ void conv_silu_kernel(const float* __restrict__ conv_w,
                                 const float* __restrict__ conv_b)
{
    int idx = blockIdx.x * blockDim.x + threadIdx.x;
    if (idx >= NTOK * EE) return;
    int e = idx % EE;
    int tk = idx / EE;
    int t = tk % LL;

    const float* src = g_xz + (size_t)(tk - t) * (2*EE) + e;
    float acc = conv_b[e];
    #pragma unroll
    for (int k = 0; k < KK; k++) {
        int tt = t + k - (KK - 1);
        if (tt >= 0)
            acc = fmaf(conv_w[e*KK + k], src[(size_t)tt * (2*EE)], acc);
    }
    float sg = 1.f / (1.f + __expf(-acc));
    g_xc[idx] = __float2half_rn(acc * sg);
}

// ---------------- transpose xc -> xcT and silu(z) -> gT ---------------------
// grid (NTOK/32, EE/32), block (32,8)
__global__ void transpose_xg()
{
    __shared__ __half tx[32][33];
    __shared__ __half tg[32][33];
    int t0 = blockIdx.x * 32, e0 = blockIdx.y * 32;
    int lx = threadIdx.x, ly = threadIdx.y;
    #pragma unroll
    for (int i = 0; i < 4; i++) {
        int t = t0 + ly + 8 * i;
        tx[ly + 8 * i][lx] = g_xc[(size_t)t * EE + e0 + lx];
        float z = g_xz[(size_t)t * (2*EE) + EE + e0 + lx];
        float sg = 1.f / (1.f + __expf(-z));
        tg[ly + 8 * i][lx] = __float2half_rn(z * sg);
    }
    __syncthreads();
    #pragma unroll
    for (int i = 0; i < 4; i++) {
        int e = e0 + ly + 8 * i;
        g_xcT[(size_t)e * NTOK + t0 + lx] = tx[lx][ly + 8 * i];
        g_gT [(size_t)e * NTOK + t0 + lx] = tg[lx][ly + 8 * i];
    }
}

// ---------------- selective scan (transposed layout, vector prefetch) ------
#define SD 8
__global__ __launch_bounds__(128)
void scan_kernel(const float* __restrict__ A_log,
                 const float* __restrict__ D_skip)
{
    int group = threadIdx.x >> 4;
    int n     = threadIdx.x & 15;
    int ch    = blockIdx.x * 8 + group;   // 0..4095
    int b = ch >> 11;
    int e = ch & (EE - 1);

    float a   = -__expf(A_log[e * NN_ + n]);
    float dsk = D_skip[e];
    float h = 0.f;

    const float*  dtp = g_dtT + (size_t)e * NTOK + b * LL;
    const __half* xp  = g_xcT + (size_t)e * NTOK + b * LL;
    const __half* gp  = g_gT  + (size_t)e * NTOK + b * LL;
    const float*  Bp  = g_bcT + (size_t)n * NTOK + b * LL;
    const float*  Cp  = g_bcT + (size_t)(16 + n) * NTOK + b * LL;
    __half* y0 = g_y + (size_t)b * LL * EE + e;

    float p_dt[2][SD], p_B[2][SD], p_C[2][SD], p_x[2][SD], p_g[2][SD];

#define PREF(BK, TP) do {                                                    \
    int tb = (TP) > (LL - SD) ? (LL - SD) : (TP);                            \
    float4 v0 = *(const float4*)(dtp + tb);                                  \
    float4 v1 = *(const float4*)(dtp + tb + 4);                              \
    p_dt[BK][0]=v0.x; p_dt[BK][1]=v0.y; p_dt[BK][2]=v0.z; p_dt[BK][3]=v0.w;  \
    p_dt[BK][4]=v1.x; p_dt[BK][5]=v1.y; p_dt[BK][6]=v1.z; p_dt[BK][7]=v1.w;  \
    v0 = *(const float4*)(Bp + tb); v1 = *(const float4*)(Bp + tb + 4);      \
    p_B[BK][0]=v0.x; p_B[BK][1]=v0.y; p_B[BK][2]=v0.z; p_B[BK][3]=v0.w;      \
    p_B[BK][4]=v1.x; p_B[BK][5]=v1.y; p_B[BK][6]=v1.z; p_B[BK][7]=v1.w;      \
    v0 = *(const float4*)(Cp + tb); v1 = *(const float4*)(Cp + tb + 4);      \
    p_C[BK][0]=v0.x; p_C[BK][1]=v0.y; p_C[BK][2]=v0.z; p_C[BK][3]=v0.w;      \
    p_C[BK][4]=v1.x; p_C[BK][5]=v1.y; p_C[BK][6]=v1.z; p_C[BK][7]=v1.w;      \
    uint4 u = *(const uint4*)(xp + tb);                                      \
    p_x[BK][0]=h2f_lo(u.x); p_x[BK][1]=h2f_hi(u.x);                          \
    p_x[BK][2]=h2f_lo(u.y); p_x[BK][3]=h2f_hi(u.y);                          \
    p_x[BK][4]=h2f_lo(u.z); p_x[BK][5]=h2f_hi(u.z);                          \
    p_x[BK][6]=h2f_lo(u.w); p_x[BK][7]=h2f_hi(u.w);                          \
    u = *(const uint4*)(gp + tb);                                            \
    p_g[BK][0]=h2f_lo(u.x); p_g[BK][1]=h2f_hi(u.x);                          \
    p_g[BK][2]=h2f_lo(u.y); p_g[BK][3]=h2f_hi(u.y);                          \
    p_g[BK][4]=h2f_lo(u.z); p_g[BK][5]=h2f_hi(u.z);                          \
    p_g[BK][6]=h2f_lo(u.w); p_g[BK][7]=h2f_hi(u.w);                          \
} while (0)

#define COMP(BK, T0) do {                                                    \
    _Pragma("unroll")                                                        \
    for (int j = 0; j < SD; j++) {                                           \
        float dte = p_dt[BK][j];                                             \
        float xe  = p_x[BK][j];                                              \
        float dA  = __expf(dte * a);                                         \
        h = fmaf(h, dA, dte * xe * p_B[BK][j]);                              \
        float p = h * p_C[BK][j];                                            \
        p += __shfl_xor_sync(0xffffffffu, p, 8);                             \
        p += __shfl_xor_sync(0xffffffffu, p, 4);                             \
        p += __shfl_xor_sync(0xffffffffu, p, 2);                             \
        p += __shfl_xor_sync(0xffffffffu, p, 1);                             \
        if (n == 0) {                                                        \
            float y = (p + xe * dsk) * p_g[BK][j];                           \
            y0[(size_t)((T0) + j) * EE] = __float2half_rn(y);                \
        }                                                                    \
    } } while (0)

    PREF(0, 0);
    for (int t0 = 0; t0 < LL; t0 += 2*SD) {
        PREF(1, t0 + SD);
        COMP(0, t0);
        PREF(0, t0 + 2*SD);
        COMP(1, t0 + SD);
    }
#undef PREF
#undef COMP
}

// ---------------- host launch ----------------
extern "C" void kernel_launch(void* const* d_in, const int* in_sizes, int n_in,
                              void* d_out, int out_size)
{
    const int*   tokens   = (const int*)  d_in[0];
    const float* embed    = (const float*)d_in[1];
    const float* norm_w   = (const float*)d_in[2];
    const float* W_in     = (const float*)d_in[3];
    const float* conv_w   = (const float*)d_in[4];
    const float* conv_b   = (const float*)d_in[5];
    const float* W_xproj  = (const float*)d_in[6];
    const float* W_dt     = (const float*)d_in[7];
    const float* dt_bias  = (const float*)d_in[8];
    const float* A_log    = (const float*)d_in[9];
    const float* D_skip   = (const float*)d_in[10];
    const float* W_out    = (const float*)d_in[11];
    const float* final_nw = (const float*)d_in[12];
    const float* lm_head  = (const float*)d_in[13];
    float* out = (float*)d_out;

    float *px, *pxz, *pxpart, *pdtT;
    __half *pxn, *pxc, *pdblh, *pdbll, *py, *pbh, *pbl;
    cudaGetSymbolAddress((void**)&px,    g_x);
    cudaGetSymbolAddress((void**)&pxn,   g_xn);
    cudaGetSymbolAddress((void**)&pxz,   g_xz);
    cudaGetSymbolAddress((void**)&pxc,   g_xc);
    cudaGetSymbolAddress((void**)&pdblh, g_dblh);
    cudaGetSymbolAddress((void**)&pdbll, g_dbll);
    cudaGetSymbolAddress((void**)&pdtT,  g_dtT);
    cudaGetSymbolAddress((void**)&py,    g_y);
    cudaGetSymbolAddress((void**)&pbh,   g_bh);
    cudaGetSymbolAddress((void**)&pbl,   g_bl);
    cudaGetSymbolAddress((void**)&pxpart, g_xpart);

    static bool attr_done = false;
    if (!attr_done) {
        cudaFuncSetAttribute(mmagemm<0>, cudaFuncAttributeMaxDynamicSharedMemorySize, SMEM_BYTES);
        cudaFuncSetAttribute(mmagemm<1>, cudaFuncAttributeMaxDynamicSharedMemorySize, SMEM_BYTES);
        cudaFuncSetAttribute(mmagemm<3>, cudaFuncAttributeMaxDynamicSharedMemorySize, SMEM_BYTES);
        attr_done = true;
    }

    embed_kernel<<<NTOK, 256>>>(tokens, embed);

    for (int l = 0; l < NLAYERS; l++) {
        const float* nw  = norm_w  + (size_t)l * DD;
        const float* win = W_in    + (size_t)l * DD * 2 * EE;
        const float* cw  = conv_w  + (size_t)l * EE * KK;
        const float* cb  = conv_b  + (size_t)l * EE;
        const float* wxp = W_xproj + (size_t)l * EE * 96;
        const float* wdt = W_dt    + (size_t)l * RR * EE;
        const float* dtb = dt_bias + (size_t)l * EE;
        const float* alg = A_log   + (size_t)l * EE * NN_;
        const float* dsk = D_skip  + (size_t)l * EE;
        const float* wo  = W_out   + (size_t)l * EE * DD;

        // 1. rmsnorm -> fp16 xn
        rmsnorm_kernel<<<NTOK, 256>>>(px, nw, pxn);

        // 2. xz = xn @ W_in   (4096 x 4096 x 1024)
        transpose_split_f16<<<dim3(DD/32, (2*EE)/32), dim3(32,8)>>>(win, DD, 2*EE, pbh, pbl);
        mmagemm<0><<<dim3(NTOK/128, (2*EE)/128), 256, SMEM_BYTES>>>(
            pxn, pbh, pbl, pxz, nullptr,
            2*EE, DD, DD, DD, 2*EE, 0);

        // 3. causal conv + silu -> fp16 xc [t][e]
        conv_silu_kernel<<<(NTOK*EE + 255)/256, 256>>>(cw, cb);

        // 3b. transpose xc -> xcT, silu(z) -> gT
        transpose_xg<<<dim3(NTOK/32, EE/32), dim3(32,8)>>>();

        // 4. dbl = xc @ W_xproj  (4096 x 96 x 2048), split-K x4 + reduce
        transpose_split_f16<<<dim3(EE/32, 128/32), dim3(32,8)>>>(wxp, EE, 96, pbh, pbl);
        mmagemm<0><<<dim3(NTOK/128, 1, 4), 256, SMEM_BYTES>>>(
            pxc, pbh, pbl, pxpart, nullptr,
            96, EE/4, EE, EE, 96, (size_t)NTOK*96);
        reduce_xproj<<<(NTOK*96 + 255)/256, 256>>>();

        // 5. dtT = softplus(W_dt^T @ dbl^T + bias[row])  -> [E, NTOK]
        //    A = wdtT hi [E,R], B = dblh/dbll [NTOK,96] (K=64)
        transpose_split_f16<<<dim3(RR/32, EE/32), dim3(32,8)>>>(wdt, RR, EE, pbh, pbl);
        mmagemm<3><<<dim3(EE/128, NTOK/128), 256, SMEM_BYTES>>>(
            pbh, pdblh, pdbll, pdtT, dtb,
            NTOK, RR, RR, 96, NTOK, 0);

        // 6. selective scan + gate -> fp16 y [t][e]
        scan_kernel<<<(BB*EE)/8, 128>>>(alg, dsk);

        // 7. x += y @ W_out  (4096 x 1024 x 2048)
        transpose_split_f16<<<dim3(EE/32, DD/32), dim3(32,8)>>>(wo, EE, DD, pbh, pbl);
        mmagemm<1><<<dim3(NTOK/128, DD/128), 256, SMEM_BYTES>>>(
            py, pbh, pbl, px, nullptr,
            DD, EE, EE, EE, DD, 0);
    }

    // final rmsnorm -> fp16 xn
    rmsnorm_kernel<<<NTOK, 256>>>(px, final_nw, pxn);

    // logits = xn @ lm_head^T  (4096 x 32000 x 1024); lm_head already [N,K]
    split_kernel_f16<<<(VV*DD/4 + 255)/256, 256>>>(
        (const float4*)lm_head, pbh, pbl, VV*DD/4);
    mmagemm<0><<<dim3(NTOK/128, VV/128), 256, SMEM_BYTES>>>(
        pxn, pbh, pbl, out, nullptr,
        VV, DD, DD, DD, VV, 0);
}

// round 10
// speedup vs baseline: 6.2569x; 1.2020x over previous
#include <cuda_runtime.h>
#include <cuda_fp16.h>
#include <math.h>
#include <stdint.h>

// Problem dims
#define BB 2
#define LL 2048
#define DD 1024
#define VV 32000
#define NLAYERS 2
#define EE 2048
#define NN_ 16
#define RR 64
#define KK 4
#define NTOK (BB*LL)          // 4096 tokens

// ---------------- scratch (device globals; no allocation allowed) ----------
__device__ float  g_x   [NTOK*DD];      // residual fp32
__device__ __half g_xn  [NTOK*DD];      // rmsnorm out fp16
__device__ float  g_xz  [NTOK*2*EE];    // W_in out fp32
__device__ __half g_xc  [NTOK*EE];      // conv+silu out fp16 [t][e]
__device__ __half g_xcT [EE*NTOK];      // conv+silu out fp16 [e][t]
__device__ __half g_gT  [EE*NTOK];      // silu(z) fp16 [e][t]
__device__ __half g_dblh[NTOK*96];      // xproj out hi fp16 (dt GEMM B)
__device__ __half g_dbll[NTOK*96];      // xproj out lo fp16
__device__ float  g_bcT [32*NTOK];      // B (rows 0..15), C (rows 16..31) [n][tk]
__device__ float  g_xpart[4*NTOK*96];   // xproj split-K partials
__device__ float  g_dtT [EE*NTOK];      // softplus(dt) fp32 [e][tk]
__device__ __half g_y   [NTOK*EE];      // scan out fp16 [t][e]
// fp16 hi/lo split weight buffers (sized for lm_head: 32000x1024)
__device__ __half g_bh[VV*DD];
__device__ __half g_bl[VV*DD];

// ======================= helpers ==============================
__device__ __forceinline__ uint32_t smem_u32(const void* p) {
    uint32_t a;
    asm("{ .reg .u64 t; cvta.to.shared.u64 t, %1; cvt.u32.u64 %0, t; }" : "=r"(a) : "l"(p));
    return a;
}
// SW64 swizzle for 64-byte rows (Swizzle<2,4,3>)
#define SWZ64(off) ((off) ^ (((off) >> 3) & 0x30))

__device__ __forceinline__ void ldsm4(uint32_t addr, uint32_t* r) {
    asm volatile("ldmatrix.sync.aligned.m8n8.x4.shared.b16 {%0,%1,%2,%3}, [%4];"
                 : "=r"(r[0]), "=r"(r[1]), "=r"(r[2]), "=r"(r[3]) : "r"(addr));
}
__device__ __forceinline__ void mma_f16(float* d, const uint32_t* a, uint32_t b0, uint32_t b1) {
    asm volatile(
        "mma.sync.aligned.m16n8k16.row.col.f32.f16.f16.f32 "
        "{%0,%1,%2,%3}, {%4,%5,%6,%7}, {%8,%9}, {%0,%1,%2,%3};"
        : "+f"(d[0]), "+f"(d[1]), "+f"(d[2]), "+f"(d[3])
        : "r"(a[0]), "r"(a[1]), "r"(a[2]), "r"(a[3]), "r"(b0), "r"(b1));
}
__device__ __forceinline__ void cp16(uint32_t s, const void* g, bool p) {
    asm volatile("cp.async.cg.shared.global [%0], [%1], 16, %2;"
                 :: "r"(s), "l"(g), "r"(p ? 16 : 0) : "memory");
}
#define CP_COMMIT() asm volatile("cp.async.commit_group;" ::: "memory")
#define CP_WAIT2()  asm volatile("cp.async.wait_group 2;"  ::: "memory")

__device__ __forceinline__ float softplus_f(float v) {
    return (v > 20.f) ? v : log1pf(expf(v));
}
__device__ __forceinline__ float h2f_lo(uint32_t w) {
    return __half2float(__ushort_as_half((unsigned short)(w & 0xFFFFu)));
}
__device__ __forceinline__ float h2f_hi(uint32_t w) {
    return __half2float(__ushort_as_half((unsigned short)(w >> 16)));
}

// ======================= fp16 mma.sync GEMM (4-stage ring, 1 sync/chunk) ====
// NT=2: C = Ah @ (Bh+Bl)^T (2-term).  NT=1: C = Ah @ Bh^T (Bl unused).
// A fp16 row-major (lda), Bh/Bl fp16 [N,K] K-major (ldb).
// CTA tile 128x128, 8 warps (4m x 2n, warp tile 32x64). K-chunk = 32.
// grid: (M/128, ceil(N/128), ksplit)
// EPI: 0=store fp32, 1=C+=acc, 3=softplus(acc+bias[row])
template<int EPI, int NT>
__global__ __launch_bounds__(256, 2)
void mmagemm(const __half* __restrict__ Ah,
             const __half* __restrict__ Bh, const __half* __restrict__ Bl,
             float* __restrict__ C, const float* __restrict__ bias,
             int N, int K, int lda, int ldb, int ldc, size_t czstride)
{
    constexpr uint32_t STAGE = (NT == 1) ? 16384u : 24576u;
    constexpr uint32_t OFF_AH = 0, OFF_BH = 8192, OFF_BL = 16384;

    extern __shared__ __align__(1024) char smem[];
    uint32_t sb = smem_u32(smem);
    const int tid = threadIdx.x;
    const int lane = tid & 31;
    const int wid = tid >> 5;
    const int warp_m = wid >> 1;
    const int warp_n = wid & 1;
    const int bm = blockIdx.x * 128;
    const int bn = blockIdx.y * 128;
    const int zoff = blockIdx.z * K;
    float* Cz = C + (size_t)blockIdx.z * czstride;
    const int nch = K >> 5;

    float acc[2][8][4];
    #pragma unroll
    for (int i = 0; i < 2; i++)
        #pragma unroll
        for (int j = 0; j < 8; j++)
            #pragma unroll
            for (int q = 0; q < 4; q++) acc[i][j][q] = 0.f;

    auto issue = [&](int c, int s) {
        if (c >= nch) return;
        uint32_t st = sb + (uint32_t)s * STAGE;
        const int k0 = zoff + (c << 5);
        const __half* pAh = Ah + (size_t)bm * lda + k0;
        #pragma unroll
        for (int i = 0; i < 2; i++) {
            int idx = i * 256 + tid;
            int row = idx >> 2, c4 = idx & 3;
            uint32_t so = SWZ64((uint32_t)(row * 64 + c4 * 16));
            cp16(st + OFF_AH + so, pAh + (size_t)row * lda + c4 * 8, true);
        }
        const __half* pBh = Bh + k0;
        const __half* pBl = Bl + k0;
        #pragma unroll
        for (int i = 0; i < 2; i++) {
            int idx = i * 256 + tid;
            int row = idx >> 2, c4 = idx & 3;
            bool ok = (bn + row) < N;
            size_t gr = ok ? (size_t)(bn + row) : 0;
            uint32_t so = SWZ64((uint32_t)(row * 64 + c4 * 16));
            cp16(st + OFF_BH + so, pBh + gr * ldb + c4 * 8, ok);
            if (NT == 2)
                cp16(st + OFF_BL + so, pBl + gr * ldb + c4 * 8, ok);
        }
    };

    issue(0, 0); CP_COMMIT();
    issue(1, 1); CP_COMMIT();
    issue(2, 2); CP_COMMIT();

    const int arow_l  = warp_m * 32 + (lane & 15);
    const int akoff_l = (lane >> 4) << 4;
    const int brow_l  = warp_n * 64 + (lane & 7) + ((lane >> 4) << 3);
    const int bkoff_l = ((lane >> 3) & 1) << 4;

    for (int c = 0; c < nch; c++) {
        CP_WAIT2();
        __syncthreads();
        uint32_t base = sb + (uint32_t)((c & 3) * STAGE);
        #pragma unroll
        for (int ks = 0; ks < 2; ks++) {
            const int kb = ks * 32;
            uint32_t ah[2][4];
            #pragma unroll
            for (int mi = 0; mi < 2; mi++) {
                uint32_t off = SWZ64((uint32_t)((arow_l + mi * 16) * 64 + kb + akoff_l));
                ldsm4(base + OFF_AH + off, ah[mi]);
            }
            #pragma unroll
            for (int nj2 = 0; nj2 < 4; nj2++) {
                uint32_t bh[4], bl[4];
                uint32_t off = SWZ64((uint32_t)((brow_l + nj2 * 16) * 64 + kb + bkoff_l));
                ldsm4(base + OFF_BH + off, bh);
                if (NT == 2) ldsm4(base + OFF_BL + off, bl);
                #pragma unroll
                for (int mi = 0; mi < 2; mi++) {
                    mma_f16(acc[mi][nj2*2+0], ah[mi], bh[0], bh[1]);
                    mma_f16(acc[mi][nj2*2+1], ah[mi], bh[2], bh[3]);
                    if (NT == 2) {
                        mma_f16(acc[mi][nj2*2+0], ah[mi], bl[0], bl[1]);
                        mma_f16(acc[mi][nj2*2+1], ah[mi], bl[2], bl[3]);
                    }
                }
            }
        }
        issue(c + 3, (c + 3) & 3);
        CP_COMMIT();
    }

    // ---- epilogue ----
    #pragma unroll
    for (int mi = 0; mi < 2; mi++) {
        #pragma unroll
        for (int nj = 0; nj < 8; nj++) {
            int row = bm + warp_m * 32 + mi * 16 + (lane >> 2);
            int col = bn + warp_n * 64 + nj * 8 + (lane & 3) * 2;
            if (col < N) {
                float* d = acc[mi][nj];
                float2 v0 = make_float2(d[0], d[1]);
                float2 v1 = make_float2(d[2], d[3]);
                float* p0 = Cz + (size_t)row * ldc + col;
                float* p1 = Cz + (size_t)(row + 8) * ldc + col;
                if (EPI == 1) {
                    float2 o0 = *(float2*)p0; v0.x += o0.x; v0.y += o0.y;
                    float2 o1 = *(float2*)p1; v1.x += o1.x; v1.y += o1.y;
                } else if (EPI == 3) {
                    float br0 = bias[row], br1 = bias[row + 8];
                    v0.x = softplus_f(v0.x + br0); v0.y = softplus_f(v0.y + br0);
                    v1.x = softplus_f(v1.x + br1); v1.y = softplus_f(v1.y + br1);
                }
                *(float2*)p0 = v0;
                *(float2*)p1 = v1;
            }
        }
    }
}

// ============== weight prep: fp32 (K,N) -> fp16 hi/lo [N,K] ==============
__global__ void transpose_split_f16(const float* __restrict__ W, int K, int N,
                                    __half* __restrict__ Bh, __half* __restrict__ Bl)
{
    __shared__ float t[32][33];
    int k0 = blockIdx.x * 32, n0 = blockIdx.y * 32;
    int tx = threadIdx.x, ty = threadIdx.y;   // 32 x 8
    #pragma unroll
    for (int i = 0; i < 4; i++) {
        int k = k0 + ty + 8 * i;
        float v = (n0 + tx < N) ? W[(size_t)k * N + n0 + tx] : 0.f;
        t[ty + 8 * i][tx] = v;
    }
    __syncthreads();
    #pragma unroll
    for (int i = 0; i < 4; i++) {
        int n = n0 + ty + 8 * i;
        int k = k0 + tx;
        float v = t[tx][ty + 8 * i];
        __half h = __float2half_rn(v);
        __half l = __float2half_rn(v - __half2float(h));
        Bh[(size_t)n * K + k] = h;
        Bl[(size_t)n * K + k] = l;
    }
}

// elementwise fp32 -> fp16 cast (already [N,K] layout): lm_head, hi only
__global__ void cast_f16(const float4* __restrict__ W,
                         __half* __restrict__ Bh, int n4)
{
    int i = blockIdx.x * blockDim.x + threadIdx.x;
    if (i >= n4) return;
    float4 v = W[i];
    __half2 h0 = __floats2half2_rn(v.x, v.y);
    __half2 h1 = __floats2half2_rn(v.z, v.w);
    uint2 hh;
    hh.x = *(uint32_t*)&h0;  hh.y = *(uint32_t*)&h1;
    ((uint2*)Bh)[i] = hh;
}

// ---------------- xproj split-K reduce: dbl hi/lo + transposed B,C ---------
__global__ void reduce_xproj()
{
    int i = blockIdx.x * blockDim.x + threadIdx.x;
    if (i >= NTOK * 96) return;
    float s = g_xpart[i] + g_xpart[i + NTOK*96] + g_xpart[i + 2*NTOK*96] + g_xpart[i + 3*NTOK*96];
    int c = i % 96, t = i / 96;
    if (c < 64) {
        __half h = __float2half_rn(s);
        __half l = __float2half_rn(s - __half2float(h));
        g_dblh[i] = h;
        g_dbll[i] = l;
    } else {
        g_bcT[(size_t)(c - 64) * NTOK + t] = s;
    }
}

// ---------------- embed gather ----------------
__global__ void embed_kernel(const int* __restrict__ tokens,
                             const float* __restrict__ embed)
{
    int t = blockIdx.x;
    int tok = tokens[t];
    const float4* src = (const float4*)(embed + (size_t)tok * DD);
    float4* dst = (float4*)(g_x + (size_t)t * DD);
    for (int i = threadIdx.x; i < DD/4; i += blockDim.x)
        dst[i] = src[i];
}

// ---------------- rmsnorm (writes fp16) ----------------
__global__ void rmsnorm_kernel(const float* __restrict__ x,
                               const float* __restrict__ w,
                               __half* __restrict__ o)
{
    int t = blockIdx.x;
    const float4* xr = (const float4*)(x + (size_t)t * DD);
    const float4* wr = (const float4*)w;

    float s = 0.f;
    for (int i = threadIdx.x; i < DD/4; i += blockDim.x) {
        float4 v = xr[i];
        s += v.x*v.x + v.y*v.y + v.z*v.z + v.w*v.w;
    }
    __shared__ float red[8];
    for (int m = 16; m > 0; m >>= 1) s += __shfl_xor_sync(0xffffffffu, s, m);
    if ((threadIdx.x & 31) == 0) red[threadIdx.x >> 5] = s;
    __syncthreads();
    float tot = 0.f;
    if (threadIdx.x < 8) tot = red[threadIdx.x];
    for (int m = 4; m > 0; m >>= 1) tot += __shfl_xor_sync(0xffffffffu, tot, m);
    __shared__ float inv_s;
    if (threadIdx.x == 0) inv_s = rsqrtf(tot / (float)DD + 1e-5f);
    __syncthreads();
    float inv = inv_s;

    for (int i = threadIdx.x; i < DD/4; i += blockDim.x) {
        float4 v = xr[i];
        float4 wv = wr[i];
        __half2 h0 = __floats2half2_rn(v.x * wv.x * inv, v.y * wv.y * inv);
        __half2 h1 = __floats2half2_rn(v.z * wv.z * inv, v.w * wv.w * inv);
        uint2 hh;
        hh.x = *(uint32_t*)&h0; hh.y = *(uint32_t*)&h1;
        *(uint2*)(o + (size_t)t * DD + i * 4) = hh;
    }
}

// ---------------- causal conv (K=4) + silu (writes fp16 [t][e]) ------------
__global__ void conv_silu_kernel(const float* __restrict__ conv_w,
                                 const float* __restrict__ conv_b)
{
    int idx = blockIdx.x * blockDim.x + threadIdx.x;
    if (idx >= NTOK * EE) return;
    int e = idx % EE;
    int tk = idx / EE;
    int t = tk % LL;

    const float* src = g_xz + (size_t)(tk - t) * (2*EE) + e;
    float acc = conv_b[e];
    #pragma unroll
    for (int k = 0; k < KK; k++) {
        int tt = t + k - (KK - 1);
        if (tt >= 0)
            acc = fmaf(conv_w[e*KK + k], src[(size_t)tt * (2*EE)], acc);
    }
    float sg = 1.f / (1.f + __expf(-acc));
    g_xc[idx] = __float2half_rn(acc * sg);
}

// ---------------- transpose xc -> xcT and silu(z) -> gT ---------------------
// grid (NTOK/32, EE/32), block (32,8)
__global__ void transpose_xg()
{
    __shared__ __half tx[32][33];
    __shared__ __half tg[32][33];
    int t0 = blockIdx.x * 32, e0 = blockIdx.y * 32;
    int lx = threadIdx.x, ly = threadIdx.y;
    #pragma unroll
    for (int i = 0; i < 4; i++) {
        int t = t0 + ly + 8 * i;
        tx[ly + 8 * i][lx] = g_xc[(size_t)t * EE + e0 + lx];
        float z = g_xz[(size_t)t * (2*EE) + EE + e0 + lx];
        float sg = 1.f / (1.f + __expf(-z));
        tg[ly + 8 * i][lx] = __float2half_rn(z * sg);
    }
    __syncthreads();
    #pragma unroll
    for (int i = 0; i < 4; i++) {
        int e = e0 + ly + 8 * i;
        g_xcT[(size_t)e * NTOK + t0 + lx] = tx[lx][ly + 8 * i];
        g_gT [(size_t)e * NTOK + t0 + lx] = tg[lx][ly + 8 * i];
    }
}

// ---------------- selective scan (transposed layout, vector prefetch) ------
#define SD 8
__global__ __launch_bounds__(128)
void scan_kernel(const float* __restrict__ A_log,
                 const float* __restrict__ D_skip)
{
    int group = threadIdx.x >> 4;
    int n     = threadIdx.x & 15;
    int ch    = blockIdx.x * 8 + group;   // 0..4095
    int b = ch >> 11;
    int e = ch & (EE - 1);

    float a   = -__expf(A_log[e * NN_ + n]);
    float dsk = D_skip[e];
    float h = 0.f;

    const float*  dtp = g_dtT + (size_t)e * NTOK + b * LL;
    const __half* xp  = g_xcT + (size_t)e * NTOK + b * LL;
    const __half* gp  = g_gT  + (size_t)e * NTOK + b * LL;
    const float*  Bp  = g_bcT + (size_t)n * NTOK + b * LL;
    const float*  Cp  = g_bcT + (size_t)(16 + n) * NTOK + b * LL;
    __half* y0 = g_y + (size_t)b * LL * EE + e;

    float p_dt[2][SD], p_B[2][SD], p_C[2][SD], p_x[2][SD], p_g[2][SD];

#define PREF(BK, TP) do {                                                    \
    int tb = (TP) > (LL - SD) ? (LL - SD) : (TP);                            \
    float4 v0 = *(const float4*)(dtp + tb);                                  \
    float4 v1 = *(const float4*)(dtp + tb + 4);                              \
    p_dt[BK][0]=v0.x; p_dt[BK][1]=v0.y; p_dt[BK][2]=v0.z; p_dt[BK][3]=v0.w;  \
    p_dt[BK][4]=v1.x; p_dt[BK][5]=v1.y; p_dt[BK][6]=v1.z; p_dt[BK][7]=v1.w;  \
    v0 = *(const float4*)(Bp + tb); v1 = *(const float4*)(Bp + tb + 4);      \
    p_B[BK][0]=v0.x; p_B[BK][1]=v0.y; p_B[BK][2]=v0.z; p_B[BK][3]=v0.w;      \
    p_B[BK][4]=v1.x; p_B[BK][5]=v1.y; p_B[BK][6]=v1.z; p_B[BK][7]=v1.w;      \
    v0 = *(const float4*)(Cp + tb); v1 = *(const float4*)(Cp + tb + 4);      \
    p_C[BK][0]=v0.x; p_C[BK][1]=v0.y; p_C[BK][2]=v0.z; p_C[BK][3]=v0.w;      \
    p_C[BK][4]=v1.x; p_C[BK][5]=v1.y; p_C[BK][6]=v1.z; p_C[BK][7]=v1.w;      \
    uint4 u = *(const uint4*)(xp + tb);                                      \
    p_x[BK][0]=h2f_lo(u.x); p_x[BK][1]=h2f_hi(u.x);                          \
    p_x[BK][2]=h2f_lo(u.y); p_x[BK][3]=h2f_hi(u.y);                          \
    p_x[BK][4]=h2f_lo(u.z); p_x[BK][5]=h2f_hi(u.z);                          \
    p_x[BK][6]=h2f_lo(u.w); p_x[BK][7]=h2f_hi(u.w);                          \
    u = *(const uint4*)(gp + tb);                                            \
    p_g[BK][0]=h2f_lo(u.x); p_g[BK][1]=h2f_hi(u.x);                          \
    p_g[BK][2]=h2f_lo(u.y); p_g[BK][3]=h2f_hi(u.y);                          \
    p_g[BK][4]=h2f_lo(u.z); p_g[BK][5]=h2f_hi(u.z);                          \
    p_g[BK][6]=h2f_lo(u.w); p_g[BK][7]=h2f_hi(u.w);                          \
} while (0)

#define COMP(BK, T0) do {                                                    \
    _Pragma("unroll")                                                        \
    for (int j = 0; j < SD; j++) {                                           \
        float dte = p_dt[BK][j];                                             \
        float xe  = p_x[BK][j];                                              \
        float dA  = __expf(dte * a);                                         \
        h = fmaf(h, dA, dte * xe * p_B[BK][j]);                              \
        float p = h * p_C[BK][j];                                            \
        p += __shfl_xor_sync(0xffffffffu, p, 8);                             \
        p += __shfl_xor_sync(0xffffffffu, p, 4);                             \
        p += __shfl_xor_sync(0xffffffffu, p, 2);                             \
        p += __shfl_xor_sync(0xffffffffu, p, 1);                             \
        if (n == 0) {                                                        \
            float y = (p + xe * dsk) * p_g[BK][j];                           \
            y0[(size_t)((T0) + j) * EE] = __float2half_rn(y);                \
        }                                                                    \
    } } while (0)

    PREF(0, 0);
    for (int t0 = 0; t0 < LL; t0 += 2*SD) {
        PREF(1, t0 + SD);
        COMP(0, t0);
        PREF(0, t0 + 2*SD);
        COMP(1, t0 + SD);
    }
#undef PREF
#undef COMP
}

// ---------------- host launch ----------------
extern "C" void kernel_launch(void* const* d_in, const int* in_sizes, int n_in,
                              void* d_out, int out_size)
{
    const int*   tokens   = (const int*)  d_in[0];
    const float* embed    = (const float*)d_in[1];
    const float* norm_w   = (const float*)d_in[2];
    const float* W_in     = (const float*)d_in[3];
    const float* conv_w   = (const float*)d_in[4];
    const float* conv_b   = (const float*)d_in[5];
    const float* W_xproj  = (const float*)d_in[6];
    const float* W_dt     = (const float*)d_in[7];
    const float* dt_bias  = (const float*)d_in[8];
    const float* A_log    = (const float*)d_in[9];
    const float* D_skip   = (const float*)d_in[10];
    const float* W_out    = (const float*)d_in[11];
    const float* final_nw = (const float*)d_in[12];
    const float* lm_head  = (const float*)d_in[13];
    float* out = (float*)d_out;

    float *px, *pxz, *pxpart, *pdtT;
    __half *pxn, *pxc, *pdblh, *pdbll, *py, *pbh, *pbl;
    cudaGetSymbolAddress((void**)&px,    g_x);
    cudaGetSymbolAddress((void**)&pxn,   g_xn);
    cudaGetSymbolAddress((void**)&pxz,   g_xz);
    cudaGetSymbolAddress((void**)&pxc,   g_xc);
    cudaGetSymbolAddress((void**)&pdblh, g_dblh);
    cudaGetSymbolAddress((void**)&pdbll, g_dbll);
    cudaGetSymbolAddress((void**)&pdtT,  g_dtT);
    cudaGetSymbolAddress((void**)&py,    g_y);
    cudaGetSymbolAddress((void**)&pbh,   g_bh);
    cudaGetSymbolAddress((void**)&pbl,   g_bl);
    cudaGetSymbolAddress((void**)&pxpart, g_xpart);

    static bool attr_done = false;
    if (!attr_done) {
        cudaFuncSetAttribute(mmagemm<0,2>, cudaFuncAttributeMaxDynamicSharedMemorySize, 4*24576);
        cudaFuncSetAttribute(mmagemm<1,2>, cudaFuncAttributeMaxDynamicSharedMemorySize, 4*24576);
        cudaFuncSetAttribute(mmagemm<3,2>, cudaFuncAttributeMaxDynamicSharedMemorySize, 4*24576);
        cudaFuncSetAttribute(mmagemm<0,1>, cudaFuncAttributeMaxDynamicSharedMemorySize, 4*16384);
        attr_done = true;
    }

    embed_kernel<<<NTOK, 256>>>(tokens, embed);

    for (int l = 0; l < NLAYERS; l++) {
        const float* nw  = norm_w  + (size_t)l * DD;
        const float* win = W_in    + (size_t)l * DD * 2 * EE;
        const float* cw  = conv_w  + (size_t)l * EE * KK;
        const float* cb  = conv_b  + (size_t)l * EE;
        const float* wxp = W_xproj + (size_t)l * EE * 96;
        const float* wdt = W_dt    + (size_t)l * RR * EE;
        const float* dtb = dt_bias + (size_t)l * EE;
        const float* alg = A_log   + (size_t)l * EE * NN_;
        const float* dsk = D_skip  + (size_t)l * EE;
        const float* wo  = W_out   + (size_t)l * EE * DD;

        // 1. rmsnorm -> fp16 xn
        rmsnorm_kernel<<<NTOK, 256>>>(px, nw, pxn);

        // 2. xz = xn @ W_in   (4096 x 4096 x 1024)
        transpose_split_f16<<<dim3(DD/32, (2*EE)/32), dim3(32,8)>>>(win, DD, 2*EE, pbh, pbl);
        mmagemm<0,2><<<dim3(NTOK/128, (2*EE)/128), 256, 4*24576>>>(
            pxn, pbh, pbl, pxz, nullptr,
            2*EE, DD, DD, DD, 2*EE, 0);

        // 3. causal conv + silu -> fp16 xc [t][e]
        conv_silu_kernel<<<(NTOK*EE + 255)/256, 256>>>(cw, cb);

        // 3b. transpose xc -> xcT, silu(z) -> gT
        transpose_xg<<<dim3(NTOK/32, EE/32), dim3(32,8)>>>();

        // 4. dbl = xc @ W_xproj  (4096 x 96 x 2048), split-K x4 + reduce
        transpose_split_f16<<<dim3(EE/32, 128/32), dim3(32,8)>>>(wxp, EE, 96, pbh, pbl);
        mmagemm<0,2><<<dim3(NTOK/128, 1, 4), 256, 4*24576>>>(
            pxc, pbh, pbl, pxpart, nullptr,
            96, EE/4, EE, EE, 96, (size_t)NTOK*96);
        reduce_xproj<<<(NTOK*96 + 255)/256, 256>>>();

        // 5. dtT = softplus(W_dt^T @ dbl^T + bias[row])  -> [E, NTOK]
        transpose_split_f16<<<dim3(RR/32, EE/32), dim3(32,8)>>>(wdt, RR, EE, pbh, pbl);
        mmagemm<3,2><<<dim3(EE/128, NTOK/128), 256, 4*24576>>>(
            pbh, pdblh, pdbll, pdtT, dtb,
            NTOK, RR, RR, 96, NTOK, 0);

        // 6. selective scan + gate -> fp16 y [t][e]
        scan_kernel<<<(BB*EE)/8, 128>>>(alg, dsk);

        // 7. x += y @ W_out  (4096 x 1024 x 2048)
        transpose_split_f16<<<dim3(EE/32, DD/32), dim3(32,8)>>>(wo, EE, DD, pbh, pbl);
        mmagemm<1,2><<<dim3(NTOK/128, DD/128), 256, 4*24576>>>(
            py, pbh, pbl, px, nullptr,
            DD, EE, EE, EE, DD, 0);
    }

    // final rmsnorm -> fp16 xn
    rmsnorm_kernel<<<NTOK, 256>>>(px, final_nw, pxn);

    // logits = xn @ lm_head^T  (4096 x 32000 x 1024); 1-term fp16
    cast_f16<<<(VV*DD/4 + 255)/256, 256>>>((const float4*)lm_head, pbh, VV*DD/4);
    mmagemm<0,1><<<dim3(NTOK/128, VV/128), 256, 4*16384>>>(
        pxn, pbh, nullptr, out, nullptr,
        VV, DD, DD, DD, VV, 0);
}

// round 11
// speedup vs baseline: 6.9682x; 1.1137x over previous
#include <cuda_runtime.h>
#include <cuda_fp16.h>
#include <math.h>
#include <stdint.h>

// Problem dims
#define BB 2
#define LL 2048
#define DD 1024
#define VV 32000
#define NLAYERS 2
#define EE 2048
#define NN_ 16
#define RR 64
#define KK 4
#define NTOK (BB*LL)          // 4096 tokens

// ---------------- scratch (device globals; no allocation allowed) ----------
__device__ float  g_x   [NTOK*DD];      // residual fp32
__device__ __half g_xn  [NTOK*DD];      // rmsnorm out fp16
__device__ float  g_xz  [NTOK*2*EE];    // W_in out fp32
__device__ __half g_xc  [NTOK*EE];      // conv+silu out fp16 [t][e]
__device__ __half g_xcT [EE*NTOK];      // conv+silu out fp16 [e][t]
__device__ __half g_gT  [EE*NTOK];      // silu(z) fp16 [e][t]
__device__ __half g_dblh[NTOK*96];      // xproj out hi fp16 (dt GEMM B)
__device__ __half g_dbll[NTOK*96];      // xproj out lo fp16
__device__ float  g_bcT [32*NTOK];      // B (rows 0..15), C (rows 16..31) [n][tk]
__device__ float  g_xpart[4*NTOK*96];   // xproj split-K partials
__device__ float  g_dtT [EE*NTOK];      // softplus(dt) fp32 [e][tk]
__device__ __half g_y   [NTOK*EE];      // scan out fp16 [t][e]
// fp16 hi/lo split weight buffers (sized for lm_head: 32000x1024)
__device__ __half g_bh[VV*DD];
__device__ __half g_bl[VV*DD];

// ======================= helpers ==============================
__device__ __forceinline__ uint32_t smem_u32(const void* p) {
    uint32_t a;
    asm("{ .reg .u64 t; cvta.to.shared.u64 t, %1; cvt.u32.u64 %0, t; }" : "=r"(a) : "l"(p));
    return a;
}
// SW64 swizzle for 64-byte rows (Swizzle<2,4,3>)
#define SWZ64(off) ((off) ^ (((off) >> 3) & 0x30))

__device__ __forceinline__ void ldsm4(uint32_t addr, uint32_t* r) {
    asm volatile("ldmatrix.sync.aligned.m8n8.x4.shared.b16 {%0,%1,%2,%3}, [%4];"
                 : "=r"(r[0]), "=r"(r[1]), "=r"(r[2]), "=r"(r[3]) : "r"(addr));
}
__device__ __forceinline__ void mma_f16(float* d, const uint32_t* a, uint32_t b0, uint32_t b1) {
    asm volatile(
        "mma.sync.aligned.m16n8k16.row.col.f32.f16.f16.f32 "
        "{%0,%1,%2,%3}, {%4,%5,%6,%7}, {%8,%9}, {%0,%1,%2,%3};"
        : "+f"(d[0]), "+f"(d[1]), "+f"(d[2]), "+f"(d[3])
        : "r"(a[0]), "r"(a[1]), "r"(a[2]), "r"(a[3]), "r"(b0), "r"(b1));
}
__device__ __forceinline__ void cp16(uint32_t s, const void* g, bool p) {
    asm volatile("cp.async.cg.shared.global [%0], [%1], 16, %2;"
                 :: "r"(s), "l"(g), "r"(p ? 16 : 0) : "memory");
}
#define CP_COMMIT() asm volatile("cp.async.commit_group;" ::: "memory")
#define CP_WAIT2()  asm volatile("cp.async.wait_group 2;"  ::: "memory")

__device__ __forceinline__ float softplus_f(float v) {
    return (v > 20.f) ? v : log1pf(expf(v));
}
__device__ __forceinline__ float h2f_lo(uint32_t w) {
    return __half2float(__ushort_as_half((unsigned short)(w & 0xFFFFu)));
}
__device__ __forceinline__ float h2f_hi(uint32_t w) {
    return __half2float(__ushort_as_half((unsigned short)(w >> 16)));
}

// ======================= fp16 mma.sync GEMM (4-stage ring, 1 sync/chunk) ====
// NT=2: C = Ah @ (Bh+Bl)^T.  NT=1: C = Ah @ Bh^T (Bl unused).
// A fp16 row-major (lda), Bh/Bl fp16 [N,K] K-major (ldb).
// CTA tile 128x128, 8 warps (4m x 2n, warp tile 32x64). K-chunk = 32.
// grid: (M/128, ceil(N/128), ksplit)
// EPI: 0=store fp32, 1=C+=acc, 3=softplus(acc+bias[row])
template<int EPI, int NT>
__global__ __launch_bounds__(256, 2)
void mmagemm(const __half* __restrict__ Ah,
             const __half* __restrict__ Bh, const __half* __restrict__ Bl,
             float* __restrict__ C, const float* __restrict__ bias,
             int N, int K, int lda, int ldb, int ldc, size_t czstride)
{
    constexpr uint32_t STAGE = (NT == 1) ? 16384u : 24576u;
    constexpr uint32_t OFF_AH = 0, OFF_BH = 8192, OFF_BL = 16384;

    extern __shared__ __align__(1024) char smem[];
    uint32_t sb = smem_u32(smem);
    const int tid = threadIdx.x;
    const int lane = tid & 31;
    const int wid = tid >> 5;
    const int warp_m = wid >> 1;
    const int warp_n = wid & 1;
    const int bm = blockIdx.x * 128;
    const int bn = blockIdx.y * 128;
    const int zoff = blockIdx.z * K;
    float* Cz = C + (size_t)blockIdx.z * czstride;
    const int nch = K >> 5;

    float acc[2][8][4];
    #pragma unroll
    for (int i = 0; i < 2; i++)
        #pragma unroll
        for (int j = 0; j < 8; j++)
            #pragma unroll
            for (int q = 0; q < 4; q++) acc[i][j][q] = 0.f;

    auto issue = [&](int c, int s) {
        if (c >= nch) return;
        uint32_t st = sb + (uint32_t)s * STAGE;
        const int k0 = zoff + (c << 5);
        const __half* pAh = Ah + (size_t)bm * lda + k0;
        #pragma unroll
        for (int i = 0; i < 2; i++) {
            int idx = i * 256 + tid;
            int row = idx >> 2, c4 = idx & 3;
            uint32_t so = SWZ64((uint32_t)(row * 64 + c4 * 16));
            cp16(st + OFF_AH + so, pAh + (size_t)row * lda + c4 * 8, true);
        }
        const __half* pBh = Bh + k0;
        const __half* pBl = Bl + k0;
        #pragma unroll
        for (int i = 0; i < 2; i++) {
            int idx = i * 256 + tid;
            int row = idx >> 2, c4 = idx & 3;
            bool ok = (bn + row) < N;
            size_t gr = ok ? (size_t)(bn + row) : 0;
            uint32_t so = SWZ64((uint32_t)(row * 64 + c4 * 16));
            cp16(st + OFF_BH + so, pBh + gr * ldb + c4 * 8, ok);
            if (NT == 2)
                cp16(st + OFF_BL + so, pBl + gr * ldb + c4 * 8, ok);
        }
    };

    issue(0, 0); CP_COMMIT();
    issue(1, 1); CP_COMMIT();
    issue(2, 2); CP_COMMIT();

    const int arow_l  = warp_m * 32 + (lane & 15);
    const int akoff_l = (lane >> 4) << 4;
    const int brow_l  = warp_n * 64 + (lane & 7) + ((lane >> 4) << 3);
    const int bkoff_l = ((lane >> 3) & 1) << 4;

    for (int c = 0; c < nch; c++) {
        CP_WAIT2();
        __syncthreads();
        uint32_t base = sb + (uint32_t)((c & 3) * STAGE);
        #pragma unroll
        for (int ks = 0; ks < 2; ks++) {
            const int kb = ks * 32;
            uint32_t ah[2][4];
            #pragma unroll
            for (int mi = 0; mi < 2; mi++) {
                uint32_t off = SWZ64((uint32_t)((arow_l + mi * 16) * 64 + kb + akoff_l));
                ldsm4(base + OFF_AH + off, ah[mi]);
            }
            #pragma unroll
            for (int nj2 = 0; nj2 < 4; nj2++) {
                uint32_t bh[4], bl[4];
                uint32_t off = SWZ64((uint32_t)((brow_l + nj2 * 16) * 64 + kb + bkoff_l));
                ldsm4(base + OFF_BH + off, bh);
                if (NT == 2) ldsm4(base + OFF_BL + off, bl);
                #pragma unroll
                for (int mi = 0; mi < 2; mi++) {
                    mma_f16(acc[mi][nj2*2+0], ah[mi], bh[0], bh[1]);
                    mma_f16(acc[mi][nj2*2+1], ah[mi], bh[2], bh[3]);
                    if (NT == 2) {
                        mma_f16(acc[mi][nj2*2+0], ah[mi], bl[0], bl[1]);
                        mma_f16(acc[mi][nj2*2+1], ah[mi], bl[2], bl[3]);
                    }
                }
            }
        }
        issue(c + 3, (c + 3) & 3);
        CP_COMMIT();
    }

    // ---- epilogue ----
    #pragma unroll
    for (int mi = 0; mi < 2; mi++) {
        #pragma unroll
        for (int nj = 0; nj < 8; nj++) {
            int row = bm + warp_m * 32 + mi * 16 + (lane >> 2);
            int col = bn + warp_n * 64 + nj * 8 + (lane & 3) * 2;
            if (col < N) {
                float* d = acc[mi][nj];
                float2 v0 = make_float2(d[0], d[1]);
                float2 v1 = make_float2(d[2], d[3]);
                float* p0 = Cz + (size_t)row * ldc + col;
                float* p1 = Cz + (size_t)(row + 8) * ldc + col;
                if (EPI == 1) {
                    float2 o0 = *(float2*)p0; v0.x += o0.x; v0.y += o0.y;
                    float2 o1 = *(float2*)p1; v1.x += o1.x; v1.y += o1.y;
                } else if (EPI == 3) {
                    float br0 = bias[row], br1 = bias[row + 8];
                    v0.x = softplus_f(v0.x + br0); v0.y = softplus_f(v0.y + br0);
                    v1.x = softplus_f(v1.x + br1); v1.y = softplus_f(v1.y + br1);
                }
                *(float2*)p0 = v0;
                *(float2*)p1 = v1;
            }
        }
    }
}

// ============== weight prep: fp32 (K,N) -> fp16 hi (+optional lo) [N,K] =====
__global__ void transpose_split_f16(const float* __restrict__ W, int K, int N,
                                    __half* __restrict__ Bh, __half* __restrict__ Bl)
{
    __shared__ float t[32][33];
    int k0 = blockIdx.x * 32, n0 = blockIdx.y * 32;
    int tx = threadIdx.x, ty = threadIdx.y;   // 32 x 8
    #pragma unroll
    for (int i = 0; i < 4; i++) {
        int k = k0 + ty + 8 * i;
        float v = (n0 + tx < N) ? W[(size_t)k * N + n0 + tx] : 0.f;
        t[ty + 8 * i][tx] = v;
    }
    __syncthreads();
    #pragma unroll
    for (int i = 0; i < 4; i++) {
        int n = n0 + ty + 8 * i;
        int k = k0 + tx;
        float v = t[tx][ty + 8 * i];
        __half h = __float2half_rn(v);
        Bh[(size_t)n * K + k] = h;
        if (Bl) Bl[(size_t)n * K + k] = __float2half_rn(v - __half2float(h));
    }
}

// elementwise fp32 -> fp16 cast (already [N,K] layout): lm_head, hi only
__global__ void cast_f16(const float4* __restrict__ W,
                         __half* __restrict__ Bh, int n4)
{
    int i = blockIdx.x * blockDim.x + threadIdx.x;
    if (i >= n4) return;
    float4 v = W[i];
    __half2 h0 = __floats2half2_rn(v.x, v.y);
    __half2 h1 = __floats2half2_rn(v.z, v.w);
    uint2 hh;
    hh.x = *(uint32_t*)&h0;  hh.y = *(uint32_t*)&h1;
    ((uint2*)Bh)[i] = hh;
}

// ---------------- xproj split-K reduce: dbl hi/lo + transposed B,C ---------
__global__ void reduce_xproj()
{
    int i = blockIdx.x * blockDim.x + threadIdx.x;
    if (i >= NTOK * 96) return;
    float s = g_xpart[i] + g_xpart[i + NTOK*96] + g_xpart[i + 2*NTOK*96] + g_xpart[i + 3*NTOK*96];
    int c = i % 96, t = i / 96;
    if (c < 64) {
        __half h = __float2half_rn(s);
        __half l = __float2half_rn(s - __half2float(h));
        g_dblh[i] = h;
        g_dbll[i] = l;
    } else {
        g_bcT[(size_t)(c - 64) * NTOK + t] = s;
    }
}

// ---------------- embed gather ----------------
__global__ void embed_kernel(const int* __restrict__ tokens,
                             const float* __restrict__ embed)
{
    int t = blockIdx.x;
    int tok = tokens[t];
    const float4* src = (const float4*)(embed + (size_t)tok * DD);
    float4* dst = (float4*)(g_x + (size_t)t * DD);
    for (int i = threadIdx.x; i < DD/4; i += blockDim.x)
        dst[i] = src[i];
}

// ---------------- rmsnorm (writes fp16) ----------------
__global__ void rmsnorm_kernel(const float* __restrict__ x,
                               const float* __restrict__ w,
                               __half* __restrict__ o)
{
    int t = blockIdx.x;
    const float4* xr = (const float4*)(x + (size_t)t * DD);
    const float4* wr = (const float4*)w;

    float s = 0.f;
    for (int i = threadIdx.x; i < DD/4; i += blockDim.x) {
        float4 v = xr[i];
        s += v.x*v.x + v.y*v.y + v.z*v.z + v.w*v.w;
    }
    __shared__ float red[8];
    for (int m = 16; m > 0; m >>= 1) s += __shfl_xor_sync(0xffffffffu, s, m);
    if ((threadIdx.x & 31) == 0) red[threadIdx.x >> 5] = s;
    __syncthreads();
    float tot = 0.f;
    if (threadIdx.x < 8) tot = red[threadIdx.x];
    for (int m = 4; m > 0; m >>= 1) tot += __shfl_xor_sync(0xffffffffu, tot, m);
    __shared__ float inv_s;
    if (threadIdx.x == 0) inv_s = rsqrtf(tot / (float)DD + 1e-5f);
    __syncthreads();
    float inv = inv_s;

    for (int i = threadIdx.x; i < DD/4; i += blockDim.x) {
        float4 v = xr[i];
        float4 wv = wr[i];
        __half2 h0 = __floats2half2_rn(v.x * wv.x * inv, v.y * wv.y * inv);
        __half2 h1 = __floats2half2_rn(v.z * wv.z * inv, v.w * wv.w * inv);
        uint2 hh;
        hh.x = *(uint32_t*)&h0; hh.y = *(uint32_t*)&h1;
        *(uint2*)(o + (size_t)t * DD + i * 4) = hh;
    }
}

// ------ fused causal conv (K=4) + silu + gate + dual-layout transpose ------
// Writes: xc[t][e], xcT[e][t], gT[e][t]=silu(z).  grid (NTOK/32, EE/32), blk (32,8)
__global__ void conv_fused(const float* __restrict__ conv_w,
                           const float* __restrict__ conv_b)
{
    __shared__ __half tx[32][33];
    __shared__ __half tg[32][33];
    int t0 = blockIdx.x * 32, e0 = blockIdx.y * 32;
    int lx = threadIdx.x, ly = threadIdx.y;
    int e = e0 + lx;
    float w0 = conv_w[e*KK+0], w1 = conv_w[e*KK+1], w2 = conv_w[e*KK+2], w3 = conv_w[e*KK+3];
    float cb = conv_b[e];
    #pragma unroll
    for (int i = 0; i < 4; i++) {
        int tk = t0 + ly + 8 * i;         // global token idx
        int t = tk % LL;
        const float* src = g_xz + (size_t)(tk - t) * (2*EE) + e;
        float acc = cb;
        if (t >= 3) {
            acc = fmaf(w0, src[(size_t)(t-3)*(2*EE)], acc);
            acc = fmaf(w1, src[(size_t)(t-2)*(2*EE)], acc);
            acc = fmaf(w2, src[(size_t)(t-1)*(2*EE)], acc);
            acc = fmaf(w3, src[(size_t)(t  )*(2*EE)], acc);
        } else {
            if (t-3 >= 0) acc = fmaf(w0, src[(size_t)(t-3)*(2*EE)], acc);
            if (t-2 >= 0) acc = fmaf(w1, src[(size_t)(t-2)*(2*EE)], acc);
            if (t-1 >= 0) acc = fmaf(w2, src[(size_t)(t-1)*(2*EE)], acc);
            acc = fmaf(w3, src[(size_t)t*(2*EE)], acc);
        }
        float sg = 1.f / (1.f + __expf(-acc));
        float v = acc * sg;
        __half hv = __float2half_rn(v);
        g_xc[(size_t)tk * EE + e] = hv;
        tx[ly + 8 * i][lx] = hv;
        float z = g_xz[(size_t)tk * (2*EE) + EE + e];
        float zg = 1.f / (1.f + __expf(-z));
        tg[ly + 8 * i][lx] = __float2half_rn(z * zg);
    }
    __syncthreads();
    #pragma unroll
    for (int i = 0; i < 4; i++) {
        int ee = e0 + ly + 8 * i;
        g_xcT[(size_t)ee * NTOK + t0 + lx] = tx[lx][ly + 8 * i];
        g_gT [(size_t)ee * NTOK + t0 + lx] = tg[lx][ly + 8 * i];
    }
}

// ---------------- selective scan (transposed layout, vector prefetch) ------
#define SD 8
__global__ __launch_bounds__(128)
void scan_kernel(const float* __restrict__ A_log,
                 const float* __restrict__ D_skip)
{
    int group = threadIdx.x >> 4;
    int n     = threadIdx.x & 15;
    int ch    = blockIdx.x * 8 + group;   // 0..4095
    int b = ch >> 11;
    int e = ch & (EE - 1);

    float a   = -__expf(A_log[e * NN_ + n]);
    float dsk = D_skip[e];
    float h = 0.f;

    const float*  dtp = g_dtT + (size_t)e * NTOK + b * LL;
    const __half* xp  = g_xcT + (size_t)e * NTOK + b * LL;
    const __half* gp  = g_gT  + (size_t)e * NTOK + b * LL;
    const float*  Bp  = g_bcT + (size_t)n * NTOK + b * LL;
    const float*  Cp  = g_bcT + (size_t)(16 + n) * NTOK + b * LL;
    __half* y0 = g_y + (size_t)b * LL * EE + e;

    float p_dt[2][SD], p_B[2][SD], p_C[2][SD], p_x[2][SD], p_g[2][SD];

#define PREF(BK, TP) do {                                                    \
    int tb = (TP) > (LL - SD) ? (LL - SD) : (TP);                            \
    float4 v0 = *(const float4*)(dtp + tb);                                  \
    float4 v1 = *(const float4*)(dtp + tb + 4);                              \
    p_dt[BK][0]=v0.x; p_dt[BK][1]=v0.y; p_dt[BK][2]=v0.z; p_dt[BK][3]=v0.w;  \
    p_dt[BK][4]=v1.x; p_dt[BK][5]=v1.y; p_dt[BK][6]=v1.z; p_dt[BK][7]=v1.w;  \
    v0 = *(const float4*)(Bp + tb); v1 = *(const float4*)(Bp + tb + 4);      \
    p_B[BK][0]=v0.x; p_B[BK][1]=v0.y; p_B[BK][2]=v0.z; p_B[BK][3]=v0.w;      \
    p_B[BK][4]=v1.x; p_B[BK][5]=v1.y; p_B[BK][6]=v1.z; p_B[BK][7]=v1.w;      \
    v0 = *(const float4*)(Cp + tb); v1 = *(const float4*)(Cp + tb + 4);      \
    p_C[BK][0]=v0.x; p_C[BK][1]=v0.y; p_C[BK][2]=v0.z; p_C[BK][3]=v0.w;      \
    p_C[BK][4]=v1.x; p_C[BK][5]=v1.y; p_C[BK][6]=v1.z; p_C[BK][7]=v1.w;      \
    uint4 u = *(const uint4*)(xp + tb);                                      \
    p_x[BK][0]=h2f_lo(u.x); p_x[BK][1]=h2f_hi(u.x);                          \
    p_x[BK][2]=h2f_lo(u.y); p_x[BK][3]=h2f_hi(u.y);                          \
    p_x[BK][4]=h2f_lo(u.z); p_x[BK][5]=h2f_hi(u.z);                          \
    p_x[BK][6]=h2f_lo(u.w); p_x[BK][7]=h2f_hi(u.w);                          \
    u = *(const uint4*)(gp + tb);                                            \
    p_g[BK][0]=h2f_lo(u.x); p_g[BK][1]=h2f_hi(u.x);                          \
    p_g[BK][2]=h2f_lo(u.y); p_g[BK][3]=h2f_hi(u.y);                          \
    p_g[BK][4]=h2f_lo(u.z); p_g[BK][5]=h2f_hi(u.z);                          \
    p_g[BK][6]=h2f_lo(u.w); p_g[BK][7]=h2f_hi(u.w);                          \
} while (0)

#define COMP(BK, T0) do {                                                    \
    _Pragma("unroll")                                                        \
    for (int j = 0; j < SD; j++) {                                           \
        float dte = p_dt[BK][j];                                             \
        float xe  = p_x[BK][j];                                              \
        float dA  = __expf(dte * a);                                         \
        h = fmaf(h, dA, dte * xe * p_B[BK][j]);                              \
        float p = h * p_C[BK][j];                                            \
        p += __shfl_xor_sync(0xffffffffu, p, 8);                             \
        p += __shfl_xor_sync(0xffffffffu, p, 4);                             \
        p += __shfl_xor_sync(0xffffffffu, p, 2);                             \
        p += __shfl_xor_sync(0xffffffffu, p, 1);                             \
        if (n == 0) {                                                        \
            float y = (p + xe * dsk) * p_g[BK][j];                           \
            y0[(size_t)((T0) + j) * EE] = __float2half_rn(y);                \
        }                                                                    \
    } } while (0)

    PREF(0, 0);
    for (int t0 = 0; t0 < LL; t0 += 2*SD) {
        PREF(1, t0 + SD);
        COMP(0, t0);
        PREF(0, t0 + 2*SD);
        COMP(1, t0 + SD);
    }
#undef PREF
#undef COMP
}

// ---------------- host launch ----------------
extern "C" void kernel_launch(void* const* d_in, const int* in_sizes, int n_in,
                              void* d_out, int out_size)
{
    const int*   tokens   = (const int*)  d_in[0];
    const float* embed    = (const float*)d_in[1];
    const float* norm_w   = (const float*)d_in[2];
    const float* W_in     = (const float*)d_in[3];
    const float* conv_w   = (const float*)d_in[4];
    const float* conv_b   = (const float*)d_in[5];
    const float* W_xproj  = (const float*)d_in[6];
    const float* W_dt     = (const float*)d_in[7];
    const float* dt_bias  = (const float*)d_in[8];
    const float* A_log    = (const float*)d_in[9];
    const float* D_skip   = (const float*)d_in[10];
    const float* W_out    = (const float*)d_in[11];
    const float* final_nw = (const float*)d_in[12];
    const float* lm_head  = (const float*)d_in[13];
    float* out = (float*)d_out;

    float *px, *pxz, *pxpart, *pdtT;
    __half *pxn, *pxc, *pdblh, *pdbll, *py, *pbh, *pbl;
    cudaGetSymbolAddress((void**)&px,    g_x);
    cudaGetSymbolAddress((void**)&pxn,   g_xn);
    cudaGetSymbolAddress((void**)&pxz,   g_xz);
    cudaGetSymbolAddress((void**)&pxc,   g_xc);
    cudaGetSymbolAddress((void**)&pdblh, g_dblh);
    cudaGetSymbolAddress((void**)&pdbll, g_dbll);
    cudaGetSymbolAddress((void**)&pdtT,  g_dtT);
    cudaGetSymbolAddress((void**)&py,    g_y);
    cudaGetSymbolAddress((void**)&pbh,   g_bh);
    cudaGetSymbolAddress((void**)&pbl,   g_bl);
    cudaGetSymbolAddress((void**)&pxpart, g_xpart);

    static bool attr_done = false;
    if (!attr_done) {
        cudaFuncSetAttribute(mmagemm<0,2>, cudaFuncAttributeMaxDynamicSharedMemorySize, 4*24576);
        cudaFuncSetAttribute(mmagemm<3,2>, cudaFuncAttributeMaxDynamicSharedMemorySize, 4*24576);
        cudaFuncSetAttribute(mmagemm<0,1>, cudaFuncAttributeMaxDynamicSharedMemorySize, 4*16384);
        cudaFuncSetAttribute(mmagemm<1,1>, cudaFuncAttributeMaxDynamicSharedMemorySize, 4*16384);
        attr_done = true;
    }

    embed_kernel<<<NTOK, 256>>>(tokens, embed);

    for (int l = 0; l < NLAYERS; l++) {
        const float* nw  = norm_w  + (size_t)l * DD;
        const float* win = W_in    + (size_t)l * DD * 2 * EE;
        const float* cw  = conv_w  + (size_t)l * EE * KK;
        const float* cb  = conv_b  + (size_t)l * EE;
        const float* wxp = W_xproj + (size_t)l * EE * 96;
        const float* wdt = W_dt    + (size_t)l * RR * EE;
        const float* dtb = dt_bias + (size_t)l * EE;
        const float* alg = A_log   + (size_t)l * EE * NN_;
        const float* dsk = D_skip  + (size_t)l * EE;
        const float* wo  = W_out   + (size_t)l * EE * DD;

        // 1. rmsnorm -> fp16 xn
        rmsnorm_kernel<<<NTOK, 256>>>(px, nw, pxn);

        // 2. xz = xn @ W_in   (1-term fp16)
        transpose_split_f16<<<dim3(DD/32, (2*EE)/32), dim3(32,8)>>>(win, DD, 2*EE, pbh, nullptr);
        mmagemm<0,1><<<dim3(NTOK/128, (2*EE)/128), 256, 4*16384>>>(
            pxn, pbh, nullptr, pxz, nullptr,
            2*EE, DD, DD, DD, 2*EE, 0);

        // 3. fused conv + silu + gate + transposes
        conv_fused<<<dim3(NTOK/32, EE/32), dim3(32,8)>>>(cw, cb);

        // 4. dbl = xc @ W_xproj  (2-term), split-K x4 + reduce
        transpose_split_f16<<<dim3(EE/32, 128/32), dim3(32,8)>>>(wxp, EE, 96, pbh, pbl);
        mmagemm<0,2><<<dim3(NTOK/128, 1, 4), 256, 4*24576>>>(
            pxc, pbh, pbl, pxpart, nullptr,
            96, EE/4, EE, EE, 96, (size_t)NTOK*96);
        reduce_xproj<<<(NTOK*96 + 255)/256, 256>>>();

        // 5. dtT = softplus(W_dt^T @ dbl^T + bias[row]) (2-term) -> [E, NTOK]
        transpose_split_f16<<<dim3(RR/32, EE/32), dim3(32,8)>>>(wdt, RR, EE, pbh, pbl);
        mmagemm<3,2><<<dim3(EE/128, NTOK/128), 256, 4*24576>>>(
            pbh, pdblh, pdbll, pdtT, dtb,
            NTOK, RR, RR, 96, NTOK, 0);

        // 6. selective scan + gate -> fp16 y [t][e]
        scan_kernel<<<(BB*EE)/8, 128>>>(alg, dsk);

        // 7. x += y @ W_out  (1-term fp16)
        transpose_split_f16<<<dim3(EE/32, DD/32), dim3(32,8)>>>(wo, EE, DD, pbh, nullptr);
        mmagemm<1,1><<<dim3(NTOK/128, DD/128), 256, 4*16384>>>(
            py, pbh, nullptr, px, nullptr,
            DD, EE, EE, EE, DD, 0);
    }

    // final rmsnorm -> fp16 xn
    rmsnorm_kernel<<<NTOK, 256>>>(px, final_nw, pxn);

    // logits = xn @ lm_head^T  (1-term fp16); lm_head already [N,K]
    cast_f16<<<(VV*DD/4 + 255)/256, 256>>>((const float4*)lm_head, pbh, VV*DD/4);
    mmagemm<0,1><<<dim3(NTOK/128, VV/128), 256, 4*16384>>>(
        pxn, pbh, nullptr, out, nullptr,
        VV, DD, DD, DD, VV, 0);
}